// round 1
// baseline (speedup 1.0000x reference)
#include <cuda_runtime.h>
#include <math.h>

#define BATCH   4
#define QLEN    512
#define KVLEN   4096
#define DMODEL  1024
#define NHEAD   16
#define DH      64

// Scratch (allocation-free rule: static __device__ globals)
__device__ float g_q  [BATCH * QLEN  * DMODEL];   //  8 MB
__device__ float g_k  [BATCH * KVLEN * DMODEL];   // 64 MB
__device__ float g_v  [BATCH * KVLEN * DMODEL];   // 64 MB
__device__ float g_att[BATCH * QLEN  * DMODEL];   //  8 MB

// ---------------------------------------------------------------------------
// SGEMM: C[M,N] = A[M,K] @ W[K,N]. Requires M%128==0, N%128==0, K%16==0.
// 256 threads, BM=BN=128, BK=16, 8x8 per thread (two 4-wide fragments per dim).
// ---------------------------------------------------------------------------
__global__ __launch_bounds__(256)
void sgemm128(const float* __restrict__ A, const float* __restrict__ W,
              float* __restrict__ C, int M, int N, int K)
{
    __shared__ float As[16][128];   // As[kk][row]  (A tile transposed)
    __shared__ float Bs[16][128];   // Bs[kk][col]

    const int tid = threadIdx.x;
    const int tx  = tid & 15;       // 0..15 -> N microtile
    const int ty  = tid >> 4;       // 0..15 -> M microtile
    const int bx  = blockIdx.x;     // N block
    const int by  = blockIdx.y;     // M block

    const float* Ab = A + (size_t)by * 128 * K;
    const float* Wb = W + (size_t)bx * 128;

    float acc[8][8];
#pragma unroll
    for (int i = 0; i < 8; i++)
#pragma unroll
        for (int j = 0; j < 8; j++) acc[i][j] = 0.f;

    for (int k0 = 0; k0 < K; k0 += 16) {
        // --- load A tile: 128 rows x 16 k (512 float4, 2 per thread) ---
#pragma unroll
        for (int i = 0; i < 2; i++) {
            int f   = tid * 2 + i;
            int ar  = f >> 2;             // 0..127
            int ac4 = (f & 3) * 4;        // 0,4,8,12
            float4 v = *(const float4*)(Ab + (size_t)ar * K + k0 + ac4);
            As[ac4 + 0][ar] = v.x;
            As[ac4 + 1][ar] = v.y;
            As[ac4 + 2][ar] = v.z;
            As[ac4 + 3][ar] = v.w;
        }
        // --- load W tile: 16 k-rows x 128 cols ---
#pragma unroll
        for (int i = 0; i < 2; i++) {
            int f   = tid * 2 + i;
            int br  = f >> 5;             // 0..15
            int bc4 = (f & 31) * 4;       // 0..124
            float4 v = *(const float4*)(Wb + (size_t)(k0 + br) * N + bc4);
            *(float4*)&Bs[br][bc4] = v;
        }
        __syncthreads();

#pragma unroll
        for (int kk = 0; kk < 16; kk++) {
            float a[8], b[8];
            *(float4*)&a[0] = *(const float4*)&As[kk][ty * 4];
            *(float4*)&a[4] = *(const float4*)&As[kk][64 + ty * 4];
            *(float4*)&b[0] = *(const float4*)&Bs[kk][tx * 4];
            *(float4*)&b[4] = *(const float4*)&Bs[kk][64 + tx * 4];
#pragma unroll
            for (int i = 0; i < 8; i++)
#pragma unroll
                for (int j = 0; j < 8; j++)
                    acc[i][j] += a[i] * b[j];
        }
        __syncthreads();
    }

    // --- epilogue ---
#pragma unroll
    for (int i = 0; i < 8; i++) {
        int row = by * 128 + ((i < 4) ? (ty * 4 + i) : (64 + ty * 4 + (i - 4)));
        float* Cr = C + (size_t)row * N + bx * 128;
        float4 v0 = make_float4(acc[i][0], acc[i][1], acc[i][2], acc[i][3]);
        float4 v1 = make_float4(acc[i][4], acc[i][5], acc[i][6], acc[i][7]);
        *(float4*)(Cr + tx * 4)      = v0;
        *(float4*)(Cr + 64 + tx * 4) = v1;
    }
}

// ---------------------------------------------------------------------------
// Fused attention: per (b, h, q-tile of 64):
//   S = (Q·Kt)*scale + bias ; P = exp(S) ; O = (P·V) / rowsum(P)
// No max-subtraction needed: |scores| <= ~10 here, exp stays finite in fp32.
// 256 threads (16x16), 4x4 microtiles over 64x64 tiles.
// Dynamic smem: Qst[64][68], KP[64][68] (K tile then P tile), Vs[64][68].
// ---------------------------------------------------------------------------
#define ATT_STRIDE 68
#define ATT_SMEM   (3 * 64 * ATT_STRIDE * 4)

__global__ __launch_bounds__(256)
void attn_kernel(const float* __restrict__ qb, const float* __restrict__ kb,
                 const float* __restrict__ vb, const float* __restrict__ bias,
                 float* __restrict__ ob)
{
    extern __shared__ float sm[];
    float* Qs = sm;                       // [d][i]  (Q transposed, pre-scaled)
    float* KP = sm + 64 * ATT_STRIDE;     // [d][j] as K-tile, then [j][i] as P
    float* Vs = sm + 2 * 64 * ATT_STRIDE; // [j][d]
    __shared__ float bs[64];
    __shared__ float dred[64][17];
    __shared__ float dfin[64];

    const int tid = threadIdx.x;
    const int tx  = tid & 15;   // k-cols (S phase) / d-cols (PV phase)
    const int ty  = tid >> 4;   // q-rows
    const int qt  = blockIdx.x; // q tile (0..7)
    const int h   = blockIdx.y; // head
    const int b   = blockIdx.z; // batch

    const int q0 = qt * 64;
    const float scale = 0.125f; // dh^-0.5, dh=64

    // --- load Q tile (transposed, pre-scaled) ---
#pragma unroll
    for (int i = 0; i < 4; i++) {
        int f  = tid + 256 * i;      // float4 index, 0..1023
        int r  = f >> 4;             // q row 0..63
        int c4 = (f & 15) * 4;       // dh col
        float4 v = *(const float4*)(qb + ((size_t)(b * QLEN + q0 + r)) * DMODEL
                                       + h * DH + c4);
        Qs[(c4 + 0) * ATT_STRIDE + r] = v.x * scale;
        Qs[(c4 + 1) * ATT_STRIDE + r] = v.y * scale;
        Qs[(c4 + 2) * ATT_STRIDE + r] = v.z * scale;
        Qs[(c4 + 3) * ATT_STRIDE + r] = v.w * scale;
    }

    float acc[4][4];
    float dsum[4] = {0.f, 0.f, 0.f, 0.f};
#pragma unroll
    for (int i = 0; i < 4; i++)
#pragma unroll
        for (int j = 0; j < 4; j++) acc[i][j] = 0.f;

    for (int k0 = 0; k0 < KVLEN; k0 += 64) {
        __syncthreads();   // previous PV done reading KP/Vs
        // --- load K tile (transposed) + V tile (natural) + bias slice ---
#pragma unroll
        for (int i = 0; i < 4; i++) {
            int f  = tid + 256 * i;
            int r  = f >> 4;           // k row in tile
            int c4 = (f & 15) * 4;     // dh col
            size_t base = ((size_t)(b * KVLEN + k0 + r)) * DMODEL + h * DH + c4;
            float4 kv = *(const float4*)(kb + base);
            KP[(c4 + 0) * ATT_STRIDE + r] = kv.x;
            KP[(c4 + 1) * ATT_STRIDE + r] = kv.y;
            KP[(c4 + 2) * ATT_STRIDE + r] = kv.z;
            KP[(c4 + 3) * ATT_STRIDE + r] = kv.w;
            float4 vv = *(const float4*)(vb + base);
            *(float4*)&Vs[r * ATT_STRIDE + c4] = vv;
        }
        if (tid < 64) bs[tid] = bias[(size_t)b * KVLEN + k0 + tid];
        __syncthreads();

        // --- S = Qt . Kt ---
        float s[4][4];
#pragma unroll
        for (int i = 0; i < 4; i++)
#pragma unroll
            for (int j = 0; j < 4; j++) s[i][j] = 0.f;
#pragma unroll 8
        for (int kk = 0; kk < 64; kk++) {
            float a[4], bb[4];
            *(float4*)a  = *(const float4*)&Qs[kk * ATT_STRIDE + ty * 4];
            *(float4*)bb = *(const float4*)&KP[kk * ATT_STRIDE + tx * 4];
#pragma unroll
            for (int i = 0; i < 4; i++)
#pragma unroll
                for (int j = 0; j < 4; j++)
                    s[i][j] += a[i] * bb[j];
        }
        // --- P = exp(S + bias) ---
#pragma unroll
        for (int j = 0; j < 4; j++) {
            float bj = bs[tx * 4 + j];
#pragma unroll
            for (int i = 0; i < 4; i++) {
                float p = __expf(s[i][j] + bj);
                s[i][j] = p;
                dsum[i] += p;
            }
        }
        __syncthreads();   // everyone done reading K tile from KP
        // store P transposed: KP[j][i]
#pragma unroll
        for (int j = 0; j < 4; j++)
#pragma unroll
            for (int i = 0; i < 4; i++)
                KP[(tx * 4 + j) * ATT_STRIDE + ty * 4 + i] = s[i][j];
        __syncthreads();

        // --- O += P . V ---
#pragma unroll 8
        for (int kk = 0; kk < 64; kk++) {
            float a[4], bb[4];
            *(float4*)a  = *(const float4*)&KP[kk * ATT_STRIDE + ty * 4];
            *(float4*)bb = *(const float4*)&Vs[kk * ATT_STRIDE + tx * 4];
#pragma unroll
            for (int i = 0; i < 4; i++)
#pragma unroll
                for (int j = 0; j < 4; j++)
                    acc[i][j] += a[i] * bb[j];
        }
    }

    // --- denominator reduction across tx ---
#pragma unroll
    for (int i = 0; i < 4; i++) dred[ty * 4 + i][tx] = dsum[i];
    __syncthreads();
    if (tid < 64) {
        float t = 0.f;
#pragma unroll
        for (int c = 0; c < 16; c++) t += dred[tid][c];
        dfin[tid] = 1.0f / t;
    }
    __syncthreads();

    // --- write output: att[b, q, h*64 + d] ---
#pragma unroll
    for (int i = 0; i < 4; i++) {
        int   row  = ty * 4 + i;
        float rinv = dfin[row];
        float4 v = make_float4(acc[i][0] * rinv, acc[i][1] * rinv,
                               acc[i][2] * rinv, acc[i][3] * rinv);
        *(float4*)(ob + ((size_t)(b * QLEN + q0 + row)) * DMODEL
                      + h * DH + tx * 4) = v;
    }
}

// ---------------------------------------------------------------------------
extern "C" void kernel_launch(void* const* d_in, const int* in_sizes, int n_in,
                              void* d_out, int out_size)
{
    const float* query  = (const float*)d_in[0];
    const float* memory = (const float*)d_in[1];
    const float* bias   = (const float*)d_in[2];
    const float* Wq     = (const float*)d_in[3];
    const float* Wk     = (const float*)d_in[4];
    const float* Wv     = (const float*)d_in[5];
    const float* Wo     = (const float*)d_in[6];
    float* out = (float*)d_out;

    float *qb, *kb, *vb, *ab;
    cudaGetSymbolAddress((void**)&qb, g_q);
    cudaGetSymbolAddress((void**)&kb, g_k);
    cudaGetSymbolAddress((void**)&vb, g_v);
    cudaGetSymbolAddress((void**)&ab, g_att);

    cudaFuncSetAttribute(attn_kernel,
                         cudaFuncAttributeMaxDynamicSharedMemorySize, ATT_SMEM);

    dim3 blk(256);
    const int M_q  = BATCH * QLEN;    // 2048
    const int M_kv = BATCH * KVLEN;   // 16384

    sgemm128<<<dim3(DMODEL / 128, M_q / 128),  blk>>>(query,  Wq, qb, M_q,  DMODEL, DMODEL);
    sgemm128<<<dim3(DMODEL / 128, M_kv / 128), blk>>>(memory, Wk, kb, M_kv, DMODEL, DMODEL);
    sgemm128<<<dim3(DMODEL / 128, M_kv / 128), blk>>>(memory, Wv, vb, M_kv, DMODEL, DMODEL);

    attn_kernel<<<dim3(QLEN / 64, NHEAD, BATCH), blk, ATT_SMEM>>>(qb, kb, vb, bias, ab);

    sgemm128<<<dim3(DMODEL / 128, M_q / 128),  blk>>>(ab, Wo, out, M_q, DMODEL, DMODEL);
}

// round 3
// speedup vs baseline: 1.0010x; 1.0010x over previous
#include <cuda_runtime.h>
#include <math.h>

#define BATCH   4
#define QLEN    512
#define KVLEN   4096
#define DMODEL  1024
#define NHEAD   16
#define DH      64

// Scratch (allocation-free rule: static __device__ globals)
__device__ float g_q  [BATCH * QLEN  * DMODEL];   //  8 MB
__device__ float g_k  [BATCH * KVLEN * DMODEL];   // 64 MB
__device__ float g_v  [BATCH * KVLEN * DMODEL];   // 64 MB
__device__ float g_att[BATCH * QLEN  * DMODEL];   //  8 MB

// ---------------------------------------------------------------------------
// SGEMM: C[M,N] = A[M,K] @ W[K,N]. Requires M%128==0, N%128==0, K%16==0.
// 256 threads, BM=BN=128, BK=16, 8x8 per thread (two 4-wide fragments per dim).
// ---------------------------------------------------------------------------
__global__ __launch_bounds__(256)
void sgemm128(const float* __restrict__ A, const float* __restrict__ W,
              float* __restrict__ C, int M, int N, int K)
{
    __shared__ float As[16][128];   // As[kk][row]  (A tile transposed)
    __shared__ float Bs[16][128];   // Bs[kk][col]

    const int tid = threadIdx.x;
    const int tx  = tid & 15;       // 0..15 -> N microtile
    const int ty  = tid >> 4;       // 0..15 -> M microtile
    const int bx  = blockIdx.x;     // N block
    const int by  = blockIdx.y;     // M block

    const float* Ab = A + (size_t)by * 128 * K;
    const float* Wb = W + (size_t)bx * 128;

    float acc[8][8];
#pragma unroll
    for (int i = 0; i < 8; i++)
#pragma unroll
        for (int j = 0; j < 8; j++) acc[i][j] = 0.f;

    for (int k0 = 0; k0 < K; k0 += 16) {
        // --- load A tile: 128 rows x 16 k (512 float4, 2 per thread) ---
#pragma unroll
        for (int i = 0; i < 2; i++) {
            int f   = tid * 2 + i;
            int ar  = f >> 2;             // 0..127
            int ac4 = (f & 3) * 4;        // 0,4,8,12
            float4 v = *(const float4*)(Ab + (size_t)ar * K + k0 + ac4);
            As[ac4 + 0][ar] = v.x;
            As[ac4 + 1][ar] = v.y;
            As[ac4 + 2][ar] = v.z;
            As[ac4 + 3][ar] = v.w;
        }
        // --- load W tile: 16 k-rows x 128 cols ---
#pragma unroll
        for (int i = 0; i < 2; i++) {
            int f   = tid * 2 + i;
            int br  = f >> 5;             // 0..15
            int bc4 = (f & 31) * 4;       // 0..124
            float4 v = *(const float4*)(Wb + (size_t)(k0 + br) * N + bc4);
            *(float4*)&Bs[br][bc4] = v;
        }
        __syncthreads();

#pragma unroll
        for (int kk = 0; kk < 16; kk++) {
            float a[8], b[8];
            *(float4*)&a[0] = *(const float4*)&As[kk][ty * 4];
            *(float4*)&a[4] = *(const float4*)&As[kk][64 + ty * 4];
            *(float4*)&b[0] = *(const float4*)&Bs[kk][tx * 4];
            *(float4*)&b[4] = *(const float4*)&Bs[kk][64 + tx * 4];
#pragma unroll
            for (int i = 0; i < 8; i++)
#pragma unroll
                for (int j = 0; j < 8; j++)
                    acc[i][j] += a[i] * b[j];
        }
        __syncthreads();
    }

    // --- epilogue ---
#pragma unroll
    for (int i = 0; i < 8; i++) {
        int row = by * 128 + ((i < 4) ? (ty * 4 + i) : (64 + ty * 4 + (i - 4)));
        float* Cr = C + (size_t)row * N + bx * 128;
        float4 v0 = make_float4(acc[i][0], acc[i][1], acc[i][2], acc[i][3]);
        float4 v1 = make_float4(acc[i][4], acc[i][5], acc[i][6], acc[i][7]);
        *(float4*)(Cr + tx * 4)      = v0;
        *(float4*)(Cr + 64 + tx * 4) = v1;
    }
}

// ---------------------------------------------------------------------------
// Fused attention: per (b, h, q-tile of 64):
//   S = (Q·Kt)*scale + bias ; P = exp(S) ; O = (P·V) / rowsum(P)
// No max-subtraction needed: |scores| <= ~10 here, exp stays finite in fp32.
// 256 threads (16x16), 4x4 microtiles over 64x64 tiles.
// Dynamic smem: Qst[64][68], KP[64][68] (K tile then P tile), Vs[64][68].
// ---------------------------------------------------------------------------
#define ATT_STRIDE 68
#define ATT_SMEM   (3 * 64 * ATT_STRIDE * 4)

__global__ __launch_bounds__(256)
void attn_kernel(const float* __restrict__ qb, const float* __restrict__ kb,
                 const float* __restrict__ vb, const float* __restrict__ bias,
                 float* __restrict__ ob)
{
    extern __shared__ float sm[];
    float* Qs = sm;                       // [d][i]  (Q transposed, pre-scaled)
    float* KP = sm + 64 * ATT_STRIDE;     // [d][j] as K-tile, then [j][i] as P
    float* Vs = sm + 2 * 64 * ATT_STRIDE; // [j][d]
    __shared__ float bs[64];
    __shared__ float dred[64][17];
    __shared__ float dfin[64];

    const int tid = threadIdx.x;
    const int tx  = tid & 15;   // k-cols (S phase) / d-cols (PV phase)
    const int ty  = tid >> 4;   // q-rows
    const int qt  = blockIdx.x; // q tile (0..7)
    const int h   = blockIdx.y; // head
    const int b   = blockIdx.z; // batch

    const int q0 = qt * 64;
    const float scale = 0.125f; // dh^-0.5, dh=64

    // --- load Q tile (transposed, pre-scaled) ---
#pragma unroll
    for (int i = 0; i < 4; i++) {
        int f  = tid + 256 * i;      // float4 index, 0..1023
        int r  = f >> 4;             // q row 0..63
        int c4 = (f & 15) * 4;       // dh col
        float4 v = *(const float4*)(qb + ((size_t)(b * QLEN + q0 + r)) * DMODEL
                                       + h * DH + c4);
        Qs[(c4 + 0) * ATT_STRIDE + r] = v.x * scale;
        Qs[(c4 + 1) * ATT_STRIDE + r] = v.y * scale;
        Qs[(c4 + 2) * ATT_STRIDE + r] = v.z * scale;
        Qs[(c4 + 3) * ATT_STRIDE + r] = v.w * scale;
    }

    float acc[4][4];
    float dsum[4] = {0.f, 0.f, 0.f, 0.f};
#pragma unroll
    for (int i = 0; i < 4; i++)
#pragma unroll
        for (int j = 0; j < 4; j++) acc[i][j] = 0.f;

    for (int k0 = 0; k0 < KVLEN; k0 += 64) {
        __syncthreads();   // previous PV done reading KP/Vs
        // --- load K tile (transposed) + V tile (natural) + bias slice ---
#pragma unroll
        for (int i = 0; i < 4; i++) {
            int f  = tid + 256 * i;
            int r  = f >> 4;           // k row in tile
            int c4 = (f & 15) * 4;     // dh col
            size_t base = ((size_t)(b * KVLEN + k0 + r)) * DMODEL + h * DH + c4;
            float4 kv = *(const float4*)(kb + base);
            KP[(c4 + 0) * ATT_STRIDE + r] = kv.x;
            KP[(c4 + 1) * ATT_STRIDE + r] = kv.y;
            KP[(c4 + 2) * ATT_STRIDE + r] = kv.z;
            KP[(c4 + 3) * ATT_STRIDE + r] = kv.w;
            float4 vv = *(const float4*)(vb + base);
            *(float4*)&Vs[r * ATT_STRIDE + c4] = vv;
        }
        if (tid < 64) bs[tid] = bias[(size_t)b * KVLEN + k0 + tid];
        __syncthreads();

        // --- S = Qt . Kt ---
        float s[4][4];
#pragma unroll
        for (int i = 0; i < 4; i++)
#pragma unroll
            for (int j = 0; j < 4; j++) s[i][j] = 0.f;
#pragma unroll 8
        for (int kk = 0; kk < 64; kk++) {
            float a[4], bb[4];
            *(float4*)a  = *(const float4*)&Qs[kk * ATT_STRIDE + ty * 4];
            *(float4*)bb = *(const float4*)&KP[kk * ATT_STRIDE + tx * 4];
#pragma unroll
            for (int i = 0; i < 4; i++)
#pragma unroll
                for (int j = 0; j < 4; j++)
                    s[i][j] += a[i] * bb[j];
        }
        // --- P = exp(S + bias) ---
#pragma unroll
        for (int j = 0; j < 4; j++) {
            float bj = bs[tx * 4 + j];
#pragma unroll
            for (int i = 0; i < 4; i++) {
                float p = __expf(s[i][j] + bj);
                s[i][j] = p;
                dsum[i] += p;
            }
        }
        __syncthreads();   // everyone done reading K tile from KP
        // store P transposed: KP[j][i]
#pragma unroll
        for (int j = 0; j < 4; j++)
#pragma unroll
            for (int i = 0; i < 4; i++)
                KP[(tx * 4 + j) * ATT_STRIDE + ty * 4 + i] = s[i][j];
        __syncthreads();

        // --- O += P . V ---
#pragma unroll 8
        for (int kk = 0; kk < 64; kk++) {
            float a[4], bb[4];
            *(float4*)a  = *(const float4*)&KP[kk * ATT_STRIDE + ty * 4];
            *(float4*)bb = *(const float4*)&Vs[kk * ATT_STRIDE + tx * 4];
#pragma unroll
            for (int i = 0; i < 4; i++)
#pragma unroll
                for (int j = 0; j < 4; j++)
                    acc[i][j] += a[i] * bb[j];
        }
    }

    // --- denominator reduction across tx ---
#pragma unroll
    for (int i = 0; i < 4; i++) dred[ty * 4 + i][tx] = dsum[i];
    __syncthreads();
    if (tid < 64) {
        float t = 0.f;
#pragma unroll
        for (int c = 0; c < 16; c++) t += dred[tid][c];
        dfin[tid] = 1.0f / t;
    }
    __syncthreads();

    // --- write output: att[b, q, h*64 + d] ---
#pragma unroll
    for (int i = 0; i < 4; i++) {
        int   row  = ty * 4 + i;
        float rinv = dfin[row];
        float4 v = make_float4(acc[i][0] * rinv, acc[i][1] * rinv,
                               acc[i][2] * rinv, acc[i][3] * rinv);
        *(float4*)(ob + ((size_t)(b * QLEN + q0 + row)) * DMODEL
                      + h * DH + tx * 4) = v;
    }
}

// ---------------------------------------------------------------------------
extern "C" void kernel_launch(void* const* d_in, const int* in_sizes, int n_in,
                              void* d_out, int out_size)
{
    const float* query  = (const float*)d_in[0];
    const float* memory = (const float*)d_in[1];
    const float* bias   = (const float*)d_in[2];
    const float* Wq     = (const float*)d_in[3];
    const float* Wk     = (const float*)d_in[4];
    const float* Wv     = (const float*)d_in[5];
    const float* Wo     = (const float*)d_in[6];
    float* out = (float*)d_out;

    float *qb, *kb, *vb, *ab;
    cudaGetSymbolAddress((void**)&qb, g_q);
    cudaGetSymbolAddress((void**)&kb, g_k);
    cudaGetSymbolAddress((void**)&vb, g_v);
    cudaGetSymbolAddress((void**)&ab, g_att);

    cudaFuncSetAttribute(attn_kernel,
                         cudaFuncAttributeMaxDynamicSharedMemorySize, ATT_SMEM);

    dim3 blk(256);
    const int M_q  = BATCH * QLEN;    // 2048
    const int M_kv = BATCH * KVLEN;   // 16384

    sgemm128<<<dim3(DMODEL / 128, M_q / 128),  blk>>>(query,  Wq, qb, M_q,  DMODEL, DMODEL);
    sgemm128<<<dim3(DMODEL / 128, M_kv / 128), blk>>>(memory, Wk, kb, M_kv, DMODEL, DMODEL);
    sgemm128<<<dim3(DMODEL / 128, M_kv / 128), blk>>>(memory, Wv, vb, M_kv, DMODEL, DMODEL);

    attn_kernel<<<dim3(QLEN / 64, NHEAD, BATCH), blk, ATT_SMEM>>>(qb, kb, vb, bias, ab);

    sgemm128<<<dim3(DMODEL / 128, M_q / 128),  blk>>>(ab, Wo, out, M_q, DMODEL, DMODEL);
}

// round 5
// speedup vs baseline: 1.4905x; 1.4890x over previous
#include <cuda_runtime.h>
#include <cuda_bf16.h>
#include <cstdint>
#include <math.h>

#define BATCH   4
#define QLEN    512
#define KVLEN   4096
#define DMODEL  1024
#define NHEAD   16
#define DH      64
#define GK      1024

// ---------------- scratch (allocation-free rule) ----------------
__device__ float g_q  [BATCH * QLEN  * DMODEL];
__device__ float g_k  [BATCH * KVLEN * DMODEL];
__device__ float g_v  [BATCH * KVLEN * DMODEL];
__device__ float g_att[BATCH * QLEN  * DMODEL];
__device__ __nv_bfloat16 g_mh[BATCH * KVLEN * DMODEL];
__device__ __nv_bfloat16 g_ml[BATCH * KVLEN * DMODEL];
__device__ __nv_bfloat16 g_qh[BATCH * QLEN  * DMODEL];
__device__ __nv_bfloat16 g_ql[BATCH * QLEN  * DMODEL];
__device__ __nv_bfloat16 g_ah[BATCH * QLEN  * DMODEL];
__device__ __nv_bfloat16 g_al[BATCH * QLEN  * DMODEL];
__device__ __nv_bfloat16 g_wh[4][DMODEL * DMODEL];
__device__ __nv_bfloat16 g_wl[4][DMODEL * DMODEL];

#define CP_ASYNC16(d, s) asm volatile("cp.async.cg.shared.global [%0], [%1], 16;" :: "r"(d), "l"(s))

__device__ __forceinline__ void mma_bf16(float* c, const uint32_t* a, const uint32_t* b) {
    asm volatile(
        "mma.sync.aligned.m16n8k16.row.col.f32.bf16.bf16.f32 "
        "{%0,%1,%2,%3}, {%4,%5,%6,%7}, {%8,%9}, {%0,%1,%2,%3};"
        : "+f"(c[0]), "+f"(c[1]), "+f"(c[2]), "+f"(c[3])
        : "r"(a[0]), "r"(a[1]), "r"(a[2]), "r"(a[3]), "r"(b[0]), "r"(b[1]));
}

// split fp32 -> (hi, lo) bf16
__global__ void k_split(const float* __restrict__ x, __nv_bfloat16* __restrict__ hi,
                        __nv_bfloat16* __restrict__ lo, int n)
{
    for (int i = blockIdx.x * blockDim.x + threadIdx.x; i < n; i += gridDim.x * blockDim.x) {
        float v = x[i];
        __nv_bfloat16 h = __float2bfloat16(v);
        hi[i] = h;
        lo[i] = __float2bfloat16(v - __bfloat162float(h));
    }
}
// transpose + split W[k][n] -> Th[n][k], Tl[n][k]
__global__ void k_tsplit(const float* __restrict__ W, __nv_bfloat16* __restrict__ Th,
                         __nv_bfloat16* __restrict__ Tl)
{
    __shared__ float t[32][33];
    int k0 = blockIdx.y * 32, n0 = blockIdx.x * 32;
    int tx = threadIdx.x, ty = threadIdx.y;
#pragma unroll
    for (int i = 0; i < 4; i++)
        t[ty + 8 * i][tx] = W[(size_t)(k0 + ty + 8 * i) * DMODEL + n0 + tx];
    __syncthreads();
#pragma unroll
    for (int i = 0; i < 4; i++) {
        float v = t[tx][ty + 8 * i];
        __nv_bfloat16 h = __float2bfloat16(v);
        size_t o = (size_t)(n0 + ty + 8 * i) * DMODEL + k0 + tx;
        Th[o] = h;
        Tl[o] = __float2bfloat16(v - __bfloat162float(h));
    }
}

// ---------------------------------------------------------------------------
// mma.sync bf16-split GEMM: C[M,N] = Ah/l[M,K=1024] @ (Bh/l[N,K])^T
// CTA 128x128, BK=32, 8 warps, warp tile 64x32 (4x4 m16n8k16 microtiles),
// 3 MMAs per microtile-kstep (hh, hl, lh). cp.async double-buffered.
// smem stride 40 halves (20 words): fragment LDS is bank-conflict-free.
// ---------------------------------------------------------------------------
#define SKH   40                 // smem row stride in halves
#define SKW   20                 // ... in 32-bit words
#define ARR_W (128 * SKW)        // words per array (2560)
#define BUF_W (4 * ARR_W)        // words per buffer (10240)
#define GEMM_SMEM (2 * BUF_W * 4)  // 81920 bytes

__global__ __launch_bounds__(256, 2)
void gemm_mma(const __nv_bfloat16* __restrict__ Ah, const __nv_bfloat16* __restrict__ Al,
              const __nv_bfloat16* __restrict__ Bh, const __nv_bfloat16* __restrict__ Bl,
              float* __restrict__ C, int N)
{
    extern __shared__ __align__(16) uint32_t sm32[];
    const int tid  = threadIdx.x;
    const int wid  = tid >> 5, lane = tid & 31;
    const int g    = lane >> 2, tg = lane & 3;
    const int wm64 = (wid & 1) * 64;     // warp m offset
    const int wn32 = (wid >> 1) * 32;    // warp n offset
    const int bn = blockIdx.x, bm = blockIdx.y;

    const size_t arow0 = (size_t)bm * 128 * GK;
    const size_t brow0 = (size_t)bn * 128 * GK;
    const uint32_t smem_b = (uint32_t)__cvta_generic_to_shared(sm32);

    float acc[4][4][4];
#pragma unroll
    for (int mt = 0; mt < 4; mt++)
#pragma unroll
        for (int nt = 0; nt < 4; nt++)
#pragma unroll
            for (int r = 0; r < 4; r++) acc[mt][nt][r] = 0.f;

    auto load_tile = [&](int kt, int buf) {
        const __nv_bfloat16* srcs[4] = {
            Ah + arow0 + kt * 32, Al + arow0 + kt * 32,
            Bh + brow0 + kt * 32, Bl + brow0 + kt * 32 };
#pragma unroll
        for (int i = 0; i < 8; i++) {
            int chunk = tid + 256 * i;        // 0..2047
            int arr = chunk >> 9;
            int w   = chunk & 511;
            int row = w >> 2, c = w & 3;      // 4x16B chunks per 64B row
            uint32_t dst = smem_b + (buf * BUF_W + arr * ARR_W + row * SKW) * 4 + c * 16;
            CP_ASYNC16(dst, srcs[arr] + (size_t)row * GK + c * 8);
        }
        asm volatile("cp.async.commit_group;");
    };

    load_tile(0, 0);

    const int NT = GK / 32;   // 32 k-tiles
    for (int kt = 0; kt < NT; kt++) {
        const int buf = kt & 1;
        if (kt + 1 < NT) {
            load_tile(kt + 1, 1 - buf);
            asm volatile("cp.async.wait_group 1;");
        } else {
            asm volatile("cp.async.wait_group 0;");
        }
        __syncthreads();

        const uint32_t* Ahw = sm32 + buf * BUF_W;
        const uint32_t* Alw = Ahw + ARR_W;
        const uint32_t* Bhw = Ahw + 2 * ARR_W;
        const uint32_t* Blw = Ahw + 3 * ARR_W;

#pragma unroll
        for (int ks = 0; ks < 2; ks++) {
            uint32_t bh[4][2], bl[4][2];
#pragma unroll
            for (int nt = 0; nt < 4; nt++) {
                int base = (wn32 + nt * 8 + g) * SKW + ks * 8 + tg;
                bh[nt][0] = Bhw[base];  bh[nt][1] = Bhw[base + 4];
                bl[nt][0] = Blw[base];  bl[nt][1] = Blw[base + 4];
            }
#pragma unroll
            for (int mt = 0; mt < 4; mt++) {
                int base = (wm64 + mt * 16 + g) * SKW + ks * 8 + tg;
                uint32_t ah[4], al[4];
                ah[0] = Ahw[base];            ah[1] = Ahw[base + 8 * SKW];
                ah[2] = Ahw[base + 4];        ah[3] = Ahw[base + 8 * SKW + 4];
                al[0] = Alw[base];            al[1] = Alw[base + 8 * SKW];
                al[2] = Alw[base + 4];        al[3] = Alw[base + 8 * SKW + 4];
#pragma unroll
                for (int nt = 0; nt < 4; nt++) {
                    mma_bf16(acc[mt][nt], ah, bh[nt]);
                    mma_bf16(acc[mt][nt], ah, bl[nt]);
                    mma_bf16(acc[mt][nt], al, bh[nt]);
                }
            }
        }
        __syncthreads();   // protect buffer 1-buf before next load overwrites
    }

    // epilogue: c0/c1 -> row g, c2/c3 -> row g+8, cols tg*2 + {0,1}
#pragma unroll
    for (int mt = 0; mt < 4; mt++) {
        int row0 = bm * 128 + wm64 + mt * 16 + g;
#pragma unroll
        for (int nt = 0; nt < 4; nt++) {
            int col = bn * 128 + wn32 + nt * 8 + tg * 2;
            *(float2*)(C + (size_t)row0 * N + col)       = make_float2(acc[mt][nt][0], acc[mt][nt][1]);
            *(float2*)(C + (size_t)(row0 + 8) * N + col) = make_float2(acc[mt][nt][2], acc[mt][nt][3]);
        }
    }
}

// ---------------------------------------------------------------------------
// Fused attention (fp32, unchanged from passing baseline)
// ---------------------------------------------------------------------------
#define ATT_STRIDE 68
#define ATT_SMEM   (3 * 64 * ATT_STRIDE * 4)

__global__ __launch_bounds__(256)
void attn_kernel(const float* __restrict__ qb, const float* __restrict__ kb,
                 const float* __restrict__ vb, const float* __restrict__ bias,
                 float* __restrict__ ob)
{
    extern __shared__ float sm[];
    float* Qs = sm;
    float* KP = sm + 64 * ATT_STRIDE;
    float* Vs = sm + 2 * 64 * ATT_STRIDE;
    __shared__ float bs[64];
    __shared__ float dred[64][17];
    __shared__ float dfin[64];

    const int tid = threadIdx.x;
    const int tx = tid & 15, ty = tid >> 4;
    const int qt = blockIdx.x, h = blockIdx.y, b = blockIdx.z;
    const int q0 = qt * 64;
    const float scale = 0.125f;

#pragma unroll
    for (int i = 0; i < 4; i++) {
        int f = tid + 256 * i, r = f >> 4, c4 = (f & 15) * 4;
        float4 v = *(const float4*)(qb + ((size_t)(b * QLEN + q0 + r)) * DMODEL + h * DH + c4);
        Qs[(c4+0)*ATT_STRIDE + r] = v.x * scale;
        Qs[(c4+1)*ATT_STRIDE + r] = v.y * scale;
        Qs[(c4+2)*ATT_STRIDE + r] = v.z * scale;
        Qs[(c4+3)*ATT_STRIDE + r] = v.w * scale;
    }

    float acc[4][4], dsum[4] = {0.f, 0.f, 0.f, 0.f};
#pragma unroll
    for (int i = 0; i < 4; i++)
#pragma unroll
        for (int j = 0; j < 4; j++) acc[i][j] = 0.f;

    for (int k0 = 0; k0 < KVLEN; k0 += 64) {
        __syncthreads();
#pragma unroll
        for (int i = 0; i < 4; i++) {
            int f = tid + 256 * i, r = f >> 4, c4 = (f & 15) * 4;
            size_t base = ((size_t)(b * KVLEN + k0 + r)) * DMODEL + h * DH + c4;
            float4 kv = *(const float4*)(kb + base);
            KP[(c4+0)*ATT_STRIDE + r] = kv.x;
            KP[(c4+1)*ATT_STRIDE + r] = kv.y;
            KP[(c4+2)*ATT_STRIDE + r] = kv.z;
            KP[(c4+3)*ATT_STRIDE + r] = kv.w;
            float4 vv = *(const float4*)(vb + base);
            *(float4*)&Vs[r * ATT_STRIDE + c4] = vv;
        }
        if (tid < 64) bs[tid] = bias[(size_t)b * KVLEN + k0 + tid];
        __syncthreads();

        float s[4][4];
#pragma unroll
        for (int i = 0; i < 4; i++)
#pragma unroll
            for (int j = 0; j < 4; j++) s[i][j] = 0.f;
#pragma unroll 8
        for (int kk = 0; kk < 64; kk++) {
            float a[4], bb[4];
            *(float4*)a  = *(const float4*)&Qs[kk * ATT_STRIDE + ty * 4];
            *(float4*)bb = *(const float4*)&KP[kk * ATT_STRIDE + tx * 4];
#pragma unroll
            for (int i = 0; i < 4; i++)
#pragma unroll
                for (int j = 0; j < 4; j++)
                    s[i][j] += a[i] * bb[j];
        }
#pragma unroll
        for (int j = 0; j < 4; j++) {
            float bj = bs[tx * 4 + j];
#pragma unroll
            for (int i = 0; i < 4; i++) {
                float p = __expf(s[i][j] + bj);
                s[i][j] = p;
                dsum[i] += p;
            }
        }
        __syncthreads();
#pragma unroll
        for (int j = 0; j < 4; j++)
#pragma unroll
            for (int i = 0; i < 4; i++)
                KP[(tx*4+j)*ATT_STRIDE + ty*4 + i] = s[i][j];
        __syncthreads();

#pragma unroll 8
        for (int kk = 0; kk < 64; kk++) {
            float a[4], bb[4];
            *(float4*)a  = *(const float4*)&KP[kk * ATT_STRIDE + ty * 4];
            *(float4*)bb = *(const float4*)&Vs[kk * ATT_STRIDE + tx * 4];
#pragma unroll
            for (int i = 0; i < 4; i++)
#pragma unroll
                for (int j = 0; j < 4; j++)
                    acc[i][j] += a[i] * bb[j];
        }
    }

#pragma unroll
    for (int i = 0; i < 4; i++) dred[ty * 4 + i][tx] = dsum[i];
    __syncthreads();
    if (tid < 64) {
        float t = 0.f;
#pragma unroll
        for (int c = 0; c < 16; c++) t += dred[tid][c];
        dfin[tid] = 1.0f / t;
    }
    __syncthreads();

#pragma unroll
    for (int i = 0; i < 4; i++) {
        int row = ty * 4 + i;
        float rinv = dfin[row];
        float4 v = make_float4(acc[i][0]*rinv, acc[i][1]*rinv, acc[i][2]*rinv, acc[i][3]*rinv);
        *(float4*)(ob + ((size_t)(b * QLEN + q0 + row)) * DMODEL + h * DH + tx * 4) = v;
    }
}

// ---------------------------------------------------------------------------
extern "C" void kernel_launch(void* const* d_in, const int* in_sizes, int n_in,
                              void* d_out, int out_size)
{
    const float* query  = (const float*)d_in[0];
    const float* memory = (const float*)d_in[1];
    const float* bias   = (const float*)d_in[2];
    const float* W[4]   = {(const float*)d_in[3], (const float*)d_in[4],
                           (const float*)d_in[5], (const float*)d_in[6]};
    float* out = (float*)d_out;

    float *qb, *kb, *vb, *ab;
    __nv_bfloat16 *mh, *ml, *qh, *ql, *ah, *al, *wh, *wl;
    cudaGetSymbolAddress((void**)&qb, g_q);
    cudaGetSymbolAddress((void**)&kb, g_k);
    cudaGetSymbolAddress((void**)&vb, g_v);
    cudaGetSymbolAddress((void**)&ab, g_att);
    cudaGetSymbolAddress((void**)&mh, g_mh);
    cudaGetSymbolAddress((void**)&ml, g_ml);
    cudaGetSymbolAddress((void**)&qh, g_qh);
    cudaGetSymbolAddress((void**)&ql, g_ql);
    cudaGetSymbolAddress((void**)&ah, g_ah);
    cudaGetSymbolAddress((void**)&al, g_al);
    cudaGetSymbolAddress((void**)&wh, g_wh);
    cudaGetSymbolAddress((void**)&wl, g_wl);

    cudaFuncSetAttribute(attn_kernel, cudaFuncAttributeMaxDynamicSharedMemorySize, ATT_SMEM);
    cudaFuncSetAttribute(gemm_mma, cudaFuncAttributeMaxDynamicSharedMemorySize, GEMM_SMEM);

    const int n_q  = BATCH * QLEN  * DMODEL;
    const int n_kv = BATCH * KVLEN * DMODEL;
    const int WSZ  = DMODEL * DMODEL;
    dim3 t32(32, 8), gT(DMODEL / 32, DMODEL / 32);

    k_split<<<2048, 256>>>(query,  qh, ql, n_q);
    k_split<<<4096, 256>>>(memory, mh, ml, n_kv);
    for (int w = 0; w < 4; w++)
        k_tsplit<<<gT, t32>>>(W[w], wh + (size_t)w * WSZ, wl + (size_t)w * WSZ);

    gemm_mma<<<dim3(DMODEL/128, (BATCH*QLEN)/128),  256, GEMM_SMEM>>>(qh, ql, wh + 0*(size_t)WSZ, wl + 0*(size_t)WSZ, qb, DMODEL);
    gemm_mma<<<dim3(DMODEL/128, (BATCH*KVLEN)/128), 256, GEMM_SMEM>>>(mh, ml, wh + 1*(size_t)WSZ, wl + 1*(size_t)WSZ, kb, DMODEL);
    gemm_mma<<<dim3(DMODEL/128, (BATCH*KVLEN)/128), 256, GEMM_SMEM>>>(mh, ml, wh + 2*(size_t)WSZ, wl + 2*(size_t)WSZ, vb, DMODEL);

    attn_kernel<<<dim3(QLEN/64, NHEAD, BATCH), 256, ATT_SMEM>>>(qb, kb, vb, bias, ab);

    k_split<<<2048, 256>>>(ab, ah, al, n_q);
    gemm_mma<<<dim3(DMODEL/128, (BATCH*QLEN)/128),  256, GEMM_SMEM>>>(ah, al, wh + 3*(size_t)WSZ, wl + 3*(size_t)WSZ, out, DMODEL);
}

// round 6
// speedup vs baseline: 2.5355x; 1.7011x over previous
#include <cuda_runtime.h>
#include <cuda_bf16.h>
#include <cstdint>
#include <math.h>

#define BATCH   4
#define QLEN    512
#define KVLEN   4096
#define DMODEL  1024
#define NHEAD   16
#define DH      64
#define GK      1024

// ---------------- scratch (allocation-free rule) ----------------
__device__ float g_q  [BATCH * QLEN  * DMODEL];
__device__ float g_k  [BATCH * KVLEN * DMODEL];
__device__ float g_v  [BATCH * KVLEN * DMODEL];
__device__ float g_att[BATCH * QLEN  * DMODEL];
__device__ __nv_bfloat16 g_mh[BATCH * KVLEN * DMODEL];
__device__ __nv_bfloat16 g_ml[BATCH * KVLEN * DMODEL];
__device__ __nv_bfloat16 g_qh[BATCH * QLEN  * DMODEL];
__device__ __nv_bfloat16 g_ql[BATCH * QLEN  * DMODEL];
__device__ __nv_bfloat16 g_ah[BATCH * QLEN  * DMODEL];
__device__ __nv_bfloat16 g_al[BATCH * QLEN  * DMODEL];
__device__ __nv_bfloat16 g_wh[4][DMODEL * DMODEL];
__device__ __nv_bfloat16 g_wl[4][DMODEL * DMODEL];
// projected tensors, split for attention
__device__ __nv_bfloat16 g_pqh[BATCH * QLEN  * DMODEL];
__device__ __nv_bfloat16 g_pql[BATCH * QLEN  * DMODEL];
__device__ __nv_bfloat16 g_pkh[BATCH * KVLEN * DMODEL];
__device__ __nv_bfloat16 g_pkl[BATCH * KVLEN * DMODEL];
__device__ __nv_bfloat16 g_vth[BATCH * DMODEL * KVLEN];   // [b, h*64+dh, kv]
__device__ __nv_bfloat16 g_vtl[BATCH * DMODEL * KVLEN];

#define CP_ASYNC16(d, s) asm volatile("cp.async.cg.shared.global [%0], [%1], 16;" :: "r"(d), "l"(s))

__device__ __forceinline__ void mma_bf16(float* c, const uint32_t* a, const uint32_t* b) {
    asm volatile(
        "mma.sync.aligned.m16n8k16.row.col.f32.bf16.bf16.f32 "
        "{%0,%1,%2,%3}, {%4,%5,%6,%7}, {%8,%9}, {%0,%1,%2,%3};"
        : "+f"(c[0]), "+f"(c[1]), "+f"(c[2]), "+f"(c[3])
        : "r"(a[0]), "r"(a[1]), "r"(a[2]), "r"(a[3]), "r"(b[0]), "r"(b[1]));
}

// split fp32 -> (hi, lo) bf16
__global__ void k_split(const float* __restrict__ x, __nv_bfloat16* __restrict__ hi,
                        __nv_bfloat16* __restrict__ lo, int n)
{
    for (int i = blockIdx.x * blockDim.x + threadIdx.x; i < n; i += gridDim.x * blockDim.x) {
        float v = x[i];
        __nv_bfloat16 h = __float2bfloat16(v);
        hi[i] = h;
        lo[i] = __float2bfloat16(v - __bfloat162float(h));
    }
}
// transpose + split W[k][n] -> Th[n][k], Tl[n][k]
__global__ void k_tsplit(const float* __restrict__ W, __nv_bfloat16* __restrict__ Th,
                         __nv_bfloat16* __restrict__ Tl)
{
    __shared__ float t[32][33];
    int k0 = blockIdx.y * 32, n0 = blockIdx.x * 32;
    int tx = threadIdx.x, ty = threadIdx.y;
#pragma unroll
    for (int i = 0; i < 4; i++)
        t[ty + 8 * i][tx] = W[(size_t)(k0 + ty + 8 * i) * DMODEL + n0 + tx];
    __syncthreads();
#pragma unroll
    for (int i = 0; i < 4; i++) {
        float v = t[tx][ty + 8 * i];
        __nv_bfloat16 h = __float2bfloat16(v);
        size_t o = (size_t)(n0 + ty + 8 * i) * DMODEL + k0 + tx;
        Th[o] = h;
        Tl[o] = __float2bfloat16(v - __bfloat162float(h));
    }
}
// transpose + split V[b][kv][d] -> Vt[b][d][kv] (hi/lo)
__global__ void k_vtsplit(const float* __restrict__ V, __nv_bfloat16* __restrict__ Th,
                          __nv_bfloat16* __restrict__ Tl)
{
    __shared__ float t[32][33];
    int kv0 = blockIdx.x * 32, d0 = blockIdx.y * 32, b = blockIdx.z;
    int tx = threadIdx.x, ty = threadIdx.y;
    const float* src = V + (size_t)b * KVLEN * DMODEL;
#pragma unroll
    for (int i = 0; i < 4; i++)
        t[ty + 8 * i][tx] = src[(size_t)(kv0 + ty + 8 * i) * DMODEL + d0 + tx];
    __syncthreads();
#pragma unroll
    for (int i = 0; i < 4; i++) {
        int d = d0 + ty + 8 * i, kv = kv0 + tx;
        float v = t[tx][ty + 8 * i];
        __nv_bfloat16 h = __float2bfloat16(v);
        size_t o = ((size_t)b * DMODEL + d) * KVLEN + kv;
        Th[o] = h;
        Tl[o] = __float2bfloat16(v - __bfloat162float(h));
    }
}

// ---------------------------------------------------------------------------
// mma.sync bf16-split GEMM (unchanged, bench-validated)
// ---------------------------------------------------------------------------
#define SKW   20
#define ARR_W (128 * SKW)
#define BUF_W (4 * ARR_W)
#define GEMM_SMEM (2 * BUF_W * 4)

__global__ __launch_bounds__(256, 2)
void gemm_mma(const __nv_bfloat16* __restrict__ Ah, const __nv_bfloat16* __restrict__ Al,
              const __nv_bfloat16* __restrict__ Bh, const __nv_bfloat16* __restrict__ Bl,
              float* __restrict__ C, int N)
{
    extern __shared__ __align__(16) uint32_t sm32[];
    const int tid  = threadIdx.x;
    const int wid  = tid >> 5, lane = tid & 31;
    const int g    = lane >> 2, tg = lane & 3;
    const int wm64 = (wid & 1) * 64;
    const int wn32 = (wid >> 1) * 32;
    const int bn = blockIdx.x, bm = blockIdx.y;

    const size_t arow0 = (size_t)bm * 128 * GK;
    const size_t brow0 = (size_t)bn * 128 * GK;
    const uint32_t smem_b = (uint32_t)__cvta_generic_to_shared(sm32);

    float acc[4][4][4];
#pragma unroll
    for (int mt = 0; mt < 4; mt++)
#pragma unroll
        for (int nt = 0; nt < 4; nt++)
#pragma unroll
            for (int r = 0; r < 4; r++) acc[mt][nt][r] = 0.f;

    auto load_tile = [&](int kt, int buf) {
        const __nv_bfloat16* srcs[4] = {
            Ah + arow0 + kt * 32, Al + arow0 + kt * 32,
            Bh + brow0 + kt * 32, Bl + brow0 + kt * 32 };
#pragma unroll
        for (int i = 0; i < 8; i++) {
            int chunk = tid + 256 * i;
            int arr = chunk >> 9;
            int w   = chunk & 511;
            int row = w >> 2, c = w & 3;
            uint32_t dst = smem_b + (buf * BUF_W + arr * ARR_W + row * SKW) * 4 + c * 16;
            CP_ASYNC16(dst, srcs[arr] + (size_t)row * GK + c * 8);
        }
        asm volatile("cp.async.commit_group;");
    };

    load_tile(0, 0);

    const int NT = GK / 32;
    for (int kt = 0; kt < NT; kt++) {
        const int buf = kt & 1;
        if (kt + 1 < NT) {
            load_tile(kt + 1, 1 - buf);
            asm volatile("cp.async.wait_group 1;");
        } else {
            asm volatile("cp.async.wait_group 0;");
        }
        __syncthreads();

        const uint32_t* Ahw = sm32 + buf * BUF_W;
        const uint32_t* Alw = Ahw + ARR_W;
        const uint32_t* Bhw = Ahw + 2 * ARR_W;
        const uint32_t* Blw = Ahw + 3 * ARR_W;

#pragma unroll
        for (int ks = 0; ks < 2; ks++) {
            uint32_t bh[4][2], bl[4][2];
#pragma unroll
            for (int nt = 0; nt < 4; nt++) {
                int base = (wn32 + nt * 8 + g) * SKW + ks * 8 + tg;
                bh[nt][0] = Bhw[base];  bh[nt][1] = Bhw[base + 4];
                bl[nt][0] = Blw[base];  bl[nt][1] = Blw[base + 4];
            }
#pragma unroll
            for (int mt = 0; mt < 4; mt++) {
                int base = (wm64 + mt * 16 + g) * SKW + ks * 8 + tg;
                uint32_t ah[4], al[4];
                ah[0] = Ahw[base];     ah[1] = Ahw[base + 8 * SKW];
                ah[2] = Ahw[base + 4]; ah[3] = Ahw[base + 8 * SKW + 4];
                al[0] = Alw[base];     al[1] = Alw[base + 8 * SKW];
                al[2] = Alw[base + 4]; al[3] = Alw[base + 8 * SKW + 4];
#pragma unroll
                for (int nt = 0; nt < 4; nt++) {
                    mma_bf16(acc[mt][nt], ah, bh[nt]);
                    mma_bf16(acc[mt][nt], ah, bl[nt]);
                    mma_bf16(acc[mt][nt], al, bh[nt]);
                }
            }
        }
        __syncthreads();
    }

#pragma unroll
    for (int mt = 0; mt < 4; mt++) {
        int row0 = bm * 128 + wm64 + mt * 16 + g;
#pragma unroll
        for (int nt = 0; nt < 4; nt++) {
            int col = bn * 128 + wn32 + nt * 8 + tg * 2;
            *(float2*)(C + (size_t)row0 * N + col)       = make_float2(acc[mt][nt][0], acc[mt][nt][1]);
            *(float2*)(C + (size_t)(row0 + 8) * N + col) = make_float2(acc[mt][nt][2], acc[mt][nt][3]);
        }
    }
}

// ---------------------------------------------------------------------------
// mma.sync bf16-split attention. CTA = (qtile 128, head, batch). 8 warps x 16 rows.
// kv blocks of 64, double-buffered. S and PV both split-2 (3 MMAs each).
// smem word layout: QH[128x36] QL[128x36] | K bufs | Vt bufs | bias bufs
// ---------------------------------------------------------------------------
#define AST    36                 // row stride in words (72 halves)
#define AQH    0
#define AQL    4608
#define AK_OFF 9216               // + buf*4608 ; [KH 2304][KL 2304]
#define AV_OFF 18432              // + buf*4608 ; [VH 2304][VL 2304]
#define AB_OFF 27648              // + buf*64
#define ATTN_SMEM ((27648 + 128) * 4)

__global__ __launch_bounds__(256, 1)
void attn_mma(const __nv_bfloat16* __restrict__ Qh, const __nv_bfloat16* __restrict__ Ql,
              const __nv_bfloat16* __restrict__ Kh, const __nv_bfloat16* __restrict__ Kl,
              const __nv_bfloat16* __restrict__ Vh, const __nv_bfloat16* __restrict__ Vl,
              const float* __restrict__ bias, float* __restrict__ ob)
{
    extern __shared__ __align__(16) uint32_t sw[];
    const uint32_t sb = (uint32_t)__cvta_generic_to_shared(sw);
    const int tid = threadIdx.x, wid = tid >> 5, lane = tid & 31;
    const int g = lane >> 2, tg = lane & 3;
    const int qt = blockIdx.x, h = blockIdx.y, b = blockIdx.z;
    const int q0 = qt * 128;

    // ---- Q load (once): [128 rows][64 halves] hi+lo ----
    {
        const __nv_bfloat16* s0 = Qh + ((size_t)(b * QLEN + q0)) * DMODEL + h * DH;
        const __nv_bfloat16* s1 = Ql + ((size_t)(b * QLEN + q0)) * DMODEL + h * DH;
#pragma unroll
        for (int i = 0; i < 8; i++) {
            int chunk = tid + 256 * i;      // 0..2047
            int arr = i >> 2;               // 0=hi 1=lo (compile-time)
            int c5 = chunk & 1023;
            int r = c5 >> 3, c = c5 & 7;
            const __nv_bfloat16* s = arr ? s1 : s0;
            uint32_t dst = sb + ((arr ? AQL : AQH) + r * AST + c * 4) * 4;
            CP_ASYNC16(dst, s + (size_t)r * DMODEL + c * 8);
        }
        asm volatile("cp.async.commit_group;");
    }

    auto load_tile = [&](int kt, int buf) {
        const int k0 = kt * 64;
        const __nv_bfloat16* kh = Kh + ((size_t)(b * KVLEN + k0)) * DMODEL + h * DH;
        const __nv_bfloat16* kl = Kl + ((size_t)(b * KVLEN + k0)) * DMODEL + h * DH;
        const __nv_bfloat16* vh = Vh + ((size_t)(b * DMODEL + h * DH)) * KVLEN + k0;
        const __nv_bfloat16* vl = Vl + ((size_t)(b * DMODEL + h * DH)) * KVLEN + k0;
#pragma unroll
        for (int i = 0; i < 8; i++) {
            int chunk = tid + 256 * i;
            int arr = i >> 1;               // 0=KH 1=KL 2=VH 3=VL (compile-time)
            int w = chunk & 511;
            int r = w >> 3, c = w & 7;
            const __nv_bfloat16* src = (arr == 0) ? kh : (arr == 1) ? kl : (arr == 2) ? vh : vl;
            size_t rstride = (arr < 2) ? DMODEL : KVLEN;
            uint32_t base = (arr < 2 ? AK_OFF : AV_OFF) + buf * 4608 + (arr & 1) * 2304;
            uint32_t dst = sb + (base + r * AST + c * 4) * 4;
            CP_ASYNC16(dst, src + (size_t)r * rstride + c * 8);
        }
        if (tid < 16) {
            uint32_t dst = sb + (AB_OFF + buf * 64 + tid * 4) * 4;
            CP_ASYNC16(dst, bias + (size_t)b * KVLEN + k0 + tid * 4);
        }
        asm volatile("cp.async.commit_group;");
    };

    float oacc[8][4];
#pragma unroll
    for (int nt = 0; nt < 8; nt++)
#pragma unroll
        for (int r = 0; r < 4; r++) oacc[nt][r] = 0.f;
    float dsum0 = 0.f, dsum1 = 0.f;

    load_tile(0, 0);
    const int NT = KVLEN / 64;
    const int qrow = wid * 16;

    for (int kt = 0; kt < NT; kt++) {
        const int buf = kt & 1;
        if (kt + 1 < NT) {
            load_tile(kt + 1, 1 - buf);
            asm volatile("cp.async.wait_group 1;");
        } else {
            asm volatile("cp.async.wait_group 0;");
        }
        __syncthreads();

        // ---- S = Q . K^T (split-2) ----
        float sacc[8][4];
#pragma unroll
        for (int nt = 0; nt < 8; nt++)
#pragma unroll
            for (int r = 0; r < 4; r++) sacc[nt][r] = 0.f;

        const int kbase0 = AK_OFF + buf * 4608;
#pragma unroll
        for (int ks = 0; ks < 4; ks++) {
            const int abase = (qrow + g) * AST + ks * 8 + tg;
            uint32_t aH[4], aL[4];
            aH[0] = sw[AQH + abase];     aH[1] = sw[AQH + abase + 8 * AST];
            aH[2] = sw[AQH + abase + 4]; aH[3] = sw[AQH + abase + 8 * AST + 4];
            aL[0] = sw[AQL + abase];     aL[1] = sw[AQL + abase + 8 * AST];
            aL[2] = sw[AQL + abase + 4]; aL[3] = sw[AQL + abase + 8 * AST + 4];
#pragma unroll
            for (int nt = 0; nt < 8; nt++) {
                const int bbase = kbase0 + (nt * 8 + g) * AST + ks * 8 + tg;
                uint32_t bH[2] = { sw[bbase], sw[bbase + 4] };
                uint32_t bL[2] = { sw[bbase + 2304], sw[bbase + 2304 + 4] };
                mma_bf16(sacc[nt], aH, bH);
                mma_bf16(sacc[nt], aH, bL);
                mma_bf16(sacc[nt], aL, bH);
            }
        }

        // ---- P = exp(S*scale + bias); accumulate denominators ----
        const float* bsm = (const float*)(sw + AB_OFF + buf * 64);
#pragma unroll
        for (int nt = 0; nt < 8; nt++) {
            float b0 = bsm[nt * 8 + tg * 2];
            float b1 = bsm[nt * 8 + tg * 2 + 1];
            float p0 = __expf(fmaf(sacc[nt][0], 0.125f, b0));
            float p1 = __expf(fmaf(sacc[nt][1], 0.125f, b1));
            float p2 = __expf(fmaf(sacc[nt][2], 0.125f, b0));
            float p3 = __expf(fmaf(sacc[nt][3], 0.125f, b1));
            sacc[nt][0] = p0; sacc[nt][1] = p1; sacc[nt][2] = p2; sacc[nt][3] = p3;
            dsum0 += p0 + p1;
            dsum1 += p2 + p3;
        }

        // ---- O += P . V (split-2; P frags built from registers) ----
        const int vbase0 = AV_OFF + buf * 4608;
#pragma unroll
        for (int ks = 0; ks < 4; ks++) {
            const float* pa = sacc[2 * ks];
            const float* pb = sacc[2 * ks + 1];
            __nv_bfloat162 h0 = __floats2bfloat162_rn(pa[0], pa[1]);
            __nv_bfloat162 h1 = __floats2bfloat162_rn(pa[2], pa[3]);
            __nv_bfloat162 h2 = __floats2bfloat162_rn(pb[0], pb[1]);
            __nv_bfloat162 h3 = __floats2bfloat162_rn(pb[2], pb[3]);
            __nv_bfloat162 l0 = __floats2bfloat162_rn(pa[0] - __bfloat162float(h0.x), pa[1] - __bfloat162float(h0.y));
            __nv_bfloat162 l1 = __floats2bfloat162_rn(pa[2] - __bfloat162float(h1.x), pa[3] - __bfloat162float(h1.y));
            __nv_bfloat162 l2 = __floats2bfloat162_rn(pb[0] - __bfloat162float(h2.x), pb[1] - __bfloat162float(h2.y));
            __nv_bfloat162 l3 = __floats2bfloat162_rn(pb[2] - __bfloat162float(h3.x), pb[3] - __bfloat162float(h3.y));
            uint32_t aPh[4] = { *(uint32_t*)&h0, *(uint32_t*)&h1, *(uint32_t*)&h2, *(uint32_t*)&h3 };
            uint32_t aPl[4] = { *(uint32_t*)&l0, *(uint32_t*)&l1, *(uint32_t*)&l2, *(uint32_t*)&l3 };
#pragma unroll
            for (int nt = 0; nt < 8; nt++) {
                const int bbase = vbase0 + (nt * 8 + g) * AST + ks * 8 + tg;
                uint32_t bH[2] = { sw[bbase], sw[bbase + 4] };
                uint32_t bL[2] = { sw[bbase + 2304], sw[bbase + 2304 + 4] };
                mma_bf16(oacc[nt], aPh, bH);
                mma_bf16(oacc[nt], aPh, bL);
                mma_bf16(oacc[nt], aPl, bH);
            }
        }
        __syncthreads();
    }

    // ---- denominators: reduce across the quad (lanes sharing a row) ----
    dsum0 += __shfl_xor_sync(0xFFFFFFFFu, dsum0, 1);
    dsum0 += __shfl_xor_sync(0xFFFFFFFFu, dsum0, 2);
    dsum1 += __shfl_xor_sync(0xFFFFFFFFu, dsum1, 1);
    dsum1 += __shfl_xor_sync(0xFFFFFFFFu, dsum1, 2);
    const float inv0 = 1.f / dsum0, inv1 = 1.f / dsum1;

    const int row = b * QLEN + q0 + qrow + g;
#pragma unroll
    for (int nt = 0; nt < 8; nt++) {
        const int col = h * DH + nt * 8 + tg * 2;
        *(float2*)(ob + (size_t)row * DMODEL + col) =
            make_float2(oacc[nt][0] * inv0, oacc[nt][1] * inv0);
        *(float2*)(ob + (size_t)(row + 8) * DMODEL + col) =
            make_float2(oacc[nt][2] * inv1, oacc[nt][3] * inv1);
    }
}

// ---------------------------------------------------------------------------
extern "C" void kernel_launch(void* const* d_in, const int* in_sizes, int n_in,
                              void* d_out, int out_size)
{
    const float* query  = (const float*)d_in[0];
    const float* memory = (const float*)d_in[1];
    const float* bias   = (const float*)d_in[2];
    const float* W[4]   = {(const float*)d_in[3], (const float*)d_in[4],
                           (const float*)d_in[5], (const float*)d_in[6]};
    float* out = (float*)d_out;

    float *qb, *kb, *vb, *ab;
    __nv_bfloat16 *mh, *ml, *qh, *ql, *ah, *al, *wh, *wl;
    __nv_bfloat16 *pqh, *pql, *pkh, *pkl, *vth, *vtl;
    cudaGetSymbolAddress((void**)&qb, g_q);
    cudaGetSymbolAddress((void**)&kb, g_k);
    cudaGetSymbolAddress((void**)&vb, g_v);
    cudaGetSymbolAddress((void**)&ab, g_att);
    cudaGetSymbolAddress((void**)&mh, g_mh);
    cudaGetSymbolAddress((void**)&ml, g_ml);
    cudaGetSymbolAddress((void**)&qh, g_qh);
    cudaGetSymbolAddress((void**)&ql, g_ql);
    cudaGetSymbolAddress((void**)&ah, g_ah);
    cudaGetSymbolAddress((void**)&al, g_al);
    cudaGetSymbolAddress((void**)&wh, g_wh);
    cudaGetSymbolAddress((void**)&wl, g_wl);
    cudaGetSymbolAddress((void**)&pqh, g_pqh);
    cudaGetSymbolAddress((void**)&pql, g_pql);
    cudaGetSymbolAddress((void**)&pkh, g_pkh);
    cudaGetSymbolAddress((void**)&pkl, g_pkl);
    cudaGetSymbolAddress((void**)&vth, g_vth);
    cudaGetSymbolAddress((void**)&vtl, g_vtl);

    cudaFuncSetAttribute(gemm_mma, cudaFuncAttributeMaxDynamicSharedMemorySize, GEMM_SMEM);
    cudaFuncSetAttribute(attn_mma, cudaFuncAttributeMaxDynamicSharedMemorySize, ATTN_SMEM);

    const int n_q  = BATCH * QLEN  * DMODEL;
    const int n_kv = BATCH * KVLEN * DMODEL;
    const int WSZ  = DMODEL * DMODEL;
    dim3 t32(32, 8), gT(DMODEL / 32, DMODEL / 32);

    // input splits
    k_split<<<2048, 256>>>(query,  qh, ql, n_q);
    k_split<<<4096, 256>>>(memory, mh, ml, n_kv);
    for (int w = 0; w < 4; w++)
        k_tsplit<<<gT, t32>>>(W[w], wh + (size_t)w * WSZ, wl + (size_t)w * WSZ);

    // projections
    gemm_mma<<<dim3(DMODEL/128, (BATCH*QLEN)/128),  256, GEMM_SMEM>>>(qh, ql, wh + 0*(size_t)WSZ, wl + 0*(size_t)WSZ, qb, DMODEL);
    gemm_mma<<<dim3(DMODEL/128, (BATCH*KVLEN)/128), 256, GEMM_SMEM>>>(mh, ml, wh + 1*(size_t)WSZ, wl + 1*(size_t)WSZ, kb, DMODEL);
    gemm_mma<<<dim3(DMODEL/128, (BATCH*KVLEN)/128), 256, GEMM_SMEM>>>(mh, ml, wh + 2*(size_t)WSZ, wl + 2*(size_t)WSZ, vb, DMODEL);

    // splits for attention
    k_split<<<2048, 256>>>(qb, pqh, pql, n_q);
    k_split<<<4096, 256>>>(kb, pkh, pkl, n_kv);
    k_vtsplit<<<dim3(KVLEN/32, DMODEL/32, BATCH), t32>>>(vb, vth, vtl);

    // attention
    attn_mma<<<dim3(QLEN/128, NHEAD, BATCH), 256, ATTN_SMEM>>>(pqh, pql, pkh, pkl, vth, vtl, bias, ab);

    // output projection
    k_split<<<2048, 256>>>(ab, ah, al, n_q);
    gemm_mma<<<dim3(DMODEL/128, (BATCH*QLEN)/128),  256, GEMM_SMEM>>>(ah, al, wh + 3*(size_t)WSZ, wl + 3*(size_t)WSZ, out, DMODEL);
}

// round 8
// speedup vs baseline: 2.7662x; 1.0910x over previous
#include <cuda_runtime.h>
#include <cuda_bf16.h>
#include <cstdint>
#include <math.h>

#define BATCH   4
#define QLEN    512
#define KVLEN   4096
#define DMODEL  1024
#define NHEAD   16
#define DH      64
#define GK      1024

// ---------------- scratch (allocation-free rule) ----------------
__device__ float g_v  [BATCH * KVLEN * DMODEL];   // V projection (fp32, pre-transpose)
__device__ __nv_bfloat16 g_mh[BATCH * KVLEN * DMODEL];
__device__ __nv_bfloat16 g_ml[BATCH * KVLEN * DMODEL];
__device__ __nv_bfloat16 g_qh[BATCH * QLEN  * DMODEL];
__device__ __nv_bfloat16 g_ql[BATCH * QLEN  * DMODEL];
__device__ __nv_bfloat16 g_ah[BATCH * QLEN  * DMODEL];   // attention out split
__device__ __nv_bfloat16 g_al[BATCH * QLEN  * DMODEL];
__device__ __nv_bfloat16 g_wh[4][DMODEL * DMODEL];
__device__ __nv_bfloat16 g_wl[4][DMODEL * DMODEL];
__device__ __nv_bfloat16 g_pqh[BATCH * QLEN  * DMODEL];  // Q proj split
__device__ __nv_bfloat16 g_pql[BATCH * QLEN  * DMODEL];
__device__ __nv_bfloat16 g_pkh[BATCH * KVLEN * DMODEL];  // K proj split
__device__ __nv_bfloat16 g_pkl[BATCH * KVLEN * DMODEL];
__device__ __nv_bfloat16 g_vth[BATCH * DMODEL * KVLEN];  // V^T split [b, d, kv]
__device__ __nv_bfloat16 g_vtl[BATCH * DMODEL * KVLEN];

#define CP_ASYNC16(d, s) asm volatile("cp.async.cg.shared.global [%0], [%1], 16;" :: "r"(d), "l"(s))
#define LDSM_X4(r, a) \
    asm volatile("ldmatrix.sync.aligned.m8n8.x4.shared.b16 {%0,%1,%2,%3}, [%4];" \
        : "=r"((r)[0]), "=r"((r)[1]), "=r"((r)[2]), "=r"((r)[3]) : "r"(a))

__device__ __forceinline__ void mma_bf16(float* c, const uint32_t* a, const uint32_t* b) {
    asm volatile(
        "mma.sync.aligned.m16n8k16.row.col.f32.bf16.bf16.f32 "
        "{%0,%1,%2,%3}, {%4,%5,%6,%7}, {%8,%9}, {%0,%1,%2,%3};"
        : "+f"(c[0]), "+f"(c[1]), "+f"(c[2]), "+f"(c[3])
        : "r"(a[0]), "r"(a[1]), "r"(a[2]), "r"(a[3]), "r"(b[0]), "r"(b[1]));
}
__device__ __forceinline__ void split2(float v0, float v1, uint32_t& h, uint32_t& l) {
    __nv_bfloat162 hh = __floats2bfloat162_rn(v0, v1);
    __nv_bfloat162 ll = __floats2bfloat162_rn(v0 - __bfloat162float(hh.x),
                                              v1 - __bfloat162float(hh.y));
    h = *(uint32_t*)&hh;  l = *(uint32_t*)&ll;
}

// split fp32 -> (hi, lo) bf16
__global__ void k_split(const float* __restrict__ x, __nv_bfloat16* __restrict__ hi,
                        __nv_bfloat16* __restrict__ lo, int n)
{
    for (int i = blockIdx.x * blockDim.x + threadIdx.x; i < n; i += gridDim.x * blockDim.x) {
        float v = x[i];
        __nv_bfloat16 h = __float2bfloat16(v);
        hi[i] = h;
        lo[i] = __float2bfloat16(v - __bfloat162float(h));
    }
}
// transpose + split W[k][n] -> Th[n][k], Tl[n][k]
__global__ void k_tsplit(const float* __restrict__ W, __nv_bfloat16* __restrict__ Th,
                         __nv_bfloat16* __restrict__ Tl)
{
    __shared__ float t[32][33];
    int k0 = blockIdx.y * 32, n0 = blockIdx.x * 32;
    int tx = threadIdx.x, ty = threadIdx.y;
#pragma unroll
    for (int i = 0; i < 4; i++)
        t[ty + 8 * i][tx] = W[(size_t)(k0 + ty + 8 * i) * DMODEL + n0 + tx];
    __syncthreads();
#pragma unroll
    for (int i = 0; i < 4; i++) {
        float v = t[tx][ty + 8 * i];
        __nv_bfloat16 h = __float2bfloat16(v);
        size_t o = (size_t)(n0 + ty + 8 * i) * DMODEL + k0 + tx;
        Th[o] = h;
        Tl[o] = __float2bfloat16(v - __bfloat162float(h));
    }
}
// transpose + split V[b][kv][d] -> Vt[b][d][kv]
__global__ void k_vtsplit(const float* __restrict__ V, __nv_bfloat16* __restrict__ Th,
                          __nv_bfloat16* __restrict__ Tl)
{
    __shared__ float t[32][33];
    int kv0 = blockIdx.x * 32, d0 = blockIdx.y * 32, b = blockIdx.z;
    int tx = threadIdx.x, ty = threadIdx.y;
    const float* src = V + (size_t)b * KVLEN * DMODEL;
#pragma unroll
    for (int i = 0; i < 4; i++)
        t[ty + 8 * i][tx] = src[(size_t)(kv0 + ty + 8 * i) * DMODEL + d0 + tx];
    __syncthreads();
#pragma unroll
    for (int i = 0; i < 4; i++) {
        int d = d0 + ty + 8 * i, kv = kv0 + tx;
        float v = t[tx][ty + 8 * i];
        __nv_bfloat16 h = __float2bfloat16(v);
        size_t o = ((size_t)b * DMODEL + d) * KVLEN + kv;
        Th[o] = h;
        Tl[o] = __float2bfloat16(v - __bfloat162float(h));
    }
}

// ---------------------------------------------------------------------------
// mma.sync bf16-split GEMM; ldmatrix fragments; optional fused-split epilogue.
// ---------------------------------------------------------------------------
#define SKW   20
#define ARR_W (128 * SKW)
#define BUF_W (4 * ARR_W)
#define GEMM_SMEM (2 * BUF_W * 4)

__global__ __launch_bounds__(256, 2)
void gemm_mma(const __nv_bfloat16* __restrict__ Ah, const __nv_bfloat16* __restrict__ Al,
              const __nv_bfloat16* __restrict__ Bh, const __nv_bfloat16* __restrict__ Bl,
              float* __restrict__ C, __nv_bfloat16* __restrict__ Chi,
              __nv_bfloat16* __restrict__ Clo, int N)
{
    extern __shared__ __align__(16) uint32_t sm32[];
    const int tid  = threadIdx.x;
    const int wid  = tid >> 5, lane = tid & 31;
    const int g    = lane >> 2, tg = lane & 3;
    const int r8   = lane & 7, sub = lane >> 3;     // ldmatrix lane decomposition
    const int wm64 = (wid & 1) * 64;
    const int wn32 = (wid >> 1) * 32;
    const int bn = blockIdx.x, bm = blockIdx.y;

    const size_t arow0 = (size_t)bm * 128 * GK;
    const size_t brow0 = (size_t)bn * 128 * GK;
    const uint32_t smem_b = (uint32_t)__cvta_generic_to_shared(sm32);

    // per-lane ldmatrix base offsets (word units)
    const int a_row = wm64 + r8 + ((sub & 1) << 3);       // A: m row for this lane
    const int a_col = (sub >> 1) << 2;                     // k-half (+4 words)
    const int b_row = wn32 + r8;                           // B: n row
    const int b_col = ((sub & 1) << 2);                    // k-half
    const int b_arr = (sub >> 1) * ARR_W;                  // hi (0) / lo (+ARR_W)

    float acc[4][4][4];
#pragma unroll
    for (int mt = 0; mt < 4; mt++)
#pragma unroll
        for (int nt = 0; nt < 4; nt++)
#pragma unroll
            for (int r = 0; r < 4; r++) acc[mt][nt][r] = 0.f;

    auto load_tile = [&](int kt, int buf) {
        const __nv_bfloat16* srcs[4] = {
            Ah + arow0 + kt * 32, Al + arow0 + kt * 32,
            Bh + brow0 + kt * 32, Bl + brow0 + kt * 32 };
#pragma unroll
        for (int i = 0; i < 8; i++) {
            int chunk = tid + 256 * i;
            int arr = chunk >> 9;
            int w   = chunk & 511;
            int row = w >> 2, c = w & 3;
            uint32_t dst = smem_b + (buf * BUF_W + arr * ARR_W + row * SKW) * 4 + c * 16;
            CP_ASYNC16(dst, srcs[arr] + (size_t)row * GK + c * 8);
        }
        asm volatile("cp.async.commit_group;");
    };

    load_tile(0, 0);

    const int NT = GK / 32;
    for (int kt = 0; kt < NT; kt++) {
        const int buf = kt & 1;
        if (kt + 1 < NT) {
            load_tile(kt + 1, 1 - buf);
            asm volatile("cp.async.wait_group 1;");
        } else {
            asm volatile("cp.async.wait_group 0;");
        }
        __syncthreads();

        const uint32_t bufw = buf * BUF_W;
#pragma unroll
        for (int ks = 0; ks < 2; ks++) {
            // B fragments: one x4 per nt loads hi(r0,r1) + lo(r2,r3)
            uint32_t bf[4][4];
#pragma unroll
            for (int nt = 0; nt < 4; nt++) {
                uint32_t addr = smem_b + (bufw + 2 * ARR_W + b_arr
                                + (b_row + nt * 8) * SKW + ks * 8 + b_col) * 4;
                LDSM_X4(bf[nt], addr);
            }
#pragma unroll
            for (int mt = 0; mt < 4; mt++) {
                uint32_t ah[4], al[4];
                uint32_t aaddr = smem_b + (bufw + (a_row + mt * 16) * SKW + ks * 8 + a_col) * 4;
                LDSM_X4(ah, aaddr);
                LDSM_X4(al, aaddr + ARR_W * 4);
#pragma unroll
                for (int nt = 0; nt < 4; nt++) {
                    mma_bf16(acc[mt][nt], ah, bf[nt]);          // hi*hi
                    mma_bf16(acc[mt][nt], ah, bf[nt] + 2);      // hi*lo
                    mma_bf16(acc[mt][nt], al, bf[nt]);          // lo*hi
                }
            }
        }
        __syncthreads();
    }

    // epilogue
#pragma unroll
    for (int mt = 0; mt < 4; mt++) {
        int row0 = bm * 128 + wm64 + mt * 16 + g;
#pragma unroll
        for (int nt = 0; nt < 4; nt++) {
            int col = bn * 128 + wn32 + nt * 8 + tg * 2;
            if (C) {
                *(float2*)(C + (size_t)row0 * N + col)       = make_float2(acc[mt][nt][0], acc[mt][nt][1]);
                *(float2*)(C + (size_t)(row0 + 8) * N + col) = make_float2(acc[mt][nt][2], acc[mt][nt][3]);
            }
            if (Chi) {
                uint32_t h0, l0, h1, l1;
                split2(acc[mt][nt][0], acc[mt][nt][1], h0, l0);
                split2(acc[mt][nt][2], acc[mt][nt][3], h1, l1);
                *(uint32_t*)(Chi + (size_t)row0 * N + col)       = h0;
                *(uint32_t*)(Clo + (size_t)row0 * N + col)       = l0;
                *(uint32_t*)(Chi + (size_t)(row0 + 8) * N + col) = h1;
                *(uint32_t*)(Clo + (size_t)(row0 + 8) * N + col) = l1;
            }
        }
    }
}

// ---------------------------------------------------------------------------
// mma.sync bf16-split attention with ldmatrix; writes split (hi/lo) output.
// ---------------------------------------------------------------------------
#define AST    36
#define AQH    0
#define AQL    4608
#define AK_OFF 9216
#define AV_OFF 18432
#define AB_OFF 27648
#define ATTN_SMEM ((27648 + 128) * 4)

__global__ __launch_bounds__(256, 1)
void attn_mma(const __nv_bfloat16* __restrict__ Qh, const __nv_bfloat16* __restrict__ Ql,
              const __nv_bfloat16* __restrict__ Kh, const __nv_bfloat16* __restrict__ Kl,
              const __nv_bfloat16* __restrict__ Vh, const __nv_bfloat16* __restrict__ Vl,
              const float* __restrict__ bias,
              __nv_bfloat16* __restrict__ oh, __nv_bfloat16* __restrict__ ol)
{
    extern __shared__ __align__(16) uint32_t sw[];
    const uint32_t sb = (uint32_t)__cvta_generic_to_shared(sw);
    const int tid = threadIdx.x, wid = tid >> 5, lane = tid & 31;
    const int g = lane >> 2, tg = lane & 3;
    const int r8 = lane & 7, sub = lane >> 3;
    const int qt = blockIdx.x, h = blockIdx.y, b = blockIdx.z;
    const int q0 = qt * 128;
    const int qrow = wid * 16;

    // ldmatrix per-lane bases
    const int a_row = qrow + r8 + ((sub & 1) << 3);
    const int a_col = (sub >> 1) << 2;
    const int b_row = r8;                       // + nt*8
    const int b_col = ((sub & 1) << 2);
    const int b_arr = (sub >> 1) * 2304;        // hi / lo within K or V block

    // ---- Q load (once) ----
    {
        const __nv_bfloat16* s0 = Qh + ((size_t)(b * QLEN + q0)) * DMODEL + h * DH;
        const __nv_bfloat16* s1 = Ql + ((size_t)(b * QLEN + q0)) * DMODEL + h * DH;
#pragma unroll
        for (int i = 0; i < 8; i++) {
            int chunk = tid + 256 * i;
            int arr = i >> 2;
            int c5 = chunk & 1023;
            int r = c5 >> 3, c = c5 & 7;
            const __nv_bfloat16* s = arr ? s1 : s0;
            uint32_t dst = sb + ((arr ? AQL : AQH) + r * AST + c * 4) * 4;
            CP_ASYNC16(dst, s + (size_t)r * DMODEL + c * 8);
        }
        asm volatile("cp.async.commit_group;");
    }

    auto load_tile = [&](int kt, int buf) {
        const int k0 = kt * 64;
        const __nv_bfloat16* kh = Kh + ((size_t)(b * KVLEN + k0)) * DMODEL + h * DH;
        const __nv_bfloat16* kl = Kl + ((size_t)(b * KVLEN + k0)) * DMODEL + h * DH;
        const __nv_bfloat16* vh = Vh + ((size_t)(b * DMODEL + h * DH)) * KVLEN + k0;
        const __nv_bfloat16* vl = Vl + ((size_t)(b * DMODEL + h * DH)) * KVLEN + k0;
#pragma unroll
        for (int i = 0; i < 8; i++) {
            int chunk = tid + 256 * i;
            int arr = i >> 1;
            int w = chunk & 511;
            int r = w >> 3, c = w & 7;
            const __nv_bfloat16* src = (arr == 0) ? kh : (arr == 1) ? kl : (arr == 2) ? vh : vl;
            size_t rstride = (arr < 2) ? DMODEL : KVLEN;
            uint32_t base = (arr < 2 ? AK_OFF : AV_OFF) + buf * 4608 + (arr & 1) * 2304;
            uint32_t dst = sb + (base + r * AST + c * 4) * 4;
            CP_ASYNC16(dst, src + (size_t)r * rstride + c * 8);
        }
        if (tid < 16) {
            uint32_t dst = sb + (AB_OFF + buf * 64 + tid * 4) * 4;
            CP_ASYNC16(dst, bias + (size_t)b * KVLEN + kt * 64 + tid * 4);
        }
        asm volatile("cp.async.commit_group;");
    };

    float oacc[8][4];
#pragma unroll
    for (int nt = 0; nt < 8; nt++)
#pragma unroll
        for (int r = 0; r < 4; r++) oacc[nt][r] = 0.f;
    float dsum0 = 0.f, dsum1 = 0.f;

    load_tile(0, 0);
    const int NT = KVLEN / 64;

    for (int kt = 0; kt < NT; kt++) {
        const int buf = kt & 1;
        if (kt + 1 < NT) {
            load_tile(kt + 1, 1 - buf);
            asm volatile("cp.async.wait_group 1;");
        } else {
            asm volatile("cp.async.wait_group 0;");
        }
        __syncthreads();

        // ---- S = Q . K^T (split-2) ----
        float sacc[8][4];
#pragma unroll
        for (int nt = 0; nt < 8; nt++)
#pragma unroll
            for (int r = 0; r < 4; r++) sacc[nt][r] = 0.f;

        const uint32_t kbase = AK_OFF + buf * 4608;
#pragma unroll
        for (int ks = 0; ks < 4; ks++) {
            uint32_t aH[4], aL[4];
            uint32_t aaddr = sb + (a_row * AST + ks * 8 + a_col) * 4;
            LDSM_X4(aH, aaddr + AQH * 4);
            LDSM_X4(aL, aaddr + AQL * 4);
#pragma unroll
            for (int nt = 0; nt < 8; nt++) {
                uint32_t bf[4];
                uint32_t baddr = sb + (kbase + b_arr + (b_row + nt * 8) * AST + ks * 8 + b_col) * 4;
                LDSM_X4(bf, baddr);
                mma_bf16(sacc[nt], aH, bf);
                mma_bf16(sacc[nt], aH, bf + 2);
                mma_bf16(sacc[nt], aL, bf);
            }
        }

        // ---- P = exp(S*scale + bias) ----
        const float* bsm = (const float*)(sw + AB_OFF + buf * 64);
#pragma unroll
        for (int nt = 0; nt < 8; nt++) {
            float b0 = bsm[nt * 8 + tg * 2];
            float b1 = bsm[nt * 8 + tg * 2 + 1];
            float p0 = __expf(fmaf(sacc[nt][0], 0.125f, b0));
            float p1 = __expf(fmaf(sacc[nt][1], 0.125f, b1));
            float p2 = __expf(fmaf(sacc[nt][2], 0.125f, b0));
            float p3 = __expf(fmaf(sacc[nt][3], 0.125f, b1));
            sacc[nt][0] = p0; sacc[nt][1] = p1; sacc[nt][2] = p2; sacc[nt][3] = p3;
            dsum0 += p0 + p1;
            dsum1 += p2 + p3;
        }

        // ---- O += P . V (split-2, P frags register-built) ----
        const uint32_t vbase = AV_OFF + buf * 4608;
#pragma unroll
        for (int ks = 0; ks < 4; ks++) {
            const float* pa = sacc[2 * ks];
            const float* pb = sacc[2 * ks + 1];
            uint32_t aPh[4], aPl[4];
            split2(pa[0], pa[1], aPh[0], aPl[0]);
            split2(pa[2], pa[3], aPh[1], aPl[1]);
            split2(pb[0], pb[1], aPh[2], aPl[2]);
            split2(pb[2], pb[3], aPh[3], aPl[3]);
#pragma unroll
            for (int nt = 0; nt < 8; nt++) {
                uint32_t bf[4];
                uint32_t baddr = sb + (vbase + b_arr + (b_row + nt * 8) * AST + ks * 8 + b_col) * 4;
                LDSM_X4(bf, baddr);
                mma_bf16(oacc[nt], aPh, bf);
                mma_bf16(oacc[nt], aPh, bf + 2);
                mma_bf16(oacc[nt], aPl, bf);
            }
        }
        __syncthreads();
    }

    // ---- denominators (quad reduce) ----
    dsum0 += __shfl_xor_sync(0xFFFFFFFFu, dsum0, 1);
    dsum0 += __shfl_xor_sync(0xFFFFFFFFu, dsum0, 2);
    dsum1 += __shfl_xor_sync(0xFFFFFFFFu, dsum1, 1);
    dsum1 += __shfl_xor_sync(0xFFFFFFFFu, dsum1, 2);
    const float inv0 = 1.f / dsum0, inv1 = 1.f / dsum1;

    const int row = b * QLEN + q0 + qrow + g;
#pragma unroll
    for (int nt = 0; nt < 8; nt++) {
        const int col = h * DH + nt * 8 + tg * 2;
        uint32_t h0, l0, h1, l1;
        split2(oacc[nt][0] * inv0, oacc[nt][1] * inv0, h0, l0);
        split2(oacc[nt][2] * inv1, oacc[nt][3] * inv1, h1, l1);
        *(uint32_t*)(oh + (size_t)row * DMODEL + col)       = h0;
        *(uint32_t*)(ol + (size_t)row * DMODEL + col)       = l0;
        *(uint32_t*)(oh + (size_t)(row + 8) * DMODEL + col) = h1;
        *(uint32_t*)(ol + (size_t)(row + 8) * DMODEL + col) = l1;
    }
}

// ---------------------------------------------------------------------------
extern "C" void kernel_launch(void* const* d_in, const int* in_sizes, int n_in,
                              void* d_out, int out_size)
{
    const float* query  = (const float*)d_in[0];
    const float* memory = (const float*)d_in[1];
    const float* bias   = (const float*)d_in[2];
    const float* W[4]   = {(const float*)d_in[3], (const float*)d_in[4],
                           (const float*)d_in[5], (const float*)d_in[6]};
    float* out = (float*)d_out;

    float *vb;
    __nv_bfloat16 *mh, *ml, *qh, *ql, *ah, *al, *wh, *wl;
    __nv_bfloat16 *pqh, *pql, *pkh, *pkl, *vth, *vtl;
    cudaGetSymbolAddress((void**)&vb, g_v);
    cudaGetSymbolAddress((void**)&mh, g_mh);
    cudaGetSymbolAddress((void**)&ml, g_ml);
    cudaGetSymbolAddress((void**)&qh, g_qh);
    cudaGetSymbolAddress((void**)&ql, g_ql);
    cudaGetSymbolAddress((void**)&ah, g_ah);
    cudaGetSymbolAddress((void**)&al, g_al);
    cudaGetSymbolAddress((void**)&wh, g_wh);
    cudaGetSymbolAddress((void**)&wl, g_wl);
    cudaGetSymbolAddress((void**)&pqh, g_pqh);
    cudaGetSymbolAddress((void**)&pql, g_pql);
    cudaGetSymbolAddress((void**)&pkh, g_pkh);
    cudaGetSymbolAddress((void**)&pkl, g_pkl);
    cudaGetSymbolAddress((void**)&vth, g_vth);
    cudaGetSymbolAddress((void**)&vtl, g_vtl);

    cudaFuncSetAttribute(gemm_mma, cudaFuncAttributeMaxDynamicSharedMemorySize, GEMM_SMEM);
    cudaFuncSetAttribute(attn_mma, cudaFuncAttributeMaxDynamicSharedMemorySize, ATTN_SMEM);

    const int n_q  = BATCH * QLEN  * DMODEL;
    const int n_kv = BATCH * KVLEN * DMODEL;
    const int WSZ  = DMODEL * DMODEL;
    dim3 t32(32, 8), gT(DMODEL / 32, DMODEL / 32);

    // input splits
    k_split<<<2048, 256>>>(query,  qh, ql, n_q);
    k_split<<<4096, 256>>>(memory, mh, ml, n_kv);
    for (int w = 0; w < 4; w++)
        k_tsplit<<<gT, t32>>>(W[w], wh + (size_t)w * WSZ, wl + (size_t)w * WSZ);

    // projections (Q/K write split directly; V needs fp32 for transpose)
    gemm_mma<<<dim3(DMODEL/128, (BATCH*QLEN)/128),  256, GEMM_SMEM>>>(qh, ql, wh + 0*(size_t)WSZ, wl + 0*(size_t)WSZ, nullptr, pqh, pql, DMODEL);
    gemm_mma<<<dim3(DMODEL/128, (BATCH*KVLEN)/128), 256, GEMM_SMEM>>>(mh, ml, wh + 1*(size_t)WSZ, wl + 1*(size_t)WSZ, nullptr, pkh, pkl, DMODEL);
    gemm_mma<<<dim3(DMODEL/128, (BATCH*KVLEN)/128), 256, GEMM_SMEM>>>(mh, ml, wh + 2*(size_t)WSZ, wl + 2*(size_t)WSZ, vb, nullptr, nullptr, DMODEL);
    k_vtsplit<<<dim3(KVLEN/32, DMODEL/32, BATCH), t32>>>(vb, vth, vtl);

    // attention (writes split output)
    attn_mma<<<dim3(QLEN/128, NHEAD, BATCH), 256, ATTN_SMEM>>>(pqh, pql, pkh, pkl, vth, vtl, bias, ah, al);

    // output projection
    gemm_mma<<<dim3(DMODEL/128, (BATCH*QLEN)/128),  256, GEMM_SMEM>>>(ah, al, wh + 3*(size_t)WSZ, wl + 3*(size_t)WSZ, out, nullptr, nullptr, DMODEL);
}

// round 9
// speedup vs baseline: 3.8732x; 1.4002x over previous
#include <cuda_runtime.h>
#include <cuda_fp16.h>
#include <cstdint>
#include <math.h>

#define BATCH   4
#define QLEN    512
#define KVLEN   4096
#define DMODEL  1024
#define NHEAD   16
#define DH      64
#define GK      1024

// ---------------- scratch (allocation-free rule) ----------------
__device__ float g_v[BATCH * KVLEN * DMODEL];            // V projection (fp32)
__device__ __half g_mh [BATCH * KVLEN * DMODEL];         // memory fp16 (A-side, hi only)
__device__ __half g_qh [BATCH * QLEN  * DMODEL];         // query fp16
__device__ __half g_ah [BATCH * QLEN  * DMODEL];         // attention out fp16 (hi only)
__device__ __half g_wh [4][DMODEL * DMODEL];             // W^T hi
__device__ __half g_wl [4][DMODEL * DMODEL];             // W^T lo
__device__ __half g_pqh[BATCH * QLEN  * DMODEL];         // Q proj hi
__device__ __half g_pkh[BATCH * KVLEN * DMODEL];         // K proj hi
__device__ __half g_pkl[BATCH * KVLEN * DMODEL];         // K proj lo
__device__ __half g_vth[BATCH * DMODEL * KVLEN];         // V^T hi  [b, d, kv]
__device__ __half g_vtl[BATCH * DMODEL * KVLEN];         // V^T lo

#define CP_ASYNC16(d, s) asm volatile("cp.async.cg.shared.global [%0], [%1], 16;" :: "r"(d), "l"(s))
#define LDSM_X4(r, a) \
    asm volatile("ldmatrix.sync.aligned.m8n8.x4.shared.b16 {%0,%1,%2,%3}, [%4];" \
        : "=r"((r)[0]), "=r"((r)[1]), "=r"((r)[2]), "=r"((r)[3]) : "r"(a))

__device__ __forceinline__ void mma_f16(float* c, const uint32_t* a, const uint32_t* b) {
    asm volatile(
        "mma.sync.aligned.m16n8k16.row.col.f32.f16.f16.f32 "
        "{%0,%1,%2,%3}, {%4,%5,%6,%7}, {%8,%9}, {%0,%1,%2,%3};"
        : "+f"(c[0]), "+f"(c[1]), "+f"(c[2]), "+f"(c[3])
        : "r"(a[0]), "r"(a[1]), "r"(a[2]), "r"(a[3]), "r"(b[0]), "r"(b[1]));
}
__device__ __forceinline__ void split2h(float v0, float v1, uint32_t& h, uint32_t& l) {
    __half2 hh = __floats2half2_rn(v0, v1);
    __half2 ll = __floats2half2_rn(v0 - __half2float(__low2half(hh)),
                                   v1 - __half2float(__high2half(hh)));
    h = *(uint32_t*)&hh;  l = *(uint32_t*)&ll;
}

// cast fp32 -> fp16 (hi only)
__global__ void k_cast(const float* __restrict__ x, __half* __restrict__ hi, int n)
{
    for (int i = blockIdx.x * blockDim.x + threadIdx.x; i < n; i += gridDim.x * blockDim.x)
        hi[i] = __float2half_rn(x[i]);
}
// transpose + split W[k][n] -> Th[n][k], Tl[n][k] (fp16)
__global__ void k_tsplit(const float* __restrict__ W, __half* __restrict__ Th,
                         __half* __restrict__ Tl)
{
    __shared__ float t[32][33];
    int k0 = blockIdx.y * 32, n0 = blockIdx.x * 32;
    int tx = threadIdx.x, ty = threadIdx.y;
#pragma unroll
    for (int i = 0; i < 4; i++)
        t[ty + 8 * i][tx] = W[(size_t)(k0 + ty + 8 * i) * DMODEL + n0 + tx];
    __syncthreads();
#pragma unroll
    for (int i = 0; i < 4; i++) {
        float v = t[tx][ty + 8 * i];
        __half h = __float2half_rn(v);
        size_t o = (size_t)(n0 + ty + 8 * i) * DMODEL + k0 + tx;
        Th[o] = h;
        Tl[o] = __float2half_rn(v - __half2float(h));
    }
}
// transpose + split V[b][kv][d] -> Vt[b][d][kv] (fp16)
__global__ void k_vtsplit(const float* __restrict__ V, __half* __restrict__ Th,
                          __half* __restrict__ Tl)
{
    __shared__ float t[32][33];
    int kv0 = blockIdx.x * 32, d0 = blockIdx.y * 32, b = blockIdx.z;
    int tx = threadIdx.x, ty = threadIdx.y;
    const float* src = V + (size_t)b * KVLEN * DMODEL;
#pragma unroll
    for (int i = 0; i < 4; i++)
        t[ty + 8 * i][tx] = src[(size_t)(kv0 + ty + 8 * i) * DMODEL + d0 + tx];
    __syncthreads();
#pragma unroll
    for (int i = 0; i < 4; i++) {
        int d = d0 + ty + 8 * i, kv = kv0 + tx;
        float v = t[tx][ty + 8 * i];
        __half h = __float2half_rn(v);
        size_t o = ((size_t)b * DMODEL + d) * KVLEN + kv;
        Th[o] = h;
        Tl[o] = __float2half_rn(v - __half2float(h));
    }
}

// ---------------------------------------------------------------------------
// fp16 2-MMA GEMM: C = A[M,K] @ (B[N,K])^T,  D = Ah·Bh + Ah·Bl.
// CTA 128x128, BK=64, 3 smem arrays (A, Bh, Bl), stride 36 words, 2-stage.
// ---------------------------------------------------------------------------
#define SKW   36
#define ARR_W (128 * SKW)          // 4608 words
#define BUF_W (3 * ARR_W)          // 13824 words
#define GEMM_SMEM (2 * BUF_W * 4)  // 110592 bytes

__global__ __launch_bounds__(256, 2)
void gemm_mma(const __half* __restrict__ A, const __half* __restrict__ Bh,
              const __half* __restrict__ Bl, float* __restrict__ C,
              __half* __restrict__ Chi, __half* __restrict__ Clo, int N)
{
    extern __shared__ __align__(16) uint32_t sm32[];
    const int tid  = threadIdx.x;
    const int wid  = tid >> 5, lane = tid & 31;
    const int g    = lane >> 2, tg = lane & 3;
    const int r8   = lane & 7, sub = lane >> 3;
    const int wm64 = (wid & 1) * 64;
    const int wn32 = (wid >> 1) * 32;
    const int bn = blockIdx.x, bm = blockIdx.y;

    const size_t arow0 = (size_t)bm * 128 * GK;
    const size_t brow0 = (size_t)bn * 128 * GK;
    const uint32_t smem_b = (uint32_t)__cvta_generic_to_shared(sm32);

    const int a_row = wm64 + r8 + ((sub & 1) << 3);
    const int a_col = (sub >> 1) << 2;
    const int b_row = wn32 + r8;
    const int b_col = ((sub & 1) << 2);
    const int b_arr = ARR_W + (sub >> 1) * ARR_W;   // Bh / Bl

    float acc[4][4][4];
#pragma unroll
    for (int mt = 0; mt < 4; mt++)
#pragma unroll
        for (int nt = 0; nt < 4; nt++)
#pragma unroll
            for (int r = 0; r < 4; r++) acc[mt][nt][r] = 0.f;

    auto load_tile = [&](int kt, int buf) {
        const __half* srcs[3] = { A + arow0 + kt * 64, Bh + brow0 + kt * 64, Bl + brow0 + kt * 64 };
#pragma unroll
        for (int i = 0; i < 12; i++) {
            int chunk = tid + 256 * i;              // 0..3071
            int arr = chunk >> 10;
            int w   = chunk & 1023;
            int row = w >> 3, c = w & 7;
            uint32_t dst = smem_b + (buf * BUF_W + arr * ARR_W + row * SKW + c * 4) * 4;
            CP_ASYNC16(dst, srcs[arr] + (size_t)row * GK + c * 8);
        }
        asm volatile("cp.async.commit_group;");
    };

    load_tile(0, 0);

    const int NT = GK / 64;
    for (int kt = 0; kt < NT; kt++) {
        const int buf = kt & 1;
        if (kt + 1 < NT) {
            load_tile(kt + 1, 1 - buf);
            asm volatile("cp.async.wait_group 1;");
        } else {
            asm volatile("cp.async.wait_group 0;");
        }
        __syncthreads();

        const uint32_t bufw = buf * BUF_W;
#pragma unroll
        for (int ks = 0; ks < 4; ks++) {
            uint32_t bf[4][4];
#pragma unroll
            for (int nt = 0; nt < 4; nt++) {
                uint32_t addr = smem_b + (bufw + b_arr + (b_row + nt * 8) * SKW + ks * 8 + b_col) * 4;
                LDSM_X4(bf[nt], addr);
            }
#pragma unroll
            for (int mt = 0; mt < 4; mt++) {
                uint32_t ah[4];
                uint32_t aaddr = smem_b + (bufw + (a_row + mt * 16) * SKW + ks * 8 + a_col) * 4;
                LDSM_X4(ah, aaddr);
#pragma unroll
                for (int nt = 0; nt < 4; nt++) {
                    mma_f16(acc[mt][nt], ah, bf[nt]);       // A·Bh
                    mma_f16(acc[mt][nt], ah, bf[nt] + 2);   // A·Bl
                }
            }
        }
        __syncthreads();
    }

#pragma unroll
    for (int mt = 0; mt < 4; mt++) {
        int row0 = bm * 128 + wm64 + mt * 16 + g;
#pragma unroll
        for (int nt = 0; nt < 4; nt++) {
            int col = bn * 128 + wn32 + nt * 8 + tg * 2;
            if (C) {
                *(float2*)(C + (size_t)row0 * N + col)       = make_float2(acc[mt][nt][0], acc[mt][nt][1]);
                *(float2*)(C + (size_t)(row0 + 8) * N + col) = make_float2(acc[mt][nt][2], acc[mt][nt][3]);
            }
            if (Chi) {
                uint32_t h0, l0, h1, l1;
                split2h(acc[mt][nt][0], acc[mt][nt][1], h0, l0);
                split2h(acc[mt][nt][2], acc[mt][nt][3], h1, l1);
                *(uint32_t*)(Chi + (size_t)row0 * N + col)       = h0;
                *(uint32_t*)(Chi + (size_t)(row0 + 8) * N + col) = h1;
                if (Clo) {
                    *(uint32_t*)(Clo + (size_t)row0 * N + col)       = l0;
                    *(uint32_t*)(Clo + (size_t)(row0 + 8) * N + col) = l1;
                }
            }
        }
    }
}

// ---------------------------------------------------------------------------
// fp16 2-MMA attention. S = Qh·Kh + Qh·Kl ; O = Ph·Vh + Ph·Vl.
// CTA = (qtile 128, head, batch), 2 CTAs/SM -> one wave.
// ---------------------------------------------------------------------------
#define AST    36
#define AQ     0                   // Q hi: 128x36 = 4608 words
#define AKV    4608                // + buf*9216 ; [KH][KL][VH][VL] x 2304
#define AB_OFF 23040               // + buf*64
#define ATTN_SMEM ((23040 + 128) * 4)

__global__ __launch_bounds__(256, 2)
void attn_mma(const __half* __restrict__ Qh,
              const __half* __restrict__ Kh, const __half* __restrict__ Kl,
              const __half* __restrict__ Vh, const __half* __restrict__ Vl,
              const float* __restrict__ bias, __half* __restrict__ oh)
{
    extern __shared__ __align__(16) uint32_t sw[];
    const uint32_t sb = (uint32_t)__cvta_generic_to_shared(sw);
    const int tid = threadIdx.x, wid = tid >> 5, lane = tid & 31;
    const int g = lane >> 2, tg = lane & 3;
    const int r8 = lane & 7, sub = lane >> 3;
    const int qt = blockIdx.x, h = blockIdx.y, b = blockIdx.z;
    const int q0 = qt * 128;
    const int qrow = wid * 16;

    const int a_row = qrow + r8 + ((sub & 1) << 3);
    const int a_col = (sub >> 1) << 2;
    const int b_row = r8;
    const int b_col = ((sub & 1) << 2);
    const int b_arr = (sub >> 1) * 2304;

    // ---- Q load (once) ----
    {
        const __half* s0 = Qh + ((size_t)(b * QLEN + q0)) * DMODEL + h * DH;
#pragma unroll
        for (int i = 0; i < 4; i++) {
            int chunk = tid + 256 * i;          // 0..1023
            int r = chunk >> 3, c = chunk & 7;
            uint32_t dst = sb + (AQ + r * AST + c * 4) * 4;
            CP_ASYNC16(dst, s0 + (size_t)r * DMODEL + c * 8);
        }
        asm volatile("cp.async.commit_group;");
    }

    auto load_tile = [&](int kt, int buf) {
        const int k0 = kt * 64;
        const __half* kh = Kh + ((size_t)(b * KVLEN + k0)) * DMODEL + h * DH;
        const __half* kl = Kl + ((size_t)(b * KVLEN + k0)) * DMODEL + h * DH;
        const __half* vh = Vh + ((size_t)(b * DMODEL + h * DH)) * KVLEN + k0;
        const __half* vl = Vl + ((size_t)(b * DMODEL + h * DH)) * KVLEN + k0;
#pragma unroll
        for (int i = 0; i < 8; i++) {
            int chunk = tid + 256 * i;
            int arr = i >> 1;                   // compile-time 0..3
            int w = chunk & 511;
            int r = w >> 3, c = w & 7;
            const __half* src = (arr == 0) ? kh : (arr == 1) ? kl : (arr == 2) ? vh : vl;
            size_t rstride = (arr < 2) ? DMODEL : KVLEN;
            uint32_t dst = sb + (AKV + buf * 9216 + arr * 2304 + r * AST + c * 4) * 4;
            CP_ASYNC16(dst, src + (size_t)r * rstride + c * 8);
        }
        if (tid < 16) {
            uint32_t dst = sb + (AB_OFF + buf * 64 + tid * 4) * 4;
            CP_ASYNC16(dst, bias + (size_t)b * KVLEN + kt * 64 + tid * 4);
        }
        asm volatile("cp.async.commit_group;");
    };

    float oacc[8][4];
#pragma unroll
    for (int nt = 0; nt < 8; nt++)
#pragma unroll
        for (int r = 0; r < 4; r++) oacc[nt][r] = 0.f;
    float dsum0 = 0.f, dsum1 = 0.f;

    load_tile(0, 0);
    const int NT = KVLEN / 64;

    for (int kt = 0; kt < NT; kt++) {
        const int buf = kt & 1;
        if (kt + 1 < NT) {
            load_tile(kt + 1, 1 - buf);
            asm volatile("cp.async.wait_group 1;");
        } else {
            asm volatile("cp.async.wait_group 0;");
        }
        __syncthreads();

        // ---- S = Q·K^T ----
        float sacc[8][4];
#pragma unroll
        for (int nt = 0; nt < 8; nt++)
#pragma unroll
            for (int r = 0; r < 4; r++) sacc[nt][r] = 0.f;

        const uint32_t kbase = AKV + buf * 9216;
#pragma unroll
        for (int ks = 0; ks < 4; ks++) {
            uint32_t aH[4];
            LDSM_X4(aH, sb + (AQ + a_row * AST + ks * 8 + a_col) * 4);
#pragma unroll
            for (int nt = 0; nt < 8; nt++) {
                uint32_t bf[4];
                LDSM_X4(bf, sb + (kbase + b_arr + (b_row + nt * 8) * AST + ks * 8 + b_col) * 4);
                mma_f16(sacc[nt], aH, bf);
                mma_f16(sacc[nt], aH, bf + 2);
            }
        }

        // ---- P = exp(S*scale + bias) ----
        const float* bsm = (const float*)(sw + AB_OFF + buf * 64);
#pragma unroll
        for (int nt = 0; nt < 8; nt++) {
            float b0 = bsm[nt * 8 + tg * 2];
            float b1 = bsm[nt * 8 + tg * 2 + 1];
            float p0 = __expf(fmaf(sacc[nt][0], 0.125f, b0));
            float p1 = __expf(fmaf(sacc[nt][1], 0.125f, b1));
            float p2 = __expf(fmaf(sacc[nt][2], 0.125f, b0));
            float p3 = __expf(fmaf(sacc[nt][3], 0.125f, b1));
            sacc[nt][0] = p0; sacc[nt][1] = p1; sacc[nt][2] = p2; sacc[nt][3] = p3;
            dsum0 += p0 + p1;
            dsum1 += p2 + p3;
        }

        // ---- O += P·V ----
        const uint32_t vbase = AKV + buf * 9216 + 4608;
#pragma unroll
        for (int ks = 0; ks < 4; ks++) {
            const float* pa = sacc[2 * ks];
            const float* pb = sacc[2 * ks + 1];
            __half2 h0 = __floats2half2_rn(pa[0], pa[1]);
            __half2 h1 = __floats2half2_rn(pa[2], pa[3]);
            __half2 h2 = __floats2half2_rn(pb[0], pb[1]);
            __half2 h3 = __floats2half2_rn(pb[2], pb[3]);
            uint32_t aP[4] = { *(uint32_t*)&h0, *(uint32_t*)&h1, *(uint32_t*)&h2, *(uint32_t*)&h3 };
#pragma unroll
            for (int nt = 0; nt < 8; nt++) {
                uint32_t bf[4];
                LDSM_X4(bf, sb + (vbase + b_arr + (b_row + nt * 8) * AST + ks * 8 + b_col) * 4);
                mma_f16(oacc[nt], aP, bf);
                mma_f16(oacc[nt], aP, bf + 2);
            }
        }
        __syncthreads();
    }

    // ---- denominators (quad reduce) ----
    dsum0 += __shfl_xor_sync(0xFFFFFFFFu, dsum0, 1);
    dsum0 += __shfl_xor_sync(0xFFFFFFFFu, dsum0, 2);
    dsum1 += __shfl_xor_sync(0xFFFFFFFFu, dsum1, 1);
    dsum1 += __shfl_xor_sync(0xFFFFFFFFu, dsum1, 2);
    const float inv0 = 1.f / dsum0, inv1 = 1.f / dsum1;

    const int row = b * QLEN + q0 + qrow + g;
#pragma unroll
    for (int nt = 0; nt < 8; nt++) {
        const int col = h * DH + nt * 8 + tg * 2;
        __half2 o0 = __floats2half2_rn(oacc[nt][0] * inv0, oacc[nt][1] * inv0);
        __half2 o1 = __floats2half2_rn(oacc[nt][2] * inv1, oacc[nt][3] * inv1);
        *(uint32_t*)(oh + (size_t)row * DMODEL + col)       = *(uint32_t*)&o0;
        *(uint32_t*)(oh + (size_t)(row + 8) * DMODEL + col) = *(uint32_t*)&o1;
    }
}

// ---------------------------------------------------------------------------
extern "C" void kernel_launch(void* const* d_in, const int* in_sizes, int n_in,
                              void* d_out, int out_size)
{
    const float* query  = (const float*)d_in[0];
    const float* memory = (const float*)d_in[1];
    const float* bias   = (const float*)d_in[2];
    const float* W[4]   = {(const float*)d_in[3], (const float*)d_in[4],
                           (const float*)d_in[5], (const float*)d_in[6]};
    float* out = (float*)d_out;

    float *vb;
    __half *mh, *qh, *ah, *wh, *wl, *pqh, *pkh, *pkl, *vth, *vtl;
    cudaGetSymbolAddress((void**)&vb, g_v);
    cudaGetSymbolAddress((void**)&mh, g_mh);
    cudaGetSymbolAddress((void**)&qh, g_qh);
    cudaGetSymbolAddress((void**)&ah, g_ah);
    cudaGetSymbolAddress((void**)&wh, g_wh);
    cudaGetSymbolAddress((void**)&wl, g_wl);
    cudaGetSymbolAddress((void**)&pqh, g_pqh);
    cudaGetSymbolAddress((void**)&pkh, g_pkh);
    cudaGetSymbolAddress((void**)&pkl, g_pkl);
    cudaGetSymbolAddress((void**)&vth, g_vth);
    cudaGetSymbolAddress((void**)&vtl, g_vtl);

    cudaFuncSetAttribute(gemm_mma, cudaFuncAttributeMaxDynamicSharedMemorySize, GEMM_SMEM);
    cudaFuncSetAttribute(attn_mma, cudaFuncAttributeMaxDynamicSharedMemorySize, ATTN_SMEM);

    const int n_q  = BATCH * QLEN  * DMODEL;
    const int n_kv = BATCH * KVLEN * DMODEL;
    const int WSZ  = DMODEL * DMODEL;
    dim3 t32(32, 8), gT(DMODEL / 32, DMODEL / 32);

    // input casts / weight splits
    k_cast<<<1024, 256>>>(query,  qh, n_q);
    k_cast<<<4096, 256>>>(memory, mh, n_kv);
    for (int w = 0; w < 4; w++)
        k_tsplit<<<gT, t32>>>(W[w], wh + (size_t)w * WSZ, wl + (size_t)w * WSZ);

    // projections
    gemm_mma<<<dim3(DMODEL/128, (BATCH*QLEN)/128),  256, GEMM_SMEM>>>(qh, wh + 0*(size_t)WSZ, wl + 0*(size_t)WSZ, nullptr, pqh, nullptr, DMODEL);
    gemm_mma<<<dim3(DMODEL/128, (BATCH*KVLEN)/128), 256, GEMM_SMEM>>>(mh, wh + 1*(size_t)WSZ, wl + 1*(size_t)WSZ, nullptr, pkh, pkl, DMODEL);
    gemm_mma<<<dim3(DMODEL/128, (BATCH*KVLEN)/128), 256, GEMM_SMEM>>>(mh, wh + 2*(size_t)WSZ, wl + 2*(size_t)WSZ, vb, nullptr, nullptr, DMODEL);
    k_vtsplit<<<dim3(KVLEN/32, DMODEL/32, BATCH), t32>>>(vb, vth, vtl);

    // attention
    attn_mma<<<dim3(QLEN/128, NHEAD, BATCH), 256, ATTN_SMEM>>>(pqh, pkh, pkl, vth, vtl, bias, ah);

    // output projection
    gemm_mma<<<dim3(DMODEL/128, (BATCH*QLEN)/128),  256, GEMM_SMEM>>>(ah, wh + 3*(size_t)WSZ, wl + 3*(size_t)WSZ, out, nullptr, nullptr, DMODEL);
}

// round 10
// speedup vs baseline: 4.0786x; 1.0530x over previous
#include <cuda_runtime.h>
#include <cuda_fp16.h>
#include <cstdint>
#include <math.h>

#define BATCH   4
#define QLEN    512
#define KVLEN   4096
#define DMODEL  1024
#define NHEAD   16
#define DH      64
#define GK      1024
#define NKV     (BATCH * KVLEN)          // 16384

// ---------------- scratch (allocation-free rule) ----------------
__device__ __half g_mh [BATCH * KVLEN * DMODEL];   // memory hi
__device__ __half g_ml [BATCH * KVLEN * DMODEL];   // memory lo
__device__ __half g_qh [BATCH * QLEN  * DMODEL];   // query hi
__device__ __half g_ah [BATCH * QLEN  * DMODEL];   // attention out hi
__device__ __half g_wh [4][DMODEL * DMODEL];       // W^T hi
__device__ __half g_wl [4][DMODEL * DMODEL];       // W^T lo
__device__ __half g_pqh[BATCH * QLEN  * DMODEL];   // Q proj hi
__device__ __half g_pkh[BATCH * KVLEN * DMODEL];   // K proj hi
__device__ __half g_pkl[BATCH * KVLEN * DMODEL];   // K proj lo
__device__ __half g_vth[DMODEL * NKV];             // V^T hi  [d][b*kv]
__device__ __half g_vtl[DMODEL * NKV];             // V^T lo

#define CP_ASYNC16(d, s) asm volatile("cp.async.cg.shared.global [%0], [%1], 16;" :: "r"(d), "l"(s))
#define LDSM_X4(r, a) \
    asm volatile("ldmatrix.sync.aligned.m8n8.x4.shared.b16 {%0,%1,%2,%3}, [%4];" \
        : "=r"((r)[0]), "=r"((r)[1]), "=r"((r)[2]), "=r"((r)[3]) : "r"(a))

__device__ __forceinline__ void mma_f16(float* c, const uint32_t* a, const uint32_t* b) {
    asm volatile(
        "mma.sync.aligned.m16n8k16.row.col.f32.f16.f16.f32 "
        "{%0,%1,%2,%3}, {%4,%5,%6,%7}, {%8,%9}, {%0,%1,%2,%3};"
        : "+f"(c[0]), "+f"(c[1]), "+f"(c[2]), "+f"(c[3])
        : "r"(a[0]), "r"(a[1]), "r"(a[2]), "r"(a[3]), "r"(b[0]), "r"(b[1]));
}
__device__ __forceinline__ void split2h(float v0, float v1, uint32_t& h, uint32_t& l) {
    __half2 hh = __floats2half2_rn(v0, v1);
    __half2 ll = __floats2half2_rn(v0 - __half2float(__low2half(hh)),
                                   v1 - __half2float(__high2half(hh)));
    h = *(uint32_t*)&hh;  l = *(uint32_t*)&ll;
}

// ---------------- prep: query cast + memory split in one launch ----------------
__global__ void k_prep(const float* __restrict__ query, const float* __restrict__ memory)
{
    const int n_q  = BATCH * QLEN  * DMODEL;
    const int n_kv = BATCH * KVLEN * DMODEL;
    for (int i = blockIdx.x * blockDim.x + threadIdx.x; i < n_q + n_kv;
         i += gridDim.x * blockDim.x) {
        if (i < n_q) {
            g_qh[i] = __float2half_rn(query[i]);
        } else {
            int j = i - n_q;
            float v = memory[j];
            __half h = __float2half_rn(v);
            g_mh[j] = h;
            g_ml[j] = __float2half_rn(v - __half2float(h));
        }
    }
}
// transpose + split all 4 weights: W[k][n] -> WT hi/lo [n][k];  z = weight index
__global__ void k_tsplit4(const float* __restrict__ W0, const float* __restrict__ W1,
                          const float* __restrict__ W2, const float* __restrict__ W3)
{
    __shared__ float t[32][33];
    const float* Ws[4] = {W0, W1, W2, W3};
    int w = blockIdx.z;
    const float* W = Ws[w];
    __half* Th = g_wh[w];
    __half* Tl = g_wl[w];
    int k0 = blockIdx.y * 32, n0 = blockIdx.x * 32;
    int tx = threadIdx.x, ty = threadIdx.y;
#pragma unroll
    for (int i = 0; i < 4; i++)
        t[ty + 8 * i][tx] = W[(size_t)(k0 + ty + 8 * i) * DMODEL + n0 + tx];
    __syncthreads();
#pragma unroll
    for (int i = 0; i < 4; i++) {
        float v = t[tx][ty + 8 * i];
        __half h = __float2half_rn(v);
        size_t o = (size_t)(n0 + ty + 8 * i) * DMODEL + k0 + tx;
        Th[o] = h;
        Tl[o] = __float2half_rn(v - __half2float(h));
    }
}

// ---------------------------------------------------------------------------
// Shared fp16 2-MMA GEMM body: C = A[M,K=1024] @ (B[N,K])^T, D = A·Bh + A·Bl
// CTA 128x128, BK=64, 3 smem arrays, double-buffered, ldmatrix fragments.
// ---------------------------------------------------------------------------
#define SKW   36
#define ARR_W (128 * SKW)
#define BUF_W (3 * ARR_W)
#define GEMM_SMEM (2 * BUF_W * 4)

struct GemmAcc { float a[4][4][4]; };

__device__ __forceinline__ void gemm_body(
    uint32_t* sm32, const __half* A, const __half* Bh, const __half* Bl,
    int bm, int bn, GemmAcc& acc_)
{
    const int tid  = threadIdx.x;
    const int wid  = tid >> 5, lane = tid & 31;
    const int r8   = lane & 7, sub = lane >> 3;
    const int wm64 = (wid & 1) * 64;
    const int wn32 = (wid >> 1) * 32;

    const size_t arow0 = (size_t)bm * 128 * GK;
    const size_t brow0 = (size_t)bn * 128 * GK;
    const uint32_t smem_b = (uint32_t)__cvta_generic_to_shared(sm32);

    const int a_row = wm64 + r8 + ((sub & 1) << 3);
    const int a_col = (sub >> 1) << 2;
    const int b_row = wn32 + r8;
    const int b_col = ((sub & 1) << 2);
    const int b_arr = ARR_W + (sub >> 1) * ARR_W;

    float (*acc)[4][4] = acc_.a;
#pragma unroll
    for (int mt = 0; mt < 4; mt++)
#pragma unroll
        for (int nt = 0; nt < 4; nt++)
#pragma unroll
            for (int r = 0; r < 4; r++) acc[mt][nt][r] = 0.f;

    auto load_tile = [&](int kt, int buf) {
        const __half* srcs[3] = { A + arow0 + kt * 64, Bh + brow0 + kt * 64, Bl + brow0 + kt * 64 };
#pragma unroll
        for (int i = 0; i < 12; i++) {
            int chunk = tid + 256 * i;
            int arr = chunk >> 10;
            int w   = chunk & 1023;
            int row = w >> 3, c = w & 7;
            uint32_t dst = smem_b + ((buf * BUF_W + arr * ARR_W + row * SKW + c * 4) << 2);
            CP_ASYNC16(dst, srcs[arr] + (size_t)row * GK + c * 8);
        }
        asm volatile("cp.async.commit_group;");
    };

    load_tile(0, 0);

    const int NT = GK / 64;
    for (int kt = 0; kt < NT; kt++) {
        const int buf = kt & 1;
        if (kt + 1 < NT) {
            load_tile(kt + 1, 1 - buf);
            asm volatile("cp.async.wait_group 1;");
        } else {
            asm volatile("cp.async.wait_group 0;");
        }
        __syncthreads();

        const uint32_t bufw = buf * BUF_W;
#pragma unroll
        for (int ks = 0; ks < 4; ks++) {
            uint32_t bf[4][4];
#pragma unroll
            for (int nt = 0; nt < 4; nt++) {
                uint32_t addr = smem_b + ((bufw + b_arr + (b_row + nt * 8) * SKW + ks * 8 + b_col) << 2);
                LDSM_X4(bf[nt], addr);
            }
#pragma unroll
            for (int mt = 0; mt < 4; mt++) {
                uint32_t ah[4];
                uint32_t aaddr = smem_b + ((bufw + (a_row + mt * 16) * SKW + ks * 8 + a_col) << 2);
                LDSM_X4(ah, aaddr);
#pragma unroll
                for (int nt = 0; nt < 4; nt++) {
                    mma_f16(acc[mt][nt], ah, bf[nt]);
                    mma_f16(acc[mt][nt], ah, bf[nt] + 2);
                }
            }
        }
        __syncthreads();
    }
}

// Unified projection launch: Q proj | K proj | V proj (transposed) by block id.
__global__ __launch_bounds__(256, 2)
void k_proj()
{
    extern __shared__ __align__(16) uint32_t sm32[];
    const int id = blockIdx.x;

    const __half *A, *Bh, *Bl;
    __half *Chi, *Clo;
    int ldC, bm, bn;
    if (id < 128) {            // Q projection: [2048 x 1024] @ Wq
        A = g_qh; Bh = g_wh[0]; Bl = g_wl[0]; Chi = g_pqh; Clo = nullptr;
        ldC = DMODEL; bm = id >> 3; bn = id & 7;
    } else if (id < 1152) {    // K projection: [16384 x 1024] @ Wk
        int q = id - 128;
        A = g_mh; Bh = g_wh[1]; Bl = g_wl[1]; Chi = g_pkh; Clo = g_pkl;
        ldC = DMODEL; bm = q >> 3; bn = q & 7;
    } else {                   // V projection, swapped: Vt[d][b*kv] = WvT @ mem^T
        int q = id - 1152;
        A = g_wh[2]; Bh = g_mh; Bl = g_ml; Chi = g_vth; Clo = g_vtl;
        ldC = NKV; bm = q >> 7; bn = q & 127;
    }

    GemmAcc acc_;
    gemm_body(sm32, A, Bh, Bl, bm, bn, acc_);

    const int lane = threadIdx.x & 31, wid = threadIdx.x >> 5;
    const int g = lane >> 2, tg = lane & 3;
    const int wm64 = (wid & 1) * 64, wn32 = (wid >> 1) * 32;
#pragma unroll
    for (int mt = 0; mt < 4; mt++) {
        int row0 = bm * 128 + wm64 + mt * 16 + g;
#pragma unroll
        for (int nt = 0; nt < 4; nt++) {
            int col = bn * 128 + wn32 + nt * 8 + tg * 2;
            uint32_t h0, l0, h1, l1;
            split2h(acc_.a[mt][nt][0], acc_.a[mt][nt][1], h0, l0);
            split2h(acc_.a[mt][nt][2], acc_.a[mt][nt][3], h1, l1);
            *(uint32_t*)(Chi + (size_t)row0 * ldC + col)       = h0;
            *(uint32_t*)(Chi + (size_t)(row0 + 8) * ldC + col) = h1;
            if (Clo) {
                *(uint32_t*)(Clo + (size_t)row0 * ldC + col)       = l0;
                *(uint32_t*)(Clo + (size_t)(row0 + 8) * ldC + col) = l1;
            }
        }
    }
}

// Output projection: fp32 C
__global__ __launch_bounds__(256, 2)
void k_outproj(float* __restrict__ C)
{
    extern __shared__ __align__(16) uint32_t sm32[];
    const int bm = blockIdx.x >> 3, bn = blockIdx.x & 7;

    GemmAcc acc_;
    gemm_body(sm32, g_ah, g_wh[3], g_wl[3], bm, bn, acc_);

    const int lane = threadIdx.x & 31, wid = threadIdx.x >> 5;
    const int g = lane >> 2, tg = lane & 3;
    const int wm64 = (wid & 1) * 64, wn32 = (wid >> 1) * 32;
#pragma unroll
    for (int mt = 0; mt < 4; mt++) {
        int row0 = bm * 128 + wm64 + mt * 16 + g;
#pragma unroll
        for (int nt = 0; nt < 4; nt++) {
            int col = bn * 128 + wn32 + nt * 8 + tg * 2;
            *(float2*)(C + (size_t)row0 * DMODEL + col)       = make_float2(acc_.a[mt][nt][0], acc_.a[mt][nt][1]);
            *(float2*)(C + (size_t)(row0 + 8) * DMODEL + col) = make_float2(acc_.a[mt][nt][2], acc_.a[mt][nt][3]);
        }
    }
}

// ---------------------------------------------------------------------------
// fp16 2-MMA attention (validated round 9); V now in [d][b*kv] layout.
// ---------------------------------------------------------------------------
#define AST    36
#define AQ     0
#define AKV    4608
#define AB_OFF 23040
#define ATTN_SMEM ((23040 + 128) * 4)

__global__ __launch_bounds__(256, 2)
void attn_mma(const float* __restrict__ bias)
{
    extern __shared__ __align__(16) uint32_t sw[];
    const uint32_t sb = (uint32_t)__cvta_generic_to_shared(sw);
    const int tid = threadIdx.x, wid = tid >> 5, lane = tid & 31;
    const int g = lane >> 2, tg = lane & 3;
    const int r8 = lane & 7, sub = lane >> 3;
    const int qt = blockIdx.x, h = blockIdx.y, b = blockIdx.z;
    const int q0 = qt * 128;
    const int qrow = wid * 16;

    const int a_row = qrow + r8 + ((sub & 1) << 3);
    const int a_col = (sub >> 1) << 2;
    const int b_row = r8;
    const int b_col = ((sub & 1) << 2);
    const int b_arr = (sub >> 1) * 2304;

    // ---- Q load (once) ----
    {
        const __half* s0 = g_pqh + ((size_t)(b * QLEN + q0)) * DMODEL + h * DH;
#pragma unroll
        for (int i = 0; i < 4; i++) {
            int chunk = tid + 256 * i;
            int r = chunk >> 3, c = chunk & 7;
            uint32_t dst = sb + ((AQ + r * AST + c * 4) << 2);
            CP_ASYNC16(dst, s0 + (size_t)r * DMODEL + c * 8);
        }
        asm volatile("cp.async.commit_group;");
    }

    auto load_tile = [&](int kt, int buf) {
        const int k0 = kt * 64;
        const __half* kh = g_pkh + ((size_t)(b * KVLEN + k0)) * DMODEL + h * DH;
        const __half* kl = g_pkl + ((size_t)(b * KVLEN + k0)) * DMODEL + h * DH;
        const __half* vh = g_vth + (size_t)(h * DH) * NKV + b * KVLEN + k0;
        const __half* vl = g_vtl + (size_t)(h * DH) * NKV + b * KVLEN + k0;
#pragma unroll
        for (int i = 0; i < 8; i++) {
            int chunk = tid + 256 * i;
            int arr = i >> 1;
            int w = chunk & 511;
            int r = w >> 3, c = w & 7;
            const __half* src = (arr == 0) ? kh : (arr == 1) ? kl : (arr == 2) ? vh : vl;
            size_t rstride = (arr < 2) ? DMODEL : NKV;
            uint32_t dst = sb + ((AKV + buf * 9216 + arr * 2304 + r * AST + c * 4) << 2);
            CP_ASYNC16(dst, src + (size_t)r * rstride + c * 8);
        }
        if (tid < 16) {
            uint32_t dst = sb + ((AB_OFF + buf * 64 + tid * 4) << 2);
            CP_ASYNC16(dst, bias + (size_t)b * KVLEN + kt * 64 + tid * 4);
        }
        asm volatile("cp.async.commit_group;");
    };

    float oacc[8][4];
#pragma unroll
    for (int nt = 0; nt < 8; nt++)
#pragma unroll
        for (int r = 0; r < 4; r++) oacc[nt][r] = 0.f;
    float dsum0 = 0.f, dsum1 = 0.f;

    load_tile(0, 0);
    const int NT = KVLEN / 64;

    for (int kt = 0; kt < NT; kt++) {
        const int buf = kt & 1;
        if (kt + 1 < NT) {
            load_tile(kt + 1, 1 - buf);
            asm volatile("cp.async.wait_group 1;");
        } else {
            asm volatile("cp.async.wait_group 0;");
        }
        __syncthreads();

        // ---- S = Q·K^T ----
        float sacc[8][4];
#pragma unroll
        for (int nt = 0; nt < 8; nt++)
#pragma unroll
            for (int r = 0; r < 4; r++) sacc[nt][r] = 0.f;

        const uint32_t kbase = AKV + buf * 9216;
#pragma unroll
        for (int ks = 0; ks < 4; ks++) {
            uint32_t aH[4];
            LDSM_X4(aH, sb + ((AQ + a_row * AST + ks * 8 + a_col) << 2));
#pragma unroll
            for (int nt = 0; nt < 8; nt++) {
                uint32_t bf[4];
                LDSM_X4(bf, sb + ((kbase + b_arr + (b_row + nt * 8) * AST + ks * 8 + b_col) << 2));
                mma_f16(sacc[nt], aH, bf);
                mma_f16(sacc[nt], aH, bf + 2);
            }
        }

        // ---- P = exp(S*scale + bias) ----
        const float* bsm = (const float*)(sw + AB_OFF + buf * 64);
#pragma unroll
        for (int nt = 0; nt < 8; nt++) {
            float b0 = bsm[nt * 8 + tg * 2];
            float b1 = bsm[nt * 8 + tg * 2 + 1];
            float p0 = __expf(fmaf(sacc[nt][0], 0.125f, b0));
            float p1 = __expf(fmaf(sacc[nt][1], 0.125f, b1));
            float p2 = __expf(fmaf(sacc[nt][2], 0.125f, b0));
            float p3 = __expf(fmaf(sacc[nt][3], 0.125f, b1));
            sacc[nt][0] = p0; sacc[nt][1] = p1; sacc[nt][2] = p2; sacc[nt][3] = p3;
            dsum0 += p0 + p1;
            dsum1 += p2 + p3;
        }

        // ---- O += P·V ----
        const uint32_t vbase = AKV + buf * 9216 + 4608;
#pragma unroll
        for (int ks = 0; ks < 4; ks++) {
            const float* pa = sacc[2 * ks];
            const float* pb = sacc[2 * ks + 1];
            __half2 h0 = __floats2half2_rn(pa[0], pa[1]);
            __half2 h1 = __floats2half2_rn(pa[2], pa[3]);
            __half2 h2 = __floats2half2_rn(pb[0], pb[1]);
            __half2 h3 = __floats2half2_rn(pb[2], pb[3]);
            uint32_t aP[4] = { *(uint32_t*)&h0, *(uint32_t*)&h1, *(uint32_t*)&h2, *(uint32_t*)&h3 };
#pragma unroll
            for (int nt = 0; nt < 8; nt++) {
                uint32_t bf[4];
                LDSM_X4(bf, sb + ((vbase + b_arr + (b_row + nt * 8) * AST + ks * 8 + b_col) << 2));
                mma_f16(oacc[nt], aP, bf);
                mma_f16(oacc[nt], aP, bf + 2);
            }
        }
        __syncthreads();
    }

    // ---- denominators (quad reduce) ----
    dsum0 += __shfl_xor_sync(0xFFFFFFFFu, dsum0, 1);
    dsum0 += __shfl_xor_sync(0xFFFFFFFFu, dsum0, 2);
    dsum1 += __shfl_xor_sync(0xFFFFFFFFu, dsum1, 1);
    dsum1 += __shfl_xor_sync(0xFFFFFFFFu, dsum1, 2);
    const float inv0 = 1.f / dsum0, inv1 = 1.f / dsum1;

    const int row = b * QLEN + q0 + qrow + g;
#pragma unroll
    for (int nt = 0; nt < 8; nt++) {
        const int col = h * DH + nt * 8 + tg * 2;
        __half2 o0 = __floats2half2_rn(oacc[nt][0] * inv0, oacc[nt][1] * inv0);
        __half2 o1 = __floats2half2_rn(oacc[nt][2] * inv1, oacc[nt][3] * inv1);
        *(uint32_t*)(g_ah + (size_t)row * DMODEL + col)       = *(uint32_t*)&o0;
        *(uint32_t*)(g_ah + (size_t)(row + 8) * DMODEL + col) = *(uint32_t*)&o1;
    }
}

// ---------------------------------------------------------------------------
extern "C" void kernel_launch(void* const* d_in, const int* in_sizes, int n_in,
                              void* d_out, int out_size)
{
    const float* query  = (const float*)d_in[0];
    const float* memory = (const float*)d_in[1];
    const float* bias   = (const float*)d_in[2];
    const float* Wq     = (const float*)d_in[3];
    const float* Wk     = (const float*)d_in[4];
    const float* Wv     = (const float*)d_in[5];
    const float* Wo     = (const float*)d_in[6];
    float* out = (float*)d_out;

    cudaFuncSetAttribute(k_proj,    cudaFuncAttributeMaxDynamicSharedMemorySize, GEMM_SMEM);
    cudaFuncSetAttribute(k_outproj, cudaFuncAttributeMaxDynamicSharedMemorySize, GEMM_SMEM);
    cudaFuncSetAttribute(attn_mma,  cudaFuncAttributeMaxDynamicSharedMemorySize, ATTN_SMEM);

    // preps: 2 launches
    k_prep<<<4096, 256>>>(query, memory);
    k_tsplit4<<<dim3(DMODEL / 32, DMODEL / 32, 4), dim3(32, 8)>>>(Wq, Wk, Wv, Wo);

    // all three projections in one launch (Q:128 | K:1024 | V-transposed:1024)
    k_proj<<<2176, 256, GEMM_SMEM>>>();

    // attention
    attn_mma<<<dim3(QLEN / 128, NHEAD, BATCH), 256, ATTN_SMEM>>>(bias);

    // output projection
    k_outproj<<<128, 256, GEMM_SMEM>>>(out);
}

// round 12
// speedup vs baseline: 4.2212x; 1.0350x over previous
#include <cuda_runtime.h>
#include <cuda_fp16.h>
#include <cstdint>
#include <math.h>

#define BATCH   4
#define QLEN    512
#define KVLEN   4096
#define DMODEL  1024
#define NHEAD   16
#define DH      64
#define GK      1024
#define NKV     (BATCH * KVLEN)

// ---------------- scratch (allocation-free rule) ----------------
__device__ __half g_mh [BATCH * KVLEN * DMODEL];
__device__ __half g_ml [BATCH * KVLEN * DMODEL];
__device__ __half g_qh [BATCH * QLEN  * DMODEL];
__device__ __half g_ah [BATCH * QLEN  * DMODEL];
__device__ __half g_wh [4][DMODEL * DMODEL];
__device__ __half g_wl [4][DMODEL * DMODEL];
__device__ __half g_pqh[BATCH * QLEN  * DMODEL];
__device__ __half g_pkh[BATCH * KVLEN * DMODEL];
__device__ __half g_pkl[BATCH * KVLEN * DMODEL];
__device__ __half g_vth[DMODEL * NKV];
__device__ __half g_vtl[DMODEL * NKV];

#define CP_ASYNC16(d, s) asm volatile("cp.async.cg.shared.global [%0], [%1], 16;" :: "r"(d), "l"(s))
#define LDSM_X4(r, a) \
    asm volatile("ldmatrix.sync.aligned.m8n8.x4.shared.b16 {%0,%1,%2,%3}, [%4];" \
        : "=r"((r)[0]), "=r"((r)[1]), "=r"((r)[2]), "=r"((r)[3]) : "r"(a))

__device__ __forceinline__ void mma_f16(float* c, const uint32_t* a, const uint32_t* b) {
    asm volatile(
        "mma.sync.aligned.m16n8k16.row.col.f32.f16.f16.f32 "
        "{%0,%1,%2,%3}, {%4,%5,%6,%7}, {%8,%9}, {%0,%1,%2,%3};"
        : "+f"(c[0]), "+f"(c[1]), "+f"(c[2]), "+f"(c[3])
        : "r"(a[0]), "r"(a[1]), "r"(a[2]), "r"(a[3]), "r"(b[0]), "r"(b[1]));
}
__device__ __forceinline__ void split2h(float v0, float v1, uint32_t& h, uint32_t& l) {
    __half2 hh = __floats2half2_rn(v0, v1);
    __half2 ll = __floats2half2_rn(v0 - __half2float(__low2half(hh)),
                                   v1 - __half2float(__high2half(hh)));
    h = *(uint32_t*)&hh;  l = *(uint32_t*)&ll;
}

// ---------------- preps ----------------
__global__ void k_prep(const float* __restrict__ query, const float* __restrict__ memory)
{
    const int n_q  = BATCH * QLEN  * DMODEL;
    const int n_kv = BATCH * KVLEN * DMODEL;
    for (int i = blockIdx.x * blockDim.x + threadIdx.x; i < n_q + n_kv;
         i += gridDim.x * blockDim.x) {
        if (i < n_q) {
            g_qh[i] = __float2half_rn(query[i]);
        } else {
            int j = i - n_q;
            float v = memory[j];
            __half h = __float2half_rn(v);
            g_mh[j] = h;
            g_ml[j] = __float2half_rn(v - __half2float(h));
        }
    }
}
__global__ void k_tsplit4(const float* __restrict__ W0, const float* __restrict__ W1,
                          const float* __restrict__ W2, const float* __restrict__ W3)
{
    __shared__ float t[32][33];
    const float* Ws[4] = {W0, W1, W2, W3};
    int w = blockIdx.z;
    const float* W = Ws[w];
    __half* Th = g_wh[w];
    __half* Tl = g_wl[w];
    int k0 = blockIdx.y * 32, n0 = blockIdx.x * 32;
    int tx = threadIdx.x, ty = threadIdx.y;
#pragma unroll
    for (int i = 0; i < 4; i++)
        t[ty + 8 * i][tx] = W[(size_t)(k0 + ty + 8 * i) * DMODEL + n0 + tx];
    __syncthreads();
#pragma unroll
    for (int i = 0; i < 4; i++) {
        float v = t[tx][ty + 8 * i];
        __half h = __float2half_rn(v);
        size_t o = (size_t)(n0 + ty + 8 * i) * DMODEL + k0 + tx;
        Th[o] = h;
        Tl[o] = __float2half_rn(v - __half2float(h));
    }
}

// ---------------------------------------------------------------------------
// fp16 2-MMA GEMM body: 2-stage, ONE barrier per k-tile.
// ---------------------------------------------------------------------------
#define SKW   36
#define ARR_W (128 * SKW)
#define BUF_W (3 * ARR_W)
#define GEMM_SMEM (2 * BUF_W * 4)

struct GemmAcc { float a[4][4][4]; };

__device__ __forceinline__ void gemm_body(
    uint32_t* sm32, const __half* A, const __half* Bh, const __half* Bl,
    int bm, int bn, GemmAcc& acc_)
{
    const int tid  = threadIdx.x;
    const int wid  = tid >> 5, lane = tid & 31;
    const int r8   = lane & 7, sub = lane >> 3;
    const int wm64 = (wid & 1) * 64;
    const int wn32 = (wid >> 1) * 32;

    const size_t arow0 = (size_t)bm * 128 * GK;
    const size_t brow0 = (size_t)bn * 128 * GK;
    const uint32_t smem_b = (uint32_t)__cvta_generic_to_shared(sm32);

    const int a_row = wm64 + r8 + ((sub & 1) << 3);
    const int a_col = (sub >> 1) << 2;
    const int b_row = wn32 + r8;
    const int b_col = ((sub & 1) << 2);
    const int b_arr = ARR_W + (sub >> 1) * ARR_W;

    float (*acc)[4][4] = acc_.a;
#pragma unroll
    for (int mt = 0; mt < 4; mt++)
#pragma unroll
        for (int nt = 0; nt < 4; nt++)
#pragma unroll
            for (int r = 0; r < 4; r++) acc[mt][nt][r] = 0.f;

    auto load_tile = [&](int kt, int buf) {
        const __half* srcs[3] = { A + arow0 + kt * 64, Bh + brow0 + kt * 64, Bl + brow0 + kt * 64 };
#pragma unroll
        for (int i = 0; i < 12; i++) {
            int chunk = tid + 256 * i;
            int arr = chunk >> 10;
            int w   = chunk & 1023;
            int row = w >> 3, c = w & 7;
            uint32_t dst = smem_b + ((buf * BUF_W + arr * ARR_W + row * SKW + c * 4) << 2);
            CP_ASYNC16(dst, srcs[arr] + (size_t)row * GK + c * 8);
        }
        asm volatile("cp.async.commit_group;");
    };

    load_tile(0, 0);

    const int NT = GK / 64;
    for (int kt = 0; kt < NT; kt++) {
        const int buf = kt & 1;
        asm volatile("cp.async.wait_group 0;");
        __syncthreads();                      // tile kt visible; buffer 1-buf drained
        if (kt + 1 < NT) load_tile(kt + 1, 1 - buf);

        const uint32_t bufw = buf * BUF_W;
#pragma unroll
        for (int ks = 0; ks < 4; ks++) {
            uint32_t bf[4][4];
#pragma unroll
            for (int nt = 0; nt < 4; nt++) {
                uint32_t addr = smem_b + ((bufw + b_arr + (b_row + nt * 8) * SKW + ks * 8 + b_col) << 2);
                LDSM_X4(bf[nt], addr);
            }
#pragma unroll
            for (int mt = 0; mt < 4; mt++) {
                uint32_t ah[4];
                uint32_t aaddr = smem_b + ((bufw + (a_row + mt * 16) * SKW + ks * 8 + a_col) << 2);
                LDSM_X4(ah, aaddr);
#pragma unroll
                for (int nt = 0; nt < 4; nt++) {
                    mma_f16(acc[mt][nt], ah, bf[nt]);
                    mma_f16(acc[mt][nt], ah, bf[nt] + 2);
                }
            }
        }
    }
}

__global__ __launch_bounds__(256, 2)
void k_proj()
{
    extern __shared__ __align__(16) uint32_t sm32[];
    const int id = blockIdx.x;

    const __half *A, *Bh, *Bl;
    __half *Chi, *Clo;
    int ldC, bm, bn;
    if (id < 128) {
        A = g_qh; Bh = g_wh[0]; Bl = g_wl[0]; Chi = g_pqh; Clo = nullptr;
        ldC = DMODEL; bm = id >> 3; bn = id & 7;
    } else if (id < 1152) {
        int q = id - 128;
        A = g_mh; Bh = g_wh[1]; Bl = g_wl[1]; Chi = g_pkh; Clo = g_pkl;
        ldC = DMODEL; bm = q >> 3; bn = q & 7;
    } else {
        int q = id - 1152;
        A = g_wh[2]; Bh = g_mh; Bl = g_ml; Chi = g_vth; Clo = g_vtl;
        ldC = NKV; bm = q >> 7; bn = q & 127;
    }

    GemmAcc acc_;
    gemm_body(sm32, A, Bh, Bl, bm, bn, acc_);

    const int lane = threadIdx.x & 31, wid = threadIdx.x >> 5;
    const int g = lane >> 2, tg = lane & 3;
    const int wm64 = (wid & 1) * 64, wn32 = (wid >> 1) * 32;
#pragma unroll
    for (int mt = 0; mt < 4; mt++) {
        int row0 = bm * 128 + wm64 + mt * 16 + g;
#pragma unroll
        for (int nt = 0; nt < 4; nt++) {
            int col = bn * 128 + wn32 + nt * 8 + tg * 2;
            uint32_t h0, l0, h1, l1;
            split2h(acc_.a[mt][nt][0], acc_.a[mt][nt][1], h0, l0);
            split2h(acc_.a[mt][nt][2], acc_.a[mt][nt][3], h1, l1);
            *(uint32_t*)(Chi + (size_t)row0 * ldC + col)       = h0;
            *(uint32_t*)(Chi + (size_t)(row0 + 8) * ldC + col) = h1;
            if (Clo) {
                *(uint32_t*)(Clo + (size_t)row0 * ldC + col)       = l0;
                *(uint32_t*)(Clo + (size_t)(row0 + 8) * ldC + col) = l1;
            }
        }
    }
}

__global__ __launch_bounds__(256, 2)
void k_outproj(float* __restrict__ C)
{
    extern __shared__ __align__(16) uint32_t sm32[];
    const int bm = blockIdx.x >> 3, bn = blockIdx.x & 7;

    GemmAcc acc_;
    gemm_body(sm32, g_ah, g_wh[3], g_wl[3], bm, bn, acc_);

    const int lane = threadIdx.x & 31, wid = threadIdx.x >> 5;
    const int g = lane >> 2, tg = lane & 3;
    const int wm64 = (wid & 1) * 64, wn32 = (wid >> 1) * 32;
#pragma unroll
    for (int mt = 0; mt < 4; mt++) {
        int row0 = bm * 128 + wm64 + mt * 16 + g;
#pragma unroll
        for (int nt = 0; nt < 4; nt++) {
            int col = bn * 128 + wn32 + nt * 8 + tg * 2;
            *(float2*)(C + (size_t)row0 * DMODEL + col)       = make_float2(acc_.a[mt][nt][0], acc_.a[mt][nt][1]);
            *(float2*)(C + (size_t)(row0 + 8) * DMODEL + col) = make_float2(acc_.a[mt][nt][2], acc_.a[mt][nt][3]);
        }
    }
}

// ---------------------------------------------------------------------------
// fp16 attention: 512-thread CTA, q-tile 256, 4-stage KV ring, 1 barrier/tile.
// ---------------------------------------------------------------------------
#define AST    36
#define AQ     0
#define AKV    (256 * AST)                  // 9216
#define SLOT_W (4 * 64 * AST)               // 9216 words per stage
#define AB     (AKV + 4 * SLOT_W)           // 46080
#define ATTN_SMEM ((AB + 256) * 4)          // 185344 bytes

__global__ __launch_bounds__(512, 1)
void attn_mma(const float* __restrict__ bias)
{
    extern __shared__ __align__(16) uint32_t sw[];
    const uint32_t sb = (uint32_t)__cvta_generic_to_shared(sw);
    const int tid = threadIdx.x, wid = tid >> 5, lane = tid & 31;
    const int g = lane >> 2, tg = lane & 3;
    const int r8 = lane & 7, sub = lane >> 3;
    const int qt = blockIdx.x, h = blockIdx.y, b = blockIdx.z;
    const int q0 = qt * 256;
    const int qrow = wid * 16;

    const int a_row = qrow + r8 + ((sub & 1) << 3);
    const int a_col = (sub >> 1) << 2;
    const int b_row = r8;
    const int b_col = ((sub & 1) << 2);
    const int b_arr = (sub >> 1) * 2304;

    // ---- Q load (group 0): 256 rows x 8 chunks ----
    {
        const __half* s0 = g_pqh + ((size_t)(b * QLEN + q0)) * DMODEL + h * DH;
#pragma unroll
        for (int i = 0; i < 4; i++) {
            int chunk = tid + 512 * i;
            int r = chunk >> 3, c = chunk & 7;
            uint32_t dst = sb + ((AQ + r * AST + c * 4) << 2);
            CP_ASYNC16(dst, s0 + (size_t)r * DMODEL + c * 8);
        }
        asm volatile("cp.async.commit_group;");
    }

    auto load_tile = [&](int kt, int slot) {
        const int k0 = kt * 64;
        const __half* srcs[4] = {
            g_pkh + ((size_t)(b * KVLEN + k0)) * DMODEL + h * DH,
            g_pkl + ((size_t)(b * KVLEN + k0)) * DMODEL + h * DH,
            g_vth + (size_t)(h * DH) * NKV + b * KVLEN + k0,
            g_vtl + (size_t)(h * DH) * NKV + b * KVLEN + k0 };
        const int r = tid >> 3, c = tid & 7;
#pragma unroll
        for (int arr = 0; arr < 4; arr++) {
            size_t rstride = (arr < 2) ? DMODEL : NKV;
            uint32_t dst = sb + ((AKV + slot * SLOT_W + arr * 2304 + r * AST + c * 4) << 2);
            CP_ASYNC16(dst, srcs[arr] + (size_t)r * rstride + c * 8);
        }
        if (tid < 16) {
            uint32_t dst = sb + ((AB + slot * 64 + tid * 4) << 2);
            CP_ASYNC16(dst, bias + (size_t)b * KVLEN + k0 + tid * 4);
        }
        asm volatile("cp.async.commit_group;");
    };

    float oacc[8][4];
#pragma unroll
    for (int nt = 0; nt < 8; nt++)
#pragma unroll
        for (int r = 0; r < 4; r++) oacc[nt][r] = 0.f;
    float dsum0 = 0.f, dsum1 = 0.f;

    const int NT = KVLEN / 64;       // 64 tiles
    load_tile(0, 0);
    load_tile(1, 1);
    load_tile(2, 2);

    for (int kt = 0; kt < NT; kt++) {
        const int slot = kt & 3;
        if (kt < NT - 2)       asm volatile("cp.async.wait_group 2;");
        else if (kt == NT - 2) asm volatile("cp.async.wait_group 1;");
        else                   asm volatile("cp.async.wait_group 0;");
        __syncthreads();                         // tile kt visible; slot (kt+3)&3 drained
        if (kt + 3 < NT) load_tile(kt + 3, (kt + 3) & 3);

        // ---- S = Q·K^T ----
        float sacc[8][4];
#pragma unroll
        for (int nt = 0; nt < 8; nt++)
#pragma unroll
            for (int r = 0; r < 4; r++) sacc[nt][r] = 0.f;

        const uint32_t kbase = AKV + slot * SLOT_W;
#pragma unroll
        for (int ks = 0; ks < 4; ks++) {
            uint32_t aH[4];
            LDSM_X4(aH, sb + ((AQ + a_row * AST + ks * 8 + a_col) << 2));
#pragma unroll
            for (int nt = 0; nt < 8; nt++) {
                uint32_t bf[4];
                LDSM_X4(bf, sb + ((kbase + b_arr + (b_row + nt * 8) * AST + ks * 8 + b_col) << 2));
                mma_f16(sacc[nt], aH, bf);
                mma_f16(sacc[nt], aH, bf + 2);
            }
        }

        // ---- P = exp(S*scale + bias) ----
        const float* bsm = (const float*)(sw + AB + slot * 64);
#pragma unroll
        for (int nt = 0; nt < 8; nt++) {
            float b0 = bsm[nt * 8 + tg * 2];
            float b1 = bsm[nt * 8 + tg * 2 + 1];
            float p0 = __expf(fmaf(sacc[nt][0], 0.125f, b0));
            float p1 = __expf(fmaf(sacc[nt][1], 0.125f, b1));
            float p2 = __expf(fmaf(sacc[nt][2], 0.125f, b0));
            float p3 = __expf(fmaf(sacc[nt][3], 0.125f, b1));
            sacc[nt][0] = p0; sacc[nt][1] = p1; sacc[nt][2] = p2; sacc[nt][3] = p3;
            dsum0 += p0 + p1;
            dsum1 += p2 + p3;
        }

        // ---- O += P·V ----
        const uint32_t vbase = kbase + 4608;
#pragma unroll
        for (int ks = 0; ks < 4; ks++) {
            const float* pa = sacc[2 * ks];
            const float* pb = sacc[2 * ks + 1];
            __half2 h0 = __floats2half2_rn(pa[0], pa[1]);
            __half2 h1 = __floats2half2_rn(pa[2], pa[3]);
            __half2 h2 = __floats2half2_rn(pb[0], pb[1]);
            __half2 h3 = __floats2half2_rn(pb[2], pb[3]);
            uint32_t aP[4] = { *(uint32_t*)&h0, *(uint32_t*)&h1, *(uint32_t*)&h2, *(uint32_t*)&h3 };
#pragma unroll
            for (int nt = 0; nt < 8; nt++) {
                uint32_t bf[4];
                LDSM_X4(bf, sb + ((vbase + b_arr + (b_row + nt * 8) * AST + ks * 8 + b_col) << 2));
                mma_f16(oacc[nt], aP, bf);
                mma_f16(oacc[nt], aP, bf + 2);
            }
        }
    }

    // ---- denominators (quad reduce) ----
    dsum0 += __shfl_xor_sync(0xFFFFFFFFu, dsum0, 1);
    dsum0 += __shfl_xor_sync(0xFFFFFFFFu, dsum0, 2);
    dsum1 += __shfl_xor_sync(0xFFFFFFFFu, dsum1, 1);
    dsum1 += __shfl_xor_sync(0xFFFFFFFFu, dsum1, 2);
    const float inv0 = 1.f / dsum0, inv1 = 1.f / dsum1;

    const int row = b * QLEN + q0 + qrow + g;
#pragma unroll
    for (int nt = 0; nt < 8; nt++) {
        const int col = h * DH + nt * 8 + tg * 2;
        __half2 o0 = __floats2half2_rn(oacc[nt][0] * inv0, oacc[nt][1] * inv0);
        __half2 o1 = __floats2half2_rn(oacc[nt][2] * inv1, oacc[nt][3] * inv1);
        *(uint32_t*)(g_ah + (size_t)row * DMODEL + col)       = *(uint32_t*)&o0;
        *(uint32_t*)(g_ah + (size_t)(row + 8) * DMODEL + col) = *(uint32_t*)&o1;
    }
}

// ---------------------------------------------------------------------------
extern "C" void kernel_launch(void* const* d_in, const int* in_sizes, int n_in,
                              void* d_out, int out_size)
{
    const float* query  = (const float*)d_in[0];
    const float* memory = (const float*)d_in[1];
    const float* bias   = (const float*)d_in[2];
    const float* Wq     = (const float*)d_in[3];
    const float* Wk     = (const float*)d_in[4];
    const float* Wv     = (const float*)d_in[5];
    const float* Wo     = (const float*)d_in[6];
    float* out = (float*)d_out;

    cudaFuncSetAttribute(k_proj,    cudaFuncAttributeMaxDynamicSharedMemorySize, GEMM_SMEM);
    cudaFuncSetAttribute(k_outproj, cudaFuncAttributeMaxDynamicSharedMemorySize, GEMM_SMEM);
    cudaFuncSetAttribute(attn_mma,  cudaFuncAttributeMaxDynamicSharedMemorySize, ATTN_SMEM);

    k_prep<<<4096, 256>>>(query, memory);
    k_tsplit4<<<dim3(DMODEL / 32, DMODEL / 32, 4), dim3(32, 8)>>>(Wq, Wk, Wv, Wo);

    k_proj<<<2176, 256, GEMM_SMEM>>>();

    attn_mma<<<dim3(QLEN / 256, NHEAD, BATCH), 512, ATTN_SMEM>>>(bias);

    k_outproj<<<128, 256, GEMM_SMEM>>>(out);
}

// round 13
// speedup vs baseline: 4.5289x; 1.0729x over previous
#include <cuda_runtime.h>
#include <cuda_fp16.h>
#include <cstdint>
#include <math.h>

#define BATCH   4
#define QLEN    512
#define KVLEN   4096
#define DMODEL  1024
#define NHEAD   16
#define DH      64
#define GK      1024
#define NKV     (BATCH * KVLEN)

// ---------------- scratch (allocation-free rule) ----------------
__device__ __half g_mh [BATCH * KVLEN * DMODEL];
__device__ __half g_ml [BATCH * KVLEN * DMODEL];
__device__ __half g_qh [BATCH * QLEN  * DMODEL];
__device__ __half g_ah [BATCH * QLEN  * DMODEL];
__device__ __half g_wh [4][DMODEL * DMODEL];
__device__ __half g_wl [4][DMODEL * DMODEL];
__device__ __half g_pqh[BATCH * QLEN  * DMODEL];
__device__ __half g_pkh[BATCH * KVLEN * DMODEL];
__device__ __half g_pkl[BATCH * KVLEN * DMODEL];
__device__ __half g_vth[DMODEL * NKV];

#define CP_ASYNC16(d, s) asm volatile("cp.async.cg.shared.global [%0], [%1], 16;" :: "r"(d), "l"(s))
#define LDSM_X4(r, a) \
    asm volatile("ldmatrix.sync.aligned.m8n8.x4.shared.b16 {%0,%1,%2,%3}, [%4];" \
        : "=r"((r)[0]), "=r"((r)[1]), "=r"((r)[2]), "=r"((r)[3]) : "r"(a))

__device__ __forceinline__ void mma_f16(float* c, const uint32_t* a, const uint32_t* b) {
    asm volatile(
        "mma.sync.aligned.m16n8k16.row.col.f32.f16.f16.f32 "
        "{%0,%1,%2,%3}, {%4,%5,%6,%7}, {%8,%9}, {%0,%1,%2,%3};"
        : "+f"(c[0]), "+f"(c[1]), "+f"(c[2]), "+f"(c[3])
        : "r"(a[0]), "r"(a[1]), "r"(a[2]), "r"(a[3]), "r"(b[0]), "r"(b[1]));
}
__device__ __forceinline__ void split2h(float v0, float v1, uint32_t& h, uint32_t& l) {
    __half2 hh = __floats2half2_rn(v0, v1);
    __half2 ll = __floats2half2_rn(v0 - __half2float(__low2half(hh)),
                                   v1 - __half2float(__high2half(hh)));
    h = *(uint32_t*)&hh;  l = *(uint32_t*)&ll;
}

// ---------------- preps ----------------
__global__ void k_prep(const float* __restrict__ query, const float* __restrict__ memory)
{
    const int n_q  = BATCH * QLEN  * DMODEL;
    const int n_kv = BATCH * KVLEN * DMODEL;
    for (int i = blockIdx.x * blockDim.x + threadIdx.x; i < n_q + n_kv;
         i += gridDim.x * blockDim.x) {
        if (i < n_q) {
            g_qh[i] = __float2half_rn(query[i]);
        } else {
            int j = i - n_q;
            float v = memory[j];
            __half h = __float2half_rn(v);
            g_mh[j] = h;
            g_ml[j] = __float2half_rn(v - __half2float(h));
        }
    }
}
__global__ void k_tsplit4(const float* __restrict__ W0, const float* __restrict__ W1,
                          const float* __restrict__ W2, const float* __restrict__ W3)
{
    __shared__ float t[32][33];
    const float* Ws[4] = {W0, W1, W2, W3};
    int w = blockIdx.z;
    const float* W = Ws[w];
    __half* Th = g_wh[w];
    __half* Tl = g_wl[w];
    int k0 = blockIdx.y * 32, n0 = blockIdx.x * 32;
    int tx = threadIdx.x, ty = threadIdx.y;
#pragma unroll
    for (int i = 0; i < 4; i++)
        t[ty + 8 * i][tx] = W[(size_t)(k0 + ty + 8 * i) * DMODEL + n0 + tx];
    __syncthreads();
#pragma unroll
    for (int i = 0; i < 4; i++) {
        float v = t[tx][ty + 8 * i];
        __half h = __float2half_rn(v);
        size_t o = (size_t)(n0 + ty + 8 * i) * DMODEL + k0 + tx;
        Th[o] = h;
        Tl[o] = __float2half_rn(v - __half2float(h));
    }
}

// ---------------------------------------------------------------------------
// fp16 2-MMA GEMM body: 2-stage, ONE barrier per k-tile.
// ---------------------------------------------------------------------------
#define SKW   36
#define ARR_W (128 * SKW)
#define BUF_W (3 * ARR_W)
#define GEMM_SMEM (2 * BUF_W * 4)

struct GemmAcc { float a[4][4][4]; };

__device__ __forceinline__ void gemm_body(
    uint32_t* sm32, const __half* A, const __half* Bh, const __half* Bl,
    int bm, int bn, GemmAcc& acc_)
{
    const int tid  = threadIdx.x;
    const int wid  = tid >> 5, lane = tid & 31;
    const int r8   = lane & 7, sub = lane >> 3;
    const int wm64 = (wid & 1) * 64;
    const int wn32 = (wid >> 1) * 32;

    const size_t arow0 = (size_t)bm * 128 * GK;
    const size_t brow0 = (size_t)bn * 128 * GK;
    const uint32_t smem_b = (uint32_t)__cvta_generic_to_shared(sm32);

    const int a_row = wm64 + r8 + ((sub & 1) << 3);
    const int a_col = (sub >> 1) << 2;
    const int b_row = wn32 + r8;
    const int b_col = ((sub & 1) << 2);
    const int b_arr = ARR_W + (sub >> 1) * ARR_W;

    float (*acc)[4][4] = acc_.a;
#pragma unroll
    for (int mt = 0; mt < 4; mt++)
#pragma unroll
        for (int nt = 0; nt < 4; nt++)
#pragma unroll
            for (int r = 0; r < 4; r++) acc[mt][nt][r] = 0.f;

    auto load_tile = [&](int kt, int buf) {
        const __half* srcs[3] = { A + arow0 + kt * 64, Bh + brow0 + kt * 64, Bl + brow0 + kt * 64 };
#pragma unroll
        for (int i = 0; i < 12; i++) {
            int chunk = tid + 256 * i;
            int arr = chunk >> 10;
            int w   = chunk & 1023;
            int row = w >> 3, c = w & 7;
            uint32_t dst = smem_b + ((buf * BUF_W + arr * ARR_W + row * SKW + c * 4) << 2);
            CP_ASYNC16(dst, srcs[arr] + (size_t)row * GK + c * 8);
        }
        asm volatile("cp.async.commit_group;");
    };

    load_tile(0, 0);

    const int NT = GK / 64;
    for (int kt = 0; kt < NT; kt++) {
        const int buf = kt & 1;
        asm volatile("cp.async.wait_group 0;");
        __syncthreads();
        if (kt + 1 < NT) load_tile(kt + 1, 1 - buf);

        const uint32_t bufw = buf * BUF_W;
#pragma unroll
        for (int ks = 0; ks < 4; ks++) {
            uint32_t bf[4][4];
#pragma unroll
            for (int nt = 0; nt < 4; nt++) {
                uint32_t addr = smem_b + ((bufw + b_arr + (b_row + nt * 8) * SKW + ks * 8 + b_col) << 2);
                LDSM_X4(bf[nt], addr);
            }
#pragma unroll
            for (int mt = 0; mt < 4; mt++) {
                uint32_t ah[4];
                uint32_t aaddr = smem_b + ((bufw + (a_row + mt * 16) * SKW + ks * 8 + a_col) << 2);
                LDSM_X4(ah, aaddr);
#pragma unroll
                for (int nt = 0; nt < 4; nt++) {
                    mma_f16(acc[mt][nt], ah, bf[nt]);
                    mma_f16(acc[mt][nt], ah, bf[nt] + 2);
                }
            }
        }
    }
}

__global__ __launch_bounds__(256, 2)
void k_proj()
{
    extern __shared__ __align__(16) uint32_t sm32[];
    const int id = blockIdx.x;

    const __half *A, *Bh, *Bl;
    __half *Chi, *Clo;
    int ldC, bm, bn;
    if (id < 128) {
        A = g_qh; Bh = g_wh[0]; Bl = g_wl[0]; Chi = g_pqh; Clo = nullptr;
        ldC = DMODEL; bm = id >> 3; bn = id & 7;
    } else if (id < 1152) {
        int q = id - 128;
        A = g_mh; Bh = g_wh[1]; Bl = g_wl[1]; Chi = g_pkh; Clo = g_pkl;
        ldC = DMODEL; bm = q >> 3; bn = q & 7;
    } else {
        int q = id - 1152;
        A = g_wh[2]; Bh = g_mh; Bl = g_ml; Chi = g_vth; Clo = nullptr;
        ldC = NKV; bm = q >> 7; bn = q & 127;
    }

    GemmAcc acc_;
    gemm_body(sm32, A, Bh, Bl, bm, bn, acc_);

    const int lane = threadIdx.x & 31, wid = threadIdx.x >> 5;
    const int g = lane >> 2, tg = lane & 3;
    const int wm64 = (wid & 1) * 64, wn32 = (wid >> 1) * 32;
#pragma unroll
    for (int mt = 0; mt < 4; mt++) {
        int row0 = bm * 128 + wm64 + mt * 16 + g;
#pragma unroll
        for (int nt = 0; nt < 4; nt++) {
            int col = bn * 128 + wn32 + nt * 8 + tg * 2;
            uint32_t h0, l0, h1, l1;
            split2h(acc_.a[mt][nt][0], acc_.a[mt][nt][1], h0, l0);
            split2h(acc_.a[mt][nt][2], acc_.a[mt][nt][3], h1, l1);
            *(uint32_t*)(Chi + (size_t)row0 * ldC + col)       = h0;
            *(uint32_t*)(Chi + (size_t)(row0 + 8) * ldC + col) = h1;
            if (Clo) {
                *(uint32_t*)(Clo + (size_t)row0 * ldC + col)       = l0;
                *(uint32_t*)(Clo + (size_t)(row0 + 8) * ldC + col) = l1;
            }
        }
    }
}

__global__ __launch_bounds__(256, 2)
void k_outproj(float* __restrict__ C)
{
    extern __shared__ __align__(16) uint32_t sm32[];
    const int bm = blockIdx.x >> 3, bn = blockIdx.x & 7;

    GemmAcc acc_;
    gemm_body(sm32, g_ah, g_wh[3], g_wl[3], bm, bn, acc_);

    const int lane = threadIdx.x & 31, wid = threadIdx.x >> 5;
    const int g = lane >> 2, tg = lane & 3;
    const int wm64 = (wid & 1) * 64, wn32 = (wid >> 1) * 32;
#pragma unroll
    for (int mt = 0; mt < 4; mt++) {
        int row0 = bm * 128 + wm64 + mt * 16 + g;
#pragma unroll
        for (int nt = 0; nt < 4; nt++) {
            int col = bn * 128 + wn32 + nt * 8 + tg * 2;
            *(float2*)(C + (size_t)row0 * DMODEL + col)       = make_float2(acc_.a[mt][nt][0], acc_.a[mt][nt][1]);
            *(float2*)(C + (size_t)(row0 + 8) * DMODEL + col) = make_float2(acc_.a[mt][nt][2], acc_.a[mt][nt][3]);
        }
    }
}

// ---------------------------------------------------------------------------
// fp16 attention: 512 threads, q-tile 256, 4-stage ring, V hi-only (1 MMA/nt).
// Slot layout: [KH 2304][KL 2304][VH 2304] words.
// ---------------------------------------------------------------------------
#define AST    36
#define AQ     0
#define AKV    (256 * AST)                  // 9216
#define SLOT_W (3 * 64 * AST)               // 6912 words per stage
#define AB     (AKV + 4 * SLOT_W)           // 36864
#define ATTN_SMEM ((AB + 256) * 4)          // 148480 bytes

__global__ __launch_bounds__(512, 1)
void attn_mma(const float* __restrict__ bias)
{
    extern __shared__ __align__(16) uint32_t sw[];
    const uint32_t sb = (uint32_t)__cvta_generic_to_shared(sw);
    const int tid = threadIdx.x, wid = tid >> 5, lane = tid & 31;
    const int g = lane >> 2, tg = lane & 3;
    const int r8 = lane & 7, sub = lane >> 3;
    const int qt = blockIdx.x, h = blockIdx.y, b = blockIdx.z;
    const int q0 = qt * 256;
    const int qrow = wid * 16;

    const int a_row = qrow + r8 + ((sub & 1) << 3);
    const int a_col = (sub >> 1) << 2;
    // K B-frag (hi+lo in one x4): lanes 0-15 -> KH, 16-31 -> KL
    const int kb_row = r8;
    const int kb_col = ((sub & 1) << 2);
    const int kb_arr = (sub >> 1) * 2304;
    // V B-frag (hi only, one x4 spans TWO n-tiles): sub>>1 picks nt half
    const int vb_row = ((sub >> 1) << 3) + r8;
    const int vb_col = ((sub & 1) << 2);

    // ---- Q load ----
    {
        const __half* s0 = g_pqh + ((size_t)(b * QLEN + q0)) * DMODEL + h * DH;
#pragma unroll
        for (int i = 0; i < 4; i++) {
            int chunk = tid + 512 * i;
            int r = chunk >> 3, c = chunk & 7;
            uint32_t dst = sb + ((AQ + r * AST + c * 4) << 2);
            CP_ASYNC16(dst, s0 + (size_t)r * DMODEL + c * 8);
        }
        asm volatile("cp.async.commit_group;");
    }

    auto load_tile = [&](int kt, int slot) {
        const int k0 = kt * 64;
        const __half* srcs[3] = {
            g_pkh + ((size_t)(b * KVLEN + k0)) * DMODEL + h * DH,
            g_pkl + ((size_t)(b * KVLEN + k0)) * DMODEL + h * DH,
            g_vth + (size_t)(h * DH) * NKV + b * KVLEN + k0 };
        const int r = tid >> 3, c = tid & 7;
#pragma unroll
        for (int arr = 0; arr < 3; arr++) {
            size_t rstride = (arr < 2) ? DMODEL : NKV;
            uint32_t dst = sb + ((AKV + slot * SLOT_W + arr * 2304 + r * AST + c * 4) << 2);
            CP_ASYNC16(dst, srcs[arr] + (size_t)r * rstride + c * 8);
        }
        if (tid < 16) {
            uint32_t dst = sb + ((AB + slot * 64 + tid * 4) << 2);
            CP_ASYNC16(dst, bias + (size_t)b * KVLEN + k0 + tid * 4);
        }
        asm volatile("cp.async.commit_group;");
    };

    float oacc[8][4];
#pragma unroll
    for (int nt = 0; nt < 8; nt++)
#pragma unroll
        for (int r = 0; r < 4; r++) oacc[nt][r] = 0.f;
    float dsum0 = 0.f, dsum1 = 0.f;

    const int NT = KVLEN / 64;
    load_tile(0, 0);
    load_tile(1, 1);
    load_tile(2, 2);

    for (int kt = 0; kt < NT; kt++) {
        const int slot = kt & 3;
        if (kt < NT - 2)       asm volatile("cp.async.wait_group 2;");
        else if (kt == NT - 2) asm volatile("cp.async.wait_group 1;");
        else                   asm volatile("cp.async.wait_group 0;");
        __syncthreads();
        if (kt + 3 < NT) load_tile(kt + 3, (kt + 3) & 3);

        // ---- S = Q·K^T (hi + lo correction) ----
        float sacc[8][4];
#pragma unroll
        for (int nt = 0; nt < 8; nt++)
#pragma unroll
            for (int r = 0; r < 4; r++) sacc[nt][r] = 0.f;

        const uint32_t kbase = AKV + slot * SLOT_W;
#pragma unroll
        for (int ks = 0; ks < 4; ks++) {
            uint32_t aH[4];
            LDSM_X4(aH, sb + ((AQ + a_row * AST + ks * 8 + a_col) << 2));
#pragma unroll
            for (int nt = 0; nt < 8; nt++) {
                uint32_t bf[4];
                LDSM_X4(bf, sb + ((kbase + kb_arr + (kb_row + nt * 8) * AST + ks * 8 + kb_col) << 2));
                mma_f16(sacc[nt], aH, bf);
                mma_f16(sacc[nt], aH, bf + 2);
            }
        }

        // ---- P = exp(S*scale + bias) ----
        const float* bsm = (const float*)(sw + AB + slot * 64);
#pragma unroll
        for (int nt = 0; nt < 8; nt++) {
            float b0 = bsm[nt * 8 + tg * 2];
            float b1 = bsm[nt * 8 + tg * 2 + 1];
            float p0 = __expf(fmaf(sacc[nt][0], 0.125f, b0));
            float p1 = __expf(fmaf(sacc[nt][1], 0.125f, b1));
            float p2 = __expf(fmaf(sacc[nt][2], 0.125f, b0));
            float p3 = __expf(fmaf(sacc[nt][3], 0.125f, b1));
            sacc[nt][0] = p0; sacc[nt][1] = p1; sacc[nt][2] = p2; sacc[nt][3] = p3;
            dsum0 += p0 + p1;
            dsum1 += p2 + p3;
        }

        // ---- O += P·V (V hi only; one x4 -> two n-tiles) ----
        const uint32_t vbase = kbase + 2 * 2304;
#pragma unroll
        for (int ks = 0; ks < 4; ks++) {
            const float* pa = sacc[2 * ks];
            const float* pb = sacc[2 * ks + 1];
            __half2 h0 = __floats2half2_rn(pa[0], pa[1]);
            __half2 h1 = __floats2half2_rn(pa[2], pa[3]);
            __half2 h2 = __floats2half2_rn(pb[0], pb[1]);
            __half2 h3 = __floats2half2_rn(pb[2], pb[3]);
            uint32_t aP[4] = { *(uint32_t*)&h0, *(uint32_t*)&h1, *(uint32_t*)&h2, *(uint32_t*)&h3 };
#pragma unroll
            for (int np = 0; np < 4; np++) {
                uint32_t bf[4];
                LDSM_X4(bf, sb + ((vbase + (vb_row + np * 16) * AST + ks * 8 + vb_col) << 2));
                mma_f16(oacc[2 * np],     aP, bf);
                mma_f16(oacc[2 * np + 1], aP, bf + 2);
            }
        }
    }

    // ---- denominators (quad reduce) ----
    dsum0 += __shfl_xor_sync(0xFFFFFFFFu, dsum0, 1);
    dsum0 += __shfl_xor_sync(0xFFFFFFFFu, dsum0, 2);
    dsum1 += __shfl_xor_sync(0xFFFFFFFFu, dsum1, 1);
    dsum1 += __shfl_xor_sync(0xFFFFFFFFu, dsum1, 2);
    const float inv0 = 1.f / dsum0, inv1 = 1.f / dsum1;

    const int row = b * QLEN + q0 + qrow + g;
#pragma unroll
    for (int nt = 0; nt < 8; nt++) {
        const int col = h * DH + nt * 8 + tg * 2;
        __half2 o0 = __floats2half2_rn(oacc[nt][0] * inv0, oacc[nt][1] * inv0);
        __half2 o1 = __floats2half2_rn(oacc[nt][2] * inv1, oacc[nt][3] * inv1);
        *(uint32_t*)(g_ah + (size_t)row * DMODEL + col)       = *(uint32_t*)&o0;
        *(uint32_t*)(g_ah + (size_t)(row + 8) * DMODEL + col) = *(uint32_t*)&o1;
    }
}

// ---------------------------------------------------------------------------
extern "C" void kernel_launch(void* const* d_in, const int* in_sizes, int n_in,
                              void* d_out, int out_size)
{
    const float* query  = (const float*)d_in[0];
    const float* memory = (const float*)d_in[1];
    const float* bias   = (const float*)d_in[2];
    const float* Wq     = (const float*)d_in[3];
    const float* Wk     = (const float*)d_in[4];
    const float* Wv     = (const float*)d_in[5];
    const float* Wo     = (const float*)d_in[6];
    float* out = (float*)d_out;

    cudaFuncSetAttribute(k_proj,    cudaFuncAttributeMaxDynamicSharedMemorySize, GEMM_SMEM);
    cudaFuncSetAttribute(k_outproj, cudaFuncAttributeMaxDynamicSharedMemorySize, GEMM_SMEM);
    cudaFuncSetAttribute(attn_mma,  cudaFuncAttributeMaxDynamicSharedMemorySize, ATTN_SMEM);

    k_prep<<<4096, 256>>>(query, memory);
    k_tsplit4<<<dim3(DMODEL / 32, DMODEL / 32, 4), dim3(32, 8)>>>(Wq, Wk, Wv, Wo);

    k_proj<<<2176, 256, GEMM_SMEM>>>();

    attn_mma<<<dim3(QLEN / 256, NHEAD, BATCH), 512, ATTN_SMEM>>>(bias);

    k_outproj<<<128, 256, GEMM_SMEM>>>(out);
}

// round 14
// speedup vs baseline: 6.3413x; 1.4002x over previous
#include <cuda_runtime.h>
#include <cuda_fp16.h>
#include <cstdint>
#include <math.h>

#define BATCH   4
#define QLEN    512
#define KVLEN   4096
#define DMODEL  1024
#define NHEAD   16
#define DH      64
#define GK      1024
#define NKV     (BATCH * KVLEN)

// ---------------- scratch (allocation-free rule) ----------------
__device__ __half g_mh [BATCH * KVLEN * DMODEL];   // memory hi
__device__ __half g_qh [BATCH * QLEN  * DMODEL];   // query hi
__device__ __half g_ah [BATCH * QLEN  * DMODEL];   // attention out hi
__device__ __half g_wh [4][DMODEL * DMODEL];       // W^T hi
__device__ __half g_wl [4][DMODEL * DMODEL];       // W^T lo (used for Wq, Wo)
__device__ __half g_pqh[BATCH * QLEN  * DMODEL];   // Q proj hi
__device__ __half g_pkh[BATCH * KVLEN * DMODEL];   // K proj hi
__device__ __half g_vth[DMODEL * NKV];             // V^T hi [d][b*kv]

#define CP_ASYNC16(d, s) asm volatile("cp.async.cg.shared.global [%0], [%1], 16;" :: "r"(d), "l"(s))
#define LDSM_X4(r, a) \
    asm volatile("ldmatrix.sync.aligned.m8n8.x4.shared.b16 {%0,%1,%2,%3}, [%4];" \
        : "=r"((r)[0]), "=r"((r)[1]), "=r"((r)[2]), "=r"((r)[3]) : "r"(a))

__device__ __forceinline__ void mma_f16(float* c, const uint32_t* a, const uint32_t* b) {
    asm volatile(
        "mma.sync.aligned.m16n8k16.row.col.f32.f16.f16.f32 "
        "{%0,%1,%2,%3}, {%4,%5,%6,%7}, {%8,%9}, {%0,%1,%2,%3};"
        : "+f"(c[0]), "+f"(c[1]), "+f"(c[2]), "+f"(c[3])
        : "r"(a[0]), "r"(a[1]), "r"(a[2]), "r"(a[3]), "r"(b[0]), "r"(b[1]));
}
__device__ __forceinline__ void split2h(float v0, float v1, uint32_t& h, uint32_t& l) {
    __half2 hh = __floats2half2_rn(v0, v1);
    __half2 ll = __floats2half2_rn(v0 - __half2float(__low2half(hh)),
                                   v1 - __half2float(__high2half(hh)));
    h = *(uint32_t*)&hh;  l = *(uint32_t*)&ll;
}

// ---------------- preps ----------------
__global__ void k_prep(const float* __restrict__ query, const float* __restrict__ memory)
{
    const int n_q  = BATCH * QLEN  * DMODEL;
    const int n_kv = BATCH * KVLEN * DMODEL;
    for (int i = blockIdx.x * blockDim.x + threadIdx.x; i < n_q + n_kv;
         i += gridDim.x * blockDim.x) {
        if (i < n_q) g_qh[i] = __float2half_rn(query[i]);
        else         g_mh[i - n_q] = __float2half_rn(memory[i - n_q]);
    }
}
__global__ void k_tsplit4(const float* __restrict__ W0, const float* __restrict__ W1,
                          const float* __restrict__ W2, const float* __restrict__ W3)
{
    __shared__ float t[32][33];
    const float* Ws[4] = {W0, W1, W2, W3};
    int w = blockIdx.z;
    const float* W = Ws[w];
    __half* Th = g_wh[w];
    __half* Tl = g_wl[w];
    const bool need_lo = (w == 0) || (w == 3);
    int k0 = blockIdx.y * 32, n0 = blockIdx.x * 32;
    int tx = threadIdx.x, ty = threadIdx.y;
#pragma unroll
    for (int i = 0; i < 4; i++)
        t[ty + 8 * i][tx] = W[(size_t)(k0 + ty + 8 * i) * DMODEL + n0 + tx];
    __syncthreads();
#pragma unroll
    for (int i = 0; i < 4; i++) {
        float v = t[tx][ty + 8 * i];
        __half h = __float2half_rn(v);
        size_t o = (size_t)(n0 + ty + 8 * i) * DMODEL + k0 + tx;
        Th[o] = h;
        if (need_lo) Tl[o] = __float2half_rn(v - __half2float(h));
    }
}

// ---------------------------------------------------------------------------
// fp16 GEMM body, templated on number of B operands (NB=2: hi+lo, NB=1: hi).
// CTA 128x128, BK=64, 2-stage, one barrier per k-tile, ldmatrix fragments.
// ---------------------------------------------------------------------------
#define SKW   36
#define ARR_W (128 * SKW)
#define GEMM_SMEM (2 * 3 * ARR_W * 4)     // max (NB=2) layout: 110592 B

struct GemmAcc { float a[4][4][4]; };

template<int NB>
__device__ __forceinline__ void gemm_body(
    uint32_t* sm32, const __half* A, const __half* Bh, const __half* Bl,
    int bm, int bn, GemmAcc& acc_)
{
    constexpr int NARR = 1 + NB;
    constexpr int BUF_W = NARR * ARR_W;

    const int tid  = threadIdx.x;
    const int wid  = tid >> 5, lane = tid & 31;
    const int r8   = lane & 7, sub = lane >> 3;
    const int wm64 = (wid & 1) * 64;
    const int wn32 = (wid >> 1) * 32;

    const size_t arow0 = (size_t)bm * 128 * GK;
    const size_t brow0 = (size_t)bn * 128 * GK;
    const uint32_t smem_b = (uint32_t)__cvta_generic_to_shared(sm32);

    const int a_row = wm64 + r8 + ((sub & 1) << 3);
    const int a_col = (sub >> 1) << 2;
    // NB=2: x4 pairs hi/lo of one n-tile.  NB=1: x4 spans two n-tiles.
    const int b_row2 = wn32 + r8;
    const int b_col  = ((sub & 1) << 2);
    const int b_arr2 = ARR_W + (sub >> 1) * ARR_W;
    const int b_row1 = wn32 + ((sub >> 1) << 3) + r8;

    float (*acc)[4][4] = acc_.a;
#pragma unroll
    for (int mt = 0; mt < 4; mt++)
#pragma unroll
        for (int nt = 0; nt < 4; nt++)
#pragma unroll
            for (int r = 0; r < 4; r++) acc[mt][nt][r] = 0.f;

    auto load_tile = [&](int kt, int buf) {
        const __half* srcs[3] = { A + arow0 + kt * 64, Bh + brow0 + kt * 64,
                                  NB == 2 ? Bl + brow0 + kt * 64 : Bh };
#pragma unroll
        for (int i = 0; i < 4 * NARR; i++) {
            int chunk = tid + 256 * i;
            int arr = chunk >> 10;
            int w   = chunk & 1023;
            int row = w >> 3, c = w & 7;
            uint32_t dst = smem_b + ((buf * BUF_W + arr * ARR_W + row * SKW + c * 4) << 2);
            CP_ASYNC16(dst, srcs[arr] + (size_t)row * GK + c * 8);
        }
        asm volatile("cp.async.commit_group;");
    };

    load_tile(0, 0);

    const int NT = GK / 64;
    for (int kt = 0; kt < NT; kt++) {
        const int buf = kt & 1;
        asm volatile("cp.async.wait_group 0;");
        __syncthreads();
        if (kt + 1 < NT) load_tile(kt + 1, 1 - buf);

        const uint32_t bufw = buf * BUF_W;
#pragma unroll
        for (int ks = 0; ks < 4; ks++) {
            uint32_t bf[4][4];
            if (NB == 2) {
#pragma unroll
                for (int nt = 0; nt < 4; nt++)
                    LDSM_X4(bf[nt], smem_b + ((bufw + b_arr2 + (b_row2 + nt * 8) * SKW + ks * 8 + b_col) << 2));
            } else {
#pragma unroll
                for (int np = 0; np < 2; np++)
                    LDSM_X4(bf[np], smem_b + ((bufw + ARR_W + (b_row1 + np * 16) * SKW + ks * 8 + b_col) << 2));
            }
#pragma unroll
            for (int mt = 0; mt < 4; mt++) {
                uint32_t ah[4];
                LDSM_X4(ah, smem_b + ((bufw + (a_row + mt * 16) * SKW + ks * 8 + a_col) << 2));
                if (NB == 2) {
#pragma unroll
                    for (int nt = 0; nt < 4; nt++) {
                        mma_f16(acc[mt][nt], ah, bf[nt]);
                        mma_f16(acc[mt][nt], ah, bf[nt] + 2);
                    }
                } else {
#pragma unroll
                    for (int np = 0; np < 2; np++) {
                        mma_f16(acc[mt][2 * np],     ah, bf[np]);
                        mma_f16(acc[mt][2 * np + 1], ah, bf[np] + 2);
                    }
                }
            }
        }
    }
}

// Unified projections: Q (2-term) | K (1-term) | V transposed (1-term).
__global__ __launch_bounds__(256, 2)
void k_proj()
{
    extern __shared__ __align__(16) uint32_t sm32[];
    const int id = blockIdx.x;

    GemmAcc acc_;
    __half* Chi;
    int ldC, bm, bn;
    if (id < 128) {
        bm = id >> 3; bn = id & 7; ldC = DMODEL; Chi = g_pqh;
        gemm_body<2>(sm32, g_qh, g_wh[0], g_wl[0], bm, bn, acc_);
    } else if (id < 1152) {
        int q = id - 128;
        bm = q >> 3; bn = q & 7; ldC = DMODEL; Chi = g_pkh;
        gemm_body<1>(sm32, g_mh, g_wh[1], nullptr, bm, bn, acc_);
    } else {
        int q = id - 1152;
        bm = q >> 7; bn = q & 127; ldC = NKV; Chi = g_vth;
        gemm_body<1>(sm32, g_wh[2], g_mh, nullptr, bm, bn, acc_);
    }

    const int lane = threadIdx.x & 31, wid = threadIdx.x >> 5;
    const int g = lane >> 2, tg = lane & 3;
    const int wm64 = (wid & 1) * 64, wn32 = (wid >> 1) * 32;
#pragma unroll
    for (int mt = 0; mt < 4; mt++) {
        int row0 = bm * 128 + wm64 + mt * 16 + g;
#pragma unroll
        for (int nt = 0; nt < 4; nt++) {
            int col = bn * 128 + wn32 + nt * 8 + tg * 2;
            __half2 h0 = __floats2half2_rn(acc_.a[mt][nt][0], acc_.a[mt][nt][1]);
            __half2 h1 = __floats2half2_rn(acc_.a[mt][nt][2], acc_.a[mt][nt][3]);
            *(uint32_t*)(Chi + (size_t)row0 * ldC + col)       = *(uint32_t*)&h0;
            *(uint32_t*)(Chi + (size_t)(row0 + 8) * ldC + col) = *(uint32_t*)&h1;
        }
    }
}

__global__ __launch_bounds__(256, 2)
void k_outproj(float* __restrict__ C)
{
    extern __shared__ __align__(16) uint32_t sm32[];
    const int bm = blockIdx.x >> 3, bn = blockIdx.x & 7;

    GemmAcc acc_;
    gemm_body<2>(sm32, g_ah, g_wh[3], g_wl[3], bm, bn, acc_);

    const int lane = threadIdx.x & 31, wid = threadIdx.x >> 5;
    const int g = lane >> 2, tg = lane & 3;
    const int wm64 = (wid & 1) * 64, wn32 = (wid >> 1) * 32;
#pragma unroll
    for (int mt = 0; mt < 4; mt++) {
        int row0 = bm * 128 + wm64 + mt * 16 + g;
#pragma unroll
        for (int nt = 0; nt < 4; nt++) {
            int col = bn * 128 + wn32 + nt * 8 + tg * 2;
            *(float2*)(C + (size_t)row0 * DMODEL + col)       = make_float2(acc_.a[mt][nt][0], acc_.a[mt][nt][1]);
            *(float2*)(C + (size_t)(row0 + 8) * DMODEL + col) = make_float2(acc_.a[mt][nt][2], acc_.a[mt][nt][3]);
        }
    }
}

// ---------------------------------------------------------------------------
// fp16 attention: 512 threads, q-tile 256, 4-stage ring, K and V hi-only.
// Slot layout: [KH 2304][VH 2304] words. S and PV are 1 MMA per n-tile each.
// ---------------------------------------------------------------------------
#define AST    36
#define AQ     0
#define AKV    (256 * AST)                  // 9216
#define SLOT_W (2 * 64 * AST)               // 4608 words per stage
#define AB     (AKV + 4 * SLOT_W)           // 27648
#define ATTN_SMEM ((AB + 256) * 4)          // 111616 bytes

__global__ __launch_bounds__(512, 1)
void attn_mma(const float* __restrict__ bias)
{
    extern __shared__ __align__(16) uint32_t sw[];
    const uint32_t sb = (uint32_t)__cvta_generic_to_shared(sw);
    const int tid = threadIdx.x, wid = tid >> 5, lane = tid & 31;
    const int g = lane >> 2, tg = lane & 3;
    const int r8 = lane & 7, sub = lane >> 3;
    const int qt = blockIdx.x, h = blockIdx.y, b = blockIdx.z;
    const int q0 = qt * 256;
    const int qrow = wid * 16;

    const int a_row = qrow + r8 + ((sub & 1) << 3);
    const int a_col = (sub >> 1) << 2;
    // hi-only B-frag: one x4 spans TWO n-tiles (sub>>1 picks the nt half)
    const int pb_row = ((sub >> 1) << 3) + r8;
    const int pb_col = ((sub & 1) << 2);

    // ---- Q load ----
    {
        const __half* s0 = g_pqh + ((size_t)(b * QLEN + q0)) * DMODEL + h * DH;
#pragma unroll
        for (int i = 0; i < 4; i++) {
            int chunk = tid + 512 * i;
            int r = chunk >> 3, c = chunk & 7;
            uint32_t dst = sb + ((AQ + r * AST + c * 4) << 2);
            CP_ASYNC16(dst, s0 + (size_t)r * DMODEL + c * 8);
        }
        asm volatile("cp.async.commit_group;");
    }

    auto load_tile = [&](int kt, int slot) {
        const int k0 = kt * 64;
        const __half* srcs[2] = {
            g_pkh + ((size_t)(b * KVLEN + k0)) * DMODEL + h * DH,
            g_vth + (size_t)(h * DH) * NKV + b * KVLEN + k0 };
        const int r = tid >> 3, c = tid & 7;
#pragma unroll
        for (int arr = 0; arr < 2; arr++) {
            size_t rstride = (arr == 0) ? DMODEL : NKV;
            uint32_t dst = sb + ((AKV + slot * SLOT_W + arr * 2304 + r * AST + c * 4) << 2);
            CP_ASYNC16(dst, srcs[arr] + (size_t)r * rstride + c * 8);
        }
        if (tid < 16) {
            uint32_t dst = sb + ((AB + slot * 64 + tid * 4) << 2);
            CP_ASYNC16(dst, bias + (size_t)b * KVLEN + k0 + tid * 4);
        }
        asm volatile("cp.async.commit_group;");
    };

    float oacc[8][4];
#pragma unroll
    for (int nt = 0; nt < 8; nt++)
#pragma unroll
        for (int r = 0; r < 4; r++) oacc[nt][r] = 0.f;
    float dsum0 = 0.f, dsum1 = 0.f;

    const int NT = KVLEN / 64;
    load_tile(0, 0);
    load_tile(1, 1);
    load_tile(2, 2);

    for (int kt = 0; kt < NT; kt++) {
        const int slot = kt & 3;
        if (kt < NT - 2)       asm volatile("cp.async.wait_group 2;");
        else if (kt == NT - 2) asm volatile("cp.async.wait_group 1;");
        else                   asm volatile("cp.async.wait_group 0;");
        __syncthreads();
        if (kt + 3 < NT) load_tile(kt + 3, (kt + 3) & 3);

        // ---- S = Q·K^T (hi only) ----
        float sacc[8][4];
#pragma unroll
        for (int nt = 0; nt < 8; nt++)
#pragma unroll
            for (int r = 0; r < 4; r++) sacc[nt][r] = 0.f;

        const uint32_t kbase = AKV + slot * SLOT_W;
#pragma unroll
        for (int ks = 0; ks < 4; ks++) {
            uint32_t aH[4];
            LDSM_X4(aH, sb + ((AQ + a_row * AST + ks * 8 + a_col) << 2));
#pragma unroll
            for (int np = 0; np < 4; np++) {
                uint32_t bf[4];
                LDSM_X4(bf, sb + ((kbase + (pb_row + np * 16) * AST + ks * 8 + pb_col) << 2));
                mma_f16(sacc[2 * np],     aH, bf);
                mma_f16(sacc[2 * np + 1], aH, bf + 2);
            }
        }

        // ---- P = exp(S*scale + bias) ----
        const float* bsm = (const float*)(sw + AB + slot * 64);
#pragma unroll
        for (int nt = 0; nt < 8; nt++) {
            float b0 = bsm[nt * 8 + tg * 2];
            float b1 = bsm[nt * 8 + tg * 2 + 1];
            float p0 = __expf(fmaf(sacc[nt][0], 0.125f, b0));
            float p1 = __expf(fmaf(sacc[nt][1], 0.125f, b1));
            float p2 = __expf(fmaf(sacc[nt][2], 0.125f, b0));
            float p3 = __expf(fmaf(sacc[nt][3], 0.125f, b1));
            sacc[nt][0] = p0; sacc[nt][1] = p1; sacc[nt][2] = p2; sacc[nt][3] = p3;
            dsum0 += p0 + p1;
            dsum1 += p2 + p3;
        }

        // ---- O += P·V (hi only) ----
        const uint32_t vbase = kbase + 2304;
#pragma unroll
        for (int ks = 0; ks < 4; ks++) {
            const float* pa = sacc[2 * ks];
            const float* pb = sacc[2 * ks + 1];
            __half2 h0 = __floats2half2_rn(pa[0], pa[1]);
            __half2 h1 = __floats2half2_rn(pa[2], pa[3]);
            __half2 h2 = __floats2half2_rn(pb[0], pb[1]);
            __half2 h3 = __floats2half2_rn(pb[2], pb[3]);
            uint32_t aP[4] = { *(uint32_t*)&h0, *(uint32_t*)&h1, *(uint32_t*)&h2, *(uint32_t*)&h3 };
#pragma unroll
            for (int np = 0; np < 4; np++) {
                uint32_t bf[4];
                LDSM_X4(bf, sb + ((vbase + (pb_row + np * 16) * AST + ks * 8 + pb_col) << 2));
                mma_f16(oacc[2 * np],     aP, bf);
                mma_f16(oacc[2 * np + 1], aP, bf + 2);
            }
        }
    }

    // ---- denominators (quad reduce) ----
    dsum0 += __shfl_xor_sync(0xFFFFFFFFu, dsum0, 1);
    dsum0 += __shfl_xor_sync(0xFFFFFFFFu, dsum0, 2);
    dsum1 += __shfl_xor_sync(0xFFFFFFFFu, dsum1, 1);
    dsum1 += __shfl_xor_sync(0xFFFFFFFFu, dsum1, 2);
    const float inv0 = 1.f / dsum0, inv1 = 1.f / dsum1;

    const int row = b * QLEN + q0 + qrow + g;
#pragma unroll
    for (int nt = 0; nt < 8; nt++) {
        const int col = h * DH + nt * 8 + tg * 2;
        __half2 o0 = __floats2half2_rn(oacc[nt][0] * inv0, oacc[nt][1] * inv0);
        __half2 o1 = __floats2half2_rn(oacc[nt][2] * inv1, oacc[nt][3] * inv1);
        *(uint32_t*)(g_ah + (size_t)row * DMODEL + col)       = *(uint32_t*)&o0;
        *(uint32_t*)(g_ah + (size_t)(row + 8) * DMODEL + col) = *(uint32_t*)&o1;
    }
}

// ---------------------------------------------------------------------------
extern "C" void kernel_launch(void* const* d_in, const int* in_sizes, int n_in,
                              void* d_out, int out_size)
{
    const float* query  = (const float*)d_in[0];
    const float* memory = (const float*)d_in[1];
    const float* bias   = (const float*)d_in[2];
    const float* Wq     = (const float*)d_in[3];
    const float* Wk     = (const float*)d_in[4];
    const float* Wv     = (const float*)d_in[5];
    const float* Wo     = (const float*)d_in[6];
    float* out = (float*)d_out;

    cudaFuncSetAttribute(k_proj,    cudaFuncAttributeMaxDynamicSharedMemorySize, GEMM_SMEM);
    cudaFuncSetAttribute(k_outproj, cudaFuncAttributeMaxDynamicSharedMemorySize, GEMM_SMEM);
    cudaFuncSetAttribute(attn_mma,  cudaFuncAttributeMaxDynamicSharedMemorySize, ATTN_SMEM);

    k_prep<<<4096, 256>>>(query, memory);
    k_tsplit4<<<dim3(DMODEL / 32, DMODEL / 32, 4), dim3(32, 8)>>>(Wq, Wk, Wv, Wo);

    k_proj<<<2176, 256, GEMM_SMEM>>>();

    attn_mma<<<dim3(QLEN / 256, NHEAD, BATCH), 512, ATTN_SMEM>>>(bias);

    k_outproj<<<128, 256, GEMM_SMEM>>>(out);
}

// round 15
// speedup vs baseline: 6.3894x; 1.0076x over previous
#include <cuda_runtime.h>
#include <cuda_fp16.h>
#include <cstdint>
#include <math.h>

#define BATCH   4
#define QLEN    512
#define KVLEN   4096
#define DMODEL  1024
#define NHEAD   16
#define DH      64
#define GK      1024
#define NKV     (BATCH * KVLEN)

// ---------------- scratch (allocation-free rule) ----------------
__device__ __half g_mh [BATCH * KVLEN * DMODEL];
__device__ __half g_qh [BATCH * QLEN  * DMODEL];
__device__ __half g_ah [BATCH * QLEN  * DMODEL];
__device__ __half g_wh [4][DMODEL * DMODEL];
__device__ __half g_wl [4][DMODEL * DMODEL];
__device__ __half g_pqh[BATCH * QLEN  * DMODEL];
__device__ __half g_pkh[BATCH * KVLEN * DMODEL];
__device__ __half g_vth[DMODEL * NKV];
__device__ float  g_b2 [BATCH * KVLEN];            // bias * log2(e)

#define CP_ASYNC16(d, s) asm volatile("cp.async.cg.shared.global [%0], [%1], 16;" :: "r"(d), "l"(s))
#define LDSM_X4(r, a) \
    asm volatile("ldmatrix.sync.aligned.m8n8.x4.shared.b16 {%0,%1,%2,%3}, [%4];" \
        : "=r"((r)[0]), "=r"((r)[1]), "=r"((r)[2]), "=r"((r)[3]) : "r"(a))

__device__ __forceinline__ void mma_f16(float* c, const uint32_t* a, const uint32_t* b) {
    asm volatile(
        "mma.sync.aligned.m16n8k16.row.col.f32.f16.f16.f32 "
        "{%0,%1,%2,%3}, {%4,%5,%6,%7}, {%8,%9}, {%0,%1,%2,%3};"
        : "+f"(c[0]), "+f"(c[1]), "+f"(c[2]), "+f"(c[3])
        : "r"(a[0]), "r"(a[1]), "r"(a[2]), "r"(a[3]), "r"(b[0]), "r"(b[1]));
}

// ---------------- preps ----------------
__global__ void k_prep(const float* __restrict__ query, const float* __restrict__ memory,
                       const float* __restrict__ bias)
{
    const int n_q  = BATCH * QLEN  * DMODEL;
    const int n_kv = BATCH * KVLEN * DMODEL;
    const int n_b  = BATCH * KVLEN;
    for (int i = blockIdx.x * blockDim.x + threadIdx.x; i < n_q + n_kv + n_b;
         i += gridDim.x * blockDim.x) {
        if (i < n_q)           g_qh[i] = __float2half_rn(query[i]);
        else if (i < n_q + n_kv) g_mh[i - n_q] = __float2half_rn(memory[i - n_q]);
        else                   g_b2[i - n_q - n_kv] = bias[i - n_q - n_kv] * 1.4426950408889634f;
    }
}
__global__ void k_tsplit4(const float* __restrict__ W0, const float* __restrict__ W1,
                          const float* __restrict__ W2, const float* __restrict__ W3)
{
    __shared__ float t[32][33];
    const float* Ws[4] = {W0, W1, W2, W3};
    int w = blockIdx.z;
    const float* W = Ws[w];
    __half* Th = g_wh[w];
    __half* Tl = g_wl[w];
    const bool need_lo = (w == 0) || (w == 3);
    int k0 = blockIdx.y * 32, n0 = blockIdx.x * 32;
    int tx = threadIdx.x, ty = threadIdx.y;
#pragma unroll
    for (int i = 0; i < 4; i++)
        t[ty + 8 * i][tx] = W[(size_t)(k0 + ty + 8 * i) * DMODEL + n0 + tx];
    __syncthreads();
#pragma unroll
    for (int i = 0; i < 4; i++) {
        float v = t[tx][ty + 8 * i];
        __half h = __float2half_rn(v);
        size_t o = (size_t)(n0 + ty + 8 * i) * DMODEL + k0 + tx;
        Th[o] = h;
        if (need_lo) Tl[o] = __float2half_rn(v - __half2float(h));
    }
}

// ---------------------------------------------------------------------------
// fp16 GEMM body. NB=2: hi+lo B, 2-stage ring. NB=1: hi B, 3-stage ring
// (fill latency hidden). CTA 128x128, BK=64, one barrier per k-tile.
// ---------------------------------------------------------------------------
#define SKW   36
#define ARR_W (128 * SKW)
#define GEMM_SMEM (2 * 3 * ARR_W * 4)     // 110592 B (both variants fit)

struct GemmAcc { float a[4][4][4]; };

template<int NB>
__device__ __forceinline__ void gemm_body(
    uint32_t* sm32, const __half* A, const __half* Bh, const __half* Bl,
    int bm, int bn, GemmAcc& acc_)
{
    constexpr int NARR   = 1 + NB;
    constexpr int STAGES = (NB == 1) ? 3 : 2;
    constexpr int BUF_W  = NARR * ARR_W;

    const int tid  = threadIdx.x;
    const int wid  = tid >> 5, lane = tid & 31;
    const int r8   = lane & 7, sub = lane >> 3;
    const int wm64 = (wid & 1) * 64;
    const int wn32 = (wid >> 1) * 32;

    const size_t arow0 = (size_t)bm * 128 * GK;
    const size_t brow0 = (size_t)bn * 128 * GK;
    const uint32_t smem_b = (uint32_t)__cvta_generic_to_shared(sm32);

    const int a_row = wm64 + r8 + ((sub & 1) << 3);
    const int a_col = (sub >> 1) << 2;
    const int b_row2 = wn32 + r8;
    const int b_col  = ((sub & 1) << 2);
    const int b_arr2 = ARR_W + (sub >> 1) * ARR_W;
    const int b_row1 = wn32 + ((sub >> 1) << 3) + r8;

    float (*acc)[4][4] = acc_.a;
#pragma unroll
    for (int mt = 0; mt < 4; mt++)
#pragma unroll
        for (int nt = 0; nt < 4; nt++)
#pragma unroll
            for (int r = 0; r < 4; r++) acc[mt][nt][r] = 0.f;

    auto load_tile = [&](int kt, int slot) {
        const __half* srcs[3] = { A + arow0 + kt * 64, Bh + brow0 + kt * 64,
                                  NB == 2 ? Bl + brow0 + kt * 64 : Bh };
#pragma unroll
        for (int i = 0; i < 4 * NARR; i++) {
            int chunk = tid + 256 * i;
            int arr = chunk >> 10;
            int w   = chunk & 1023;
            int row = w >> 3, c = w & 7;
            uint32_t dst = smem_b + ((slot * BUF_W + arr * ARR_W + row * SKW + c * 4) << 2);
            CP_ASYNC16(dst, srcs[arr] + (size_t)row * GK + c * 8);
        }
        asm volatile("cp.async.commit_group;");
    };

    load_tile(0, 0);
    if (STAGES == 3) load_tile(1, 1);

    const int NT = GK / 64;
    for (int kt = 0; kt < NT; kt++) {
        const int slot = kt % STAGES;
        if (STAGES == 3 && kt < NT - 1) asm volatile("cp.async.wait_group 1;");
        else                            asm volatile("cp.async.wait_group 0;");
        __syncthreads();
        if (kt + STAGES - 1 < NT) load_tile(kt + STAGES - 1, (kt + STAGES - 1) % STAGES);

        const uint32_t bufw = slot * BUF_W;
#pragma unroll
        for (int ks = 0; ks < 4; ks++) {
            uint32_t bf[4][4];
            if (NB == 2) {
#pragma unroll
                for (int nt = 0; nt < 4; nt++)
                    LDSM_X4(bf[nt], smem_b + ((bufw + b_arr2 + (b_row2 + nt * 8) * SKW + ks * 8 + b_col) << 2));
            } else {
#pragma unroll
                for (int np = 0; np < 2; np++)
                    LDSM_X4(bf[np], smem_b + ((bufw + ARR_W + (b_row1 + np * 16) * SKW + ks * 8 + b_col) << 2));
            }
#pragma unroll
            for (int mt = 0; mt < 4; mt++) {
                uint32_t ah[4];
                LDSM_X4(ah, smem_b + ((bufw + (a_row + mt * 16) * SKW + ks * 8 + a_col) << 2));
                if (NB == 2) {
#pragma unroll
                    for (int nt = 0; nt < 4; nt++) {
                        mma_f16(acc[mt][nt], ah, bf[nt]);
                        mma_f16(acc[mt][nt], ah, bf[nt] + 2);
                    }
                } else {
#pragma unroll
                    for (int np = 0; np < 2; np++) {
                        mma_f16(acc[mt][2 * np],     ah, bf[np]);
                        mma_f16(acc[mt][2 * np + 1], ah, bf[np] + 2);
                    }
                }
            }
        }
    }
}

// Unified projections: Q (2-term) | K (1-term) | V transposed (1-term).
__global__ __launch_bounds__(256, 2)
void k_proj()
{
    extern __shared__ __align__(16) uint32_t sm32[];
    const int id = blockIdx.x;

    GemmAcc acc_;
    __half* Chi;
    int ldC, bm, bn;
    if (id < 128) {
        bm = id >> 3; bn = id & 7; ldC = DMODEL; Chi = g_pqh;
        gemm_body<2>(sm32, g_qh, g_wh[0], g_wl[0], bm, bn, acc_);
    } else if (id < 1152) {
        int q = id - 128;
        bm = q >> 3; bn = q & 7; ldC = DMODEL; Chi = g_pkh;
        gemm_body<1>(sm32, g_mh, g_wh[1], nullptr, bm, bn, acc_);
    } else {
        int q = id - 1152;
        bm = q >> 7; bn = q & 127; ldC = NKV; Chi = g_vth;
        gemm_body<1>(sm32, g_wh[2], g_mh, nullptr, bm, bn, acc_);
    }

    const int lane = threadIdx.x & 31, wid = threadIdx.x >> 5;
    const int g = lane >> 2, tg = lane & 3;
    const int wm64 = (wid & 1) * 64, wn32 = (wid >> 1) * 32;
#pragma unroll
    for (int mt = 0; mt < 4; mt++) {
        int row0 = bm * 128 + wm64 + mt * 16 + g;
#pragma unroll
        for (int nt = 0; nt < 4; nt++) {
            int col = bn * 128 + wn32 + nt * 8 + tg * 2;
            __half2 h0 = __floats2half2_rn(acc_.a[mt][nt][0], acc_.a[mt][nt][1]);
            __half2 h1 = __floats2half2_rn(acc_.a[mt][nt][2], acc_.a[mt][nt][3]);
            *(uint32_t*)(Chi + (size_t)row0 * ldC + col)       = *(uint32_t*)&h0;
            *(uint32_t*)(Chi + (size_t)(row0 + 8) * ldC + col) = *(uint32_t*)&h1;
        }
    }
}

__global__ __launch_bounds__(256, 2)
void k_outproj(float* __restrict__ C)
{
    extern __shared__ __align__(16) uint32_t sm32[];
    const int bm = blockIdx.x >> 3, bn = blockIdx.x & 7;

    GemmAcc acc_;
    gemm_body<2>(sm32, g_ah, g_wh[3], g_wl[3], bm, bn, acc_);

    const int lane = threadIdx.x & 31, wid = threadIdx.x >> 5;
    const int g = lane >> 2, tg = lane & 3;
    const int wm64 = (wid & 1) * 64, wn32 = (wid >> 1) * 32;
#pragma unroll
    for (int mt = 0; mt < 4; mt++) {
        int row0 = bm * 128 + wm64 + mt * 16 + g;
#pragma unroll
        for (int nt = 0; nt < 4; nt++) {
            int col = bn * 128 + wn32 + nt * 8 + tg * 2;
            *(float2*)(C + (size_t)row0 * DMODEL + col)       = make_float2(acc_.a[mt][nt][0], acc_.a[mt][nt][1]);
            *(float2*)(C + (size_t)(row0 + 8) * DMODEL + col) = make_float2(acc_.a[mt][nt][2], acc_.a[mt][nt][3]);
        }
    }
}

// ---------------------------------------------------------------------------
// fp16 attention: 512 threads, q-tile 256, 4-stage ring, K/V hi-only,
// softmax via ex2.approx.f16x2 (bias pre-scaled by log2e).
// ---------------------------------------------------------------------------
#define AST    36
#define AQ     0
#define AKV    (256 * AST)
#define SLOT_W (2 * 64 * AST)
#define AB     (AKV + 4 * SLOT_W)
#define ATTN_SMEM ((AB + 256) * 4)

__global__ __launch_bounds__(512, 1)
void attn_mma()
{
    extern __shared__ __align__(16) uint32_t sw[];
    const uint32_t sb = (uint32_t)__cvta_generic_to_shared(sw);
    const int tid = threadIdx.x, wid = tid >> 5, lane = tid & 31;
    const int g = lane >> 2, tg = lane & 3;
    const int r8 = lane & 7, sub = lane >> 3;
    const int qt = blockIdx.x, h = blockIdx.y, b = blockIdx.z;
    const int q0 = qt * 256;
    const int qrow = wid * 16;

    const int a_row = qrow + r8 + ((sub & 1) << 3);
    const int a_col = (sub >> 1) << 2;
    const int pb_row = ((sub >> 1) << 3) + r8;
    const int pb_col = ((sub & 1) << 2);

    // ---- Q load ----
    {
        const __half* s0 = g_pqh + ((size_t)(b * QLEN + q0)) * DMODEL + h * DH;
#pragma unroll
        for (int i = 0; i < 4; i++) {
            int chunk = tid + 512 * i;
            int r = chunk >> 3, c = chunk & 7;
            uint32_t dst = sb + ((AQ + r * AST + c * 4) << 2);
            CP_ASYNC16(dst, s0 + (size_t)r * DMODEL + c * 8);
        }
        asm volatile("cp.async.commit_group;");
    }

    auto load_tile = [&](int kt, int slot) {
        const int k0 = kt * 64;
        const __half* srcs[2] = {
            g_pkh + ((size_t)(b * KVLEN + k0)) * DMODEL + h * DH,
            g_vth + (size_t)(h * DH) * NKV + b * KVLEN + k0 };
        const int r = tid >> 3, c = tid & 7;
#pragma unroll
        for (int arr = 0; arr < 2; arr++) {
            size_t rstride = (arr == 0) ? DMODEL : NKV;
            uint32_t dst = sb + ((AKV + slot * SLOT_W + arr * 2304 + r * AST + c * 4) << 2);
            CP_ASYNC16(dst, srcs[arr] + (size_t)r * rstride + c * 8);
        }
        if (tid < 16) {
            uint32_t dst = sb + ((AB + slot * 64 + tid * 4) << 2);
            CP_ASYNC16(dst, g_b2 + (size_t)b * KVLEN + k0 + tid * 4);
        }
        asm volatile("cp.async.commit_group;");
    };

    float oacc[8][4];
#pragma unroll
    for (int nt = 0; nt < 8; nt++)
#pragma unroll
        for (int r = 0; r < 4; r++) oacc[nt][r] = 0.f;
    float dsum0 = 0.f, dsum1 = 0.f;
    const float C1 = 0.125f * 1.4426950408889634f;   // scale * log2(e)

    const int NT = KVLEN / 64;
    load_tile(0, 0);
    load_tile(1, 1);
    load_tile(2, 2);

    for (int kt = 0; kt < NT; kt++) {
        const int slot = kt & 3;
        if (kt < NT - 2)       asm volatile("cp.async.wait_group 2;");
        else if (kt == NT - 2) asm volatile("cp.async.wait_group 1;");
        else                   asm volatile("cp.async.wait_group 0;");
        __syncthreads();
        if (kt + 3 < NT) load_tile(kt + 3, (kt + 3) & 3);

        // ---- S = Q·K^T ----
        float sacc[8][4];
#pragma unroll
        for (int nt = 0; nt < 8; nt++)
#pragma unroll
            for (int r = 0; r < 4; r++) sacc[nt][r] = 0.f;

        const uint32_t kbase = AKV + slot * SLOT_W;
#pragma unroll
        for (int ks = 0; ks < 4; ks++) {
            uint32_t aH[4];
            LDSM_X4(aH, sb + ((AQ + a_row * AST + ks * 8 + a_col) << 2));
#pragma unroll
            for (int np = 0; np < 4; np++) {
                uint32_t bf[4];
                LDSM_X4(bf, sb + ((kbase + (pb_row + np * 16) * AST + ks * 8 + pb_col) << 2));
                mma_f16(sacc[2 * np],     aH, bf);
                mma_f16(sacc[2 * np + 1], aH, bf + 2);
            }
        }

        // ---- P = 2^(S*C1 + bias*log2e) via ex2.approx.f16x2 ----
        const float* bsm = (const float*)(sw + AB + slot * 64);
        uint32_t ph[8][2];
#pragma unroll
        for (int nt = 0; nt < 8; nt++) {
            float bl0 = bsm[nt * 8 + tg * 2];
            float bl1 = bsm[nt * 8 + tg * 2 + 1];
            __half2 q0 = __floats2half2_rn(fmaf(sacc[nt][0], C1, bl0),
                                           fmaf(sacc[nt][1], C1, bl1));
            __half2 q1 = __floats2half2_rn(fmaf(sacc[nt][2], C1, bl0),
                                           fmaf(sacc[nt][3], C1, bl1));
            uint32_t p0, p1;
            asm("ex2.approx.f16x2 %0, %1;" : "=r"(p0) : "r"(*(uint32_t*)&q0));
            asm("ex2.approx.f16x2 %0, %1;" : "=r"(p1) : "r"(*(uint32_t*)&q1));
            ph[nt][0] = p0;  ph[nt][1] = p1;
            float2 f0 = __half22float2(*(__half2*)&p0);
            float2 f1 = __half22float2(*(__half2*)&p1);
            dsum0 += f0.x + f0.y;
            dsum1 += f1.x + f1.y;
        }

        // ---- O += P·V ----
        const uint32_t vbase = kbase + 2304;
#pragma unroll
        for (int ks = 0; ks < 4; ks++) {
            uint32_t aP[4] = { ph[2 * ks][0], ph[2 * ks][1],
                               ph[2 * ks + 1][0], ph[2 * ks + 1][1] };
#pragma unroll
            for (int np = 0; np < 4; np++) {
                uint32_t bf[4];
                LDSM_X4(bf, sb + ((vbase + (pb_row + np * 16) * AST + ks * 8 + pb_col) << 2));
                mma_f16(oacc[2 * np],     aP, bf);
                mma_f16(oacc[2 * np + 1], aP, bf + 2);
            }
        }
    }

    // ---- denominators (quad reduce) ----
    dsum0 += __shfl_xor_sync(0xFFFFFFFFu, dsum0, 1);
    dsum0 += __shfl_xor_sync(0xFFFFFFFFu, dsum0, 2);
    dsum1 += __shfl_xor_sync(0xFFFFFFFFu, dsum1, 1);
    dsum1 += __shfl_xor_sync(0xFFFFFFFFu, dsum1, 2);
    const float inv0 = 1.f / dsum0, inv1 = 1.f / dsum1;

    const int row = b * QLEN + q0 + qrow + g;
#pragma unroll
    for (int nt = 0; nt < 8; nt++) {
        const int col = h * DH + nt * 8 + tg * 2;
        __half2 o0 = __floats2half2_rn(oacc[nt][0] * inv0, oacc[nt][1] * inv0);
        __half2 o1 = __floats2half2_rn(oacc[nt][2] * inv1, oacc[nt][3] * inv1);
        *(uint32_t*)(g_ah + (size_t)row * DMODEL + col)       = *(uint32_t*)&o0;
        *(uint32_t*)(g_ah + (size_t)(row + 8) * DMODEL + col) = *(uint32_t*)&o1;
    }
}

// ---------------------------------------------------------------------------
extern "C" void kernel_launch(void* const* d_in, const int* in_sizes, int n_in,
                              void* d_out, int out_size)
{
    const float* query  = (const float*)d_in[0];
    const float* memory = (const float*)d_in[1];
    const float* bias   = (const float*)d_in[2];
    const float* Wq     = (const float*)d_in[3];
    const float* Wk     = (const float*)d_in[4];
    const float* Wv     = (const float*)d_in[5];
    const float* Wo     = (const float*)d_in[6];
    float* out = (float*)d_out;

    cudaFuncSetAttribute(k_proj,    cudaFuncAttributeMaxDynamicSharedMemorySize, GEMM_SMEM);
    cudaFuncSetAttribute(k_outproj, cudaFuncAttributeMaxDynamicSharedMemorySize, GEMM_SMEM);
    cudaFuncSetAttribute(attn_mma,  cudaFuncAttributeMaxDynamicSharedMemorySize, ATTN_SMEM);

    k_prep<<<4096, 256>>>(query, memory, bias);
    k_tsplit4<<<dim3(DMODEL / 32, DMODEL / 32, 4), dim3(32, 8)>>>(Wq, Wk, Wv, Wo);

    k_proj<<<2176, 256, GEMM_SMEM>>>();

    attn_mma<<<dim3(QLEN / 256, NHEAD, BATCH), 512, ATTN_SMEM>>>();

    k_outproj<<<128, 256, GEMM_SMEM>>>(out);
}